// round 1
// baseline (speedup 1.0000x reference)
#include <cuda_runtime.h>

// Shapes
#define BB     8
#define HH     96
#define WWIDTH 96
#define DIM    384
#define NHEADS 12
#define HD     32
#define WS     12
#define NWH    8
#define NWW    8
#define NW     64
#define WSQ    144
#define INNER  384
#define MROWS  73728        // BB*NW*WSQ
#define QKV_N  1152

// Scratch (allocation-free rule: __device__ globals)
__device__ float g_q[MROWS * INNER];
__device__ float g_k[MROWS * INNER];
__device__ float g_v[MROWS * INNER];
__device__ float g_att[MROWS * INNER];

// ---------------------------------------------------------------------------
// Kernel 1: fused cyclic-shift gather + QKV GEMM.
// C[r, n] = x[shifted(r), :] @ w_qkv[:, n],  r in windowed order.
// Output scattered into per-head layout [B, NW, HEADS, 144, 32] for q/k/v.
// Tile: BM=128, BN=128, BK=8, 256 threads, 8x8 microtile (split 4+4).
// ---------------------------------------------------------------------------
__global__ __launch_bounds__(256, 2) void qkv_gemm(const float* __restrict__ X,
                                                   const float* __restrict__ Wqkv) {
    __shared__ float As[8][128];
    __shared__ float Bs[8][128];
    __shared__ int rowoff[128];

    const int tid = threadIdx.x;
    const int m0 = blockIdx.y * 128;
    const int n0 = blockIdx.x * 128;

    if (tid < 128) {
        int r = m0 + tid;
        int b = r / 9216; int rem = r - b * 9216;
        int w = rem / 144; int i = rem - w * 144;
        int ys = (w >> 3) * 12 + i / 12;
        int xs = (w & 7) * 12 + i % 12;
        int y = ys + 6; if (y >= 96) y -= 96;   // roll(-6) gather
        int x = xs + 6; if (x >= 96) x -= 96;
        rowoff[tid] = ((b * 96 + y) * 96 + x) * 384;
    }
    __syncthreads();

    const int tx = tid & 15, ty = tid >> 4;
    const int ar = tid & 127, ac = (tid >> 7) * 4;
    const int br = tid >> 5,  bc = (tid & 31) * 4;
    const int aoff = rowoff[ar];

    float acc[8][8];
#pragma unroll
    for (int u = 0; u < 8; u++)
#pragma unroll
        for (int t = 0; t < 8; t++) acc[u][t] = 0.f;

    for (int k0 = 0; k0 < 384; k0 += 8) {
        float4 av = *(const float4*)(X + aoff + k0 + ac);
        float4 bv = *(const float4*)(Wqkv + (k0 + br) * QKV_N + n0 + bc);
        As[ac + 0][ar] = av.x; As[ac + 1][ar] = av.y;
        As[ac + 2][ar] = av.z; As[ac + 3][ar] = av.w;
        *(float4*)(&Bs[br][bc]) = bv;
        __syncthreads();
#pragma unroll
        for (int kk = 0; kk < 8; kk++) {
            float a[8], bb[8];
            *(float4*)&a[0]  = *(const float4*)(&As[kk][ty * 4]);
            *(float4*)&a[4]  = *(const float4*)(&As[kk][ty * 4 + 64]);
            *(float4*)&bb[0] = *(const float4*)(&Bs[kk][tx * 4]);
            *(float4*)&bb[4] = *(const float4*)(&Bs[kk][tx * 4 + 64]);
#pragma unroll
            for (int u = 0; u < 8; u++)
#pragma unroll
                for (int t = 0; t < 8; t++) acc[u][t] += a[u] * bb[t];
        }
        __syncthreads();
    }

    // Epilogue: scatter to q/k/v per-head layout.
    const int part = n0 / 384;          // 0=q 1=k 2=v (tile never crosses a part)
    float* outb = (part == 0) ? g_q : (part == 1 ? g_k : g_v);
    const int cpart = n0 - part * 384;

#pragma unroll
    for (int ci = 0; ci < 2; ci++) {
        int c = cpart + ci * 64 + tx * 4;   // within [0,384)
        int h = c >> 5, d0 = c & 31;        // head constant per 4-col group
#pragma unroll
        for (int ri = 0; ri < 2; ri++) {
#pragma unroll
            for (int rr = 0; rr < 4; rr++) {
                int r = m0 + ri * 64 + ty * 4 + rr;
                int b = r / 9216; int rem = r - b * 9216;
                int w = rem / 144; int i = rem - w * 144;
                int off = (((b * 64 + w) * 12 + h) * 144 + i) * 32 + d0;
                float4 v;
                v.x = acc[ri * 4 + rr][ci * 4 + 0];
                v.y = acc[ri * 4 + rr][ci * 4 + 1];
                v.z = acc[ri * 4 + rr][ci * 4 + 2];
                v.w = acc[ri * 4 + rr][ci * 4 + 3];
                *(float4*)(outb + off) = v;
            }
        }
    }
}

// ---------------------------------------------------------------------------
// Kernel 2: per-(b, window, head) attention with all masks fused.
// 144 threads, thread i owns query row i. Online softmax, acc in registers.
// ---------------------------------------------------------------------------
__global__ __launch_bounds__(144) void attn_kernel(const int* __restrict__ pixmap,
                                                   const float* __restrict__ posemb,
                                                   const float* __restrict__ pixemb) {
    __shared__ float4 ks4[WSQ * 8];
    __shared__ float4 vs4[WSQ * 8];
    __shared__ float pmv[WSQ];
    __shared__ float pose[529];
    __shared__ float pes[2];

    const int tid = threadIdx.x;
    const int b = blockIdx.y;
    const int w = blockIdx.x / 12;
    const int h = blockIdx.x - w * 12;
    const int tbase = ((b * 64 + w) * 12 + h) * (WSQ * HD);

    const float4* kg = (const float4*)(g_k + tbase);
    const float4* vg = (const float4*)(g_v + tbase);
    for (int f = tid; f < WSQ * 8; f += 144) { ks4[f] = kg[f]; vs4[f] = vg[f]; }
    for (int f = tid; f < 529; f += 144) pose[f] = posemb[f];
    {
        int wy = w >> 3, wx = w & 7;
        int iy = tid / 12, ix = tid - iy * 12;
        // pixel map uses UNSHIFTED coordinates (matches reference)
        pmv[tid] = (float)pixmap[(b * 96 + wy * 12 + iy) * 96 + wx * 12 + ix];
    }
    if (tid < 2) pes[tid] = pixemb[tid];
    __syncthreads();

    const int i = tid;
    float4 qr[8];
    const float4* qg = (const float4*)(g_q + tbase + i * 32);
#pragma unroll
    for (int d4 = 0; d4 < 8; d4++) qr[d4] = qg[d4];

    float acc[32];
#pragma unroll
    for (int d = 0; d < 32; d++) acc[d] = 0.f;
    float mrow = -1e30f, lrow = 0.f;

    const int iy = i / 12, ix = i - iy * 12;
    const float pmi = pmv[i];
    const bool ul = (w >> 3) == 7;       // last window row -> upper/lower mask
    const bool lr = (w & 7) == 7;        // last window col -> left/right mask
    const bool ih = (i >= 72);
    const bool ixh = (ix >= 6);
    const float pe0 = pes[0], pe1 = pes[1];
    const int pbase = (11 - iy) * 23 + (11 - ix);

    int jy = 0, jx = 0;
    for (int j = 0; j < 144; j++) {
        float s = 0.f;
        const float4* kr = ks4 + j * 8;
#pragma unroll
        for (int d4 = 0; d4 < 8; d4++) {
            float4 kv = kr[d4];
            s += qr[d4].x * kv.x + qr[d4].y * kv.y + qr[d4].z * kv.z + qr[d4].w * kv.w;
        }
        s *= 0.17677669529663689f;                       // 32^-0.5
        s += (pmi * pmv[j] != 0.f) ? pe1 : pe0;          // pixel-map mask
        s += pose[pbase + jy * 23 + jx];                 // relative pos bias
        bool masked = (ul && (ih != (j >= 72))) || (lr && (ixh != (jx >= 6)));
        if (masked) s = -1e30f;

        if (s > mrow) {                                  // online softmax
            float cf = __expf(mrow - s);
            mrow = s;
            lrow *= cf;
#pragma unroll
            for (int d = 0; d < 32; d++) acc[d] *= cf;
        }
        float p = __expf(s - mrow);
        lrow += p;
        const float4* vr = vs4 + j * 8;
#pragma unroll
        for (int d4 = 0; d4 < 8; d4++) {
            float4 vv = vr[d4];
            acc[d4 * 4 + 0] += p * vv.x;
            acc[d4 * 4 + 1] += p * vv.y;
            acc[d4 * 4 + 2] += p * vv.z;
            acc[d4 * 4 + 3] += p * vv.w;
        }
        jx++; if (jx == 12) { jx = 0; jy++; }
    }

    const float inv = 1.f / lrow;
    float4* op = (float4*)(g_att + ((b * 64 + w) * 144 + i) * 384 + h * 32);
#pragma unroll
    for (int d4 = 0; d4 < 8; d4++)
        op[d4] = make_float4(acc[4 * d4 + 0] * inv, acc[4 * d4 + 1] * inv,
                             acc[4 * d4 + 2] * inv, acc[4 * d4 + 3] * inv);
}

// ---------------------------------------------------------------------------
// Kernel 3: output projection + bias + window-merge + roll(+6,+6) scatter.
// ---------------------------------------------------------------------------
__global__ __launch_bounds__(256, 2) void out_gemm(const float* __restrict__ Wout,
                                                   const float* __restrict__ bout,
                                                   float* __restrict__ Out) {
    __shared__ float As[8][128];
    __shared__ float Bs[8][128];

    const int tid = threadIdx.x;
    const int m0 = blockIdx.y * 128;
    const int n0 = blockIdx.x * 128;

    const int tx = tid & 15, ty = tid >> 4;
    const int ar = tid & 127, ac = (tid >> 7) * 4;
    const int br = tid >> 5,  bc = (tid & 31) * 4;
    const int aoff = (m0 + ar) * 384;

    float acc[8][8];
#pragma unroll
    for (int u = 0; u < 8; u++)
#pragma unroll
        for (int t = 0; t < 8; t++) acc[u][t] = 0.f;

    for (int k0 = 0; k0 < 384; k0 += 8) {
        float4 av = *(const float4*)(g_att + aoff + k0 + ac);
        float4 bv = *(const float4*)(Wout + (k0 + br) * 384 + n0 + bc);
        As[ac + 0][ar] = av.x; As[ac + 1][ar] = av.y;
        As[ac + 2][ar] = av.z; As[ac + 3][ar] = av.w;
        *(float4*)(&Bs[br][bc]) = bv;
        __syncthreads();
#pragma unroll
        for (int kk = 0; kk < 8; kk++) {
            float a[8], bb[8];
            *(float4*)&a[0]  = *(const float4*)(&As[kk][ty * 4]);
            *(float4*)&a[4]  = *(const float4*)(&As[kk][ty * 4 + 64]);
            *(float4*)&bb[0] = *(const float4*)(&Bs[kk][tx * 4]);
            *(float4*)&bb[4] = *(const float4*)(&Bs[kk][tx * 4 + 64]);
#pragma unroll
            for (int u = 0; u < 8; u++)
#pragma unroll
                for (int t = 0; t < 8; t++) acc[u][t] += a[u] * bb[t];
        }
        __syncthreads();
    }

#pragma unroll
    for (int ci = 0; ci < 2; ci++) {
        int c = n0 + ci * 64 + tx * 4;
        float4 bi = *(const float4*)(bout + c);
#pragma unroll
        for (int ri = 0; ri < 2; ri++) {
#pragma unroll
            for (int rr = 0; rr < 4; rr++) {
                int r = m0 + ri * 64 + ty * 4 + rr;
                int b = r / 9216; int rem = r - b * 9216;
                int w = rem / 144; int i = rem - w * 144;
                int iy = i / 12, ix = i - iy * 12;
                int ys = (w >> 3) * 12 + iy, xs = (w & 7) * 12 + ix;
                int y = ys + 6; if (y >= 96) y -= 96;   // roll(+6) scatter
                int x = xs + 6; if (x >= 96) x -= 96;
                float4 v;
                v.x = acc[ri * 4 + rr][ci * 4 + 0] + bi.x;
                v.y = acc[ri * 4 + rr][ci * 4 + 1] + bi.y;
                v.z = acc[ri * 4 + rr][ci * 4 + 2] + bi.z;
                v.w = acc[ri * 4 + rr][ci * 4 + 3] + bi.w;
                *(float4*)(Out + ((b * 96 + y) * 96 + x) * 384 + c) = v;
            }
        }
    }
}

// ---------------------------------------------------------------------------
extern "C" void kernel_launch(void* const* d_in, const int* in_sizes, int n_in,
                              void* d_out, int out_size) {
    (void)in_sizes; (void)n_in; (void)out_size;
    const float* x      = (const float*)d_in[0];
    const int*   pixmap = (const int*)d_in[1];
    const float* wqkv   = (const float*)d_in[2];
    const float* posemb = (const float*)d_in[3];
    const float* pixemb = (const float*)d_in[4];
    const float* wout   = (const float*)d_in[5];
    const float* bout   = (const float*)d_in[6];
    float* out = (float*)d_out;

    qkv_gemm<<<dim3(QKV_N / 128, MROWS / 128), 256>>>(x, wqkv);
    attn_kernel<<<dim3(NW * NHEADS, BB), 144>>>(pixmap, posemb, pixemb);
    out_gemm<<<dim3(INNER / 128, MROWS / 128), 256>>>(wout, bout, out);
}

// round 2
// speedup vs baseline: 1.0524x; 1.0524x over previous
#include <cuda_runtime.h>
#include <cuda_bf16.h>
#include <cstdint>

// Shapes
#define BB     8
#define DIM    384
#define NHEADS 12
#define HD     32
#define WS     12
#define NW     64
#define WSQ    144
#define INNER  384
#define MROWS  73728        // BB*NW*WSQ
#define QKV_N  1152

// Scratch (allocation-free rule: __device__ globals)
__device__ float g_q[MROWS * INNER];
__device__ float g_k[MROWS * INNER];
__device__ float g_v[MROWS * INNER];
__device__ float g_att[MROWS * INNER];

// ---------------------------------------------------------------------------
// mma helpers
// ---------------------------------------------------------------------------
__device__ __forceinline__ uint32_t smem_u32(const void* p) {
    return (uint32_t)__cvta_generic_to_shared(p);
}
__device__ __forceinline__ void ldsmx4(uint32_t& r0, uint32_t& r1, uint32_t& r2,
                                       uint32_t& r3, uint32_t a) {
    asm volatile("ldmatrix.sync.aligned.m8n8.x4.shared.b16 {%0,%1,%2,%3}, [%4];"
                 : "=r"(r0), "=r"(r1), "=r"(r2), "=r"(r3) : "r"(a));
}
__device__ __forceinline__ void ldsmx4t(uint32_t& r0, uint32_t& r1, uint32_t& r2,
                                        uint32_t& r3, uint32_t a) {
    asm volatile("ldmatrix.sync.aligned.m8n8.x4.trans.shared.b16 {%0,%1,%2,%3}, [%4];"
                 : "=r"(r0), "=r"(r1), "=r"(r2), "=r"(r3) : "r"(a));
}
__device__ __forceinline__ void mma_bf16(float* c, const uint32_t* a,
                                         uint32_t b0, uint32_t b1) {
    asm volatile(
        "mma.sync.aligned.m16n8k16.row.col.f32.bf16.bf16.f32 "
        "{%0,%1,%2,%3},{%4,%5,%6,%7},{%8,%9},{%0,%1,%2,%3};"
        : "+f"(c[0]), "+f"(c[1]), "+f"(c[2]), "+f"(c[3])
        : "r"(a[0]), "r"(a[1]), "r"(a[2]), "r"(a[3]), "r"(b0), "r"(b1));
}
__device__ __forceinline__ void split2(float f, __nv_bfloat16& h, __nv_bfloat16& l) {
    h = __float2bfloat16_rn(f);
    l = __float2bfloat16_rn(f - __bfloat162float(h));
}

#define ASTR 40     // A smem row stride (bf16 elems) -> 80 B
#define BSTR 136    // B smem row stride (bf16 elems) -> 272 B

// ---------------------------------------------------------------------------
// Kernel 1: fused roll gather + QKV GEMM, bf16 split-2 tensor cores.
// Block 128x128, BK=32, 256 threads (8 warps: 4 m x 2 n, warp tile 32x64).
// ---------------------------------------------------------------------------
__global__ __launch_bounds__(256, 1) void qkv_gemm_mma(const float* __restrict__ X,
                                                       const float* __restrict__ Wqkv) {
    __shared__ __align__(16) __nv_bfloat16 Ah[128 * ASTR], Al[128 * ASTR];
    __shared__ __align__(16) __nv_bfloat16 Bh[32 * BSTR],  Bl[32 * BSTR];
    __shared__ int rowoff[128];

    const int tid = threadIdx.x;
    const int m0 = blockIdx.y * 128;
    const int n0 = blockIdx.x * 128;
    const int wid = tid >> 5, lane = tid & 31;
    const int wm = (wid >> 1) * 32;     // warp m-offset (0,32,64,96)
    const int wn = (wid & 1) * 64;      // warp n-offset (0,64)

    if (tid < 128) {
        int r = m0 + tid;
        int b = r / 9216; int rem = r - b * 9216;
        int w = rem / 144; int i = rem - w * 144;
        int y = (w >> 3) * 12 + i / 12 + 6; if (y >= 96) y -= 96;
        int x = (w & 7) * 12 + i % 12 + 6;  if (x >= 96) x -= 96;
        rowoff[tid] = ((b * 96 + y) * 96 + x) * 384;
    }
    __syncthreads();

    float acc[2][8][4];
#pragma unroll
    for (int a = 0; a < 2; a++)
#pragma unroll
        for (int b = 0; b < 8; b++)
#pragma unroll
            for (int c = 0; c < 4; c++) acc[a][b][c] = 0.f;

    for (int k0 = 0; k0 < 384; k0 += 32) {
        // -- load A (X gather) 128x32, convert to hi/lo bf16
#pragma unroll
        for (int it = 0; it < 4; it++) {
            int id = tid + it * 256;
            int row = id >> 3, c4 = (id & 7) * 4;
            float4 v = *(const float4*)(X + rowoff[row] + k0 + c4);
            __nv_bfloat16 hx, hy, hz, hw, lx, ly, lz, lw;
            split2(v.x, hx, lx); split2(v.y, hy, ly);
            split2(v.z, hz, lz); split2(v.w, hw, lw);
            *(__nv_bfloat162*)(Ah + row * ASTR + c4)     = __nv_bfloat162(hx, hy);
            *(__nv_bfloat162*)(Ah + row * ASTR + c4 + 2) = __nv_bfloat162(hz, hw);
            *(__nv_bfloat162*)(Al + row * ASTR + c4)     = __nv_bfloat162(lx, ly);
            *(__nv_bfloat162*)(Al + row * ASTR + c4 + 2) = __nv_bfloat162(lz, lw);
        }
        // -- load B (Wqkv) 32x128, row-major [k][n]
#pragma unroll
        for (int it = 0; it < 4; it++) {
            int id = tid + it * 256;
            int kr = id >> 5, n4 = (id & 31) * 4;
            float4 v = *(const float4*)(Wqkv + (k0 + kr) * QKV_N + n0 + n4);
            __nv_bfloat16 hx, hy, hz, hw, lx, ly, lz, lw;
            split2(v.x, hx, lx); split2(v.y, hy, ly);
            split2(v.z, hz, lz); split2(v.w, hw, lw);
            *(__nv_bfloat162*)(Bh + kr * BSTR + n4)     = __nv_bfloat162(hx, hy);
            *(__nv_bfloat162*)(Bh + kr * BSTR + n4 + 2) = __nv_bfloat162(hz, hw);
            *(__nv_bfloat162*)(Bl + kr * BSTR + n4)     = __nv_bfloat162(lx, ly);
            *(__nv_bfloat162*)(Bl + kr * BSTR + n4 + 2) = __nv_bfloat162(lz, lw);
        }
        __syncthreads();

#pragma unroll
        for (int ks = 0; ks < 2; ks++) {
            const int kk = ks * 16;
            uint32_t ah[2][4], al[2][4], bh[4][4], bl[4][4];
            const int arow = wm + (lane & 15);
            const int acol = kk + (lane >> 4) * 8;
#pragma unroll
            for (int mt = 0; mt < 2; mt++) {
                ldsmx4(ah[mt][0], ah[mt][1], ah[mt][2], ah[mt][3],
                       smem_u32(Ah + (arow + mt * 16) * ASTR + acol));
                ldsmx4(al[mt][0], al[mt][1], al[mt][2], al[mt][3],
                       smem_u32(Al + (arow + mt * 16) * ASTR + acol));
            }
            const int bk = kk + (lane & 15);
            const int bnb = wn + (lane >> 4) * 8;
#pragma unroll
            for (int g = 0; g < 4; g++) {
                ldsmx4t(bh[g][0], bh[g][1], bh[g][2], bh[g][3],
                        smem_u32(Bh + bk * BSTR + bnb + g * 16));
                ldsmx4t(bl[g][0], bl[g][1], bl[g][2], bl[g][3],
                        smem_u32(Bl + bk * BSTR + bnb + g * 16));
            }
#pragma unroll
            for (int mt = 0; mt < 2; mt++)
#pragma unroll
                for (int g = 0; g < 4; g++)
#pragma unroll
                    for (int hf = 0; hf < 2; hf++) {
                        float* c = acc[mt][2 * g + hf];
                        mma_bf16(c, ah[mt], bh[g][2 * hf], bh[g][2 * hf + 1]);
                        mma_bf16(c, ah[mt], bl[g][2 * hf], bl[g][2 * hf + 1]);
                        mma_bf16(c, al[mt], bh[g][2 * hf], bh[g][2 * hf + 1]);
                    }
        }
        __syncthreads();
    }

    // Epilogue: scatter to q/k/v per-head layout [B,NW,HEADS,144,32]
    const int part = n0 / 384;
    float* outb = (part == 0) ? g_q : (part == 1 ? g_k : g_v);
    const int cbase = n0 - part * 384;

#pragma unroll
    for (int mt = 0; mt < 2; mt++) {
#pragma unroll
        for (int rr = 0; rr < 2; rr++) {
            int r = m0 + wm + mt * 16 + (lane >> 2) + rr * 8;
            int b = r / 9216; int rem = r - b * 9216;
            int w = rem / 144; int i = rem - w * 144;
            int bw12 = (b * 64 + w) * 12;
#pragma unroll
            for (int nt = 0; nt < 8; nt++) {
                int c = cbase + wn + nt * 8 + (lane & 3) * 2;
                int h = c >> 5, d = c & 31;
                float2 v = make_float2(acc[mt][nt][rr * 2], acc[mt][nt][rr * 2 + 1]);
                *(float2*)(outb + ((bw12 + h) * 144 + i) * 32 + d) = v;
            }
        }
    }
}

// ---------------------------------------------------------------------------
// Kernel 2: per-(b, window, head) attention with all masks fused (fp32).
// ---------------------------------------------------------------------------
__global__ __launch_bounds__(144) void attn_kernel(const int* __restrict__ pixmap,
                                                   const float* __restrict__ posemb,
                                                   const float* __restrict__ pixemb) {
    __shared__ float4 ks4[WSQ * 8];
    __shared__ float4 vs4[WSQ * 8];
    __shared__ float pmv[WSQ];
    __shared__ float pose[529];
    __shared__ float pes[2];

    const int tid = threadIdx.x;
    const int b = blockIdx.y;
    const int w = blockIdx.x / 12;
    const int h = blockIdx.x - w * 12;
    const int tbase = ((b * 64 + w) * 12 + h) * (WSQ * HD);

    const float4* kg = (const float4*)(g_k + tbase);
    const float4* vg = (const float4*)(g_v + tbase);
    for (int f = tid; f < WSQ * 8; f += 144) { ks4[f] = kg[f]; vs4[f] = vg[f]; }
    for (int f = tid; f < 529; f += 144) pose[f] = posemb[f];
    {
        int wy = w >> 3, wx = w & 7;
        int iy = tid / 12, ix = tid - iy * 12;
        pmv[tid] = (float)pixmap[(b * 96 + wy * 12 + iy) * 96 + wx * 12 + ix];
    }
    if (tid < 2) pes[tid] = pixemb[tid];
    __syncthreads();

    const int i = tid;
    float4 qr[8];
    const float4* qg = (const float4*)(g_q + tbase + i * 32);
#pragma unroll
    for (int d4 = 0; d4 < 8; d4++) qr[d4] = qg[d4];

    float acc[32];
#pragma unroll
    for (int d = 0; d < 32; d++) acc[d] = 0.f;
    float mrow = -1e30f, lrow = 0.f;

    const int iy = i / 12, ix = i - iy * 12;
    const float pmi = pmv[i];
    const bool ul = (w >> 3) == 7;
    const bool lr = (w & 7) == 7;
    const bool ih = (i >= 72);
    const bool ixh = (ix >= 6);
    const float pe0 = pes[0], pe1 = pes[1];
    const int pbase = (11 - iy) * 23 + (11 - ix);

    int jy = 0, jx = 0;
    for (int j = 0; j < 144; j++) {
        float s = 0.f;
        const float4* kr = ks4 + j * 8;
#pragma unroll
        for (int d4 = 0; d4 < 8; d4++) {
            float4 kv = kr[d4];
            s += qr[d4].x * kv.x + qr[d4].y * kv.y + qr[d4].z * kv.z + qr[d4].w * kv.w;
        }
        s *= 0.17677669529663689f;
        s += (pmi * pmv[j] != 0.f) ? pe1 : pe0;
        s += pose[pbase + jy * 23 + jx];
        bool masked = (ul && (ih != (j >= 72))) || (lr && (ixh != (jx >= 6)));
        if (masked) s = -1e30f;

        if (s > mrow) {
            float cf = __expf(mrow - s);
            mrow = s;
            lrow *= cf;
#pragma unroll
            for (int d = 0; d < 32; d++) acc[d] *= cf;
        }
        float p = __expf(s - mrow);
        lrow += p;
        const float4* vr = vs4 + j * 8;
#pragma unroll
        for (int d4 = 0; d4 < 8; d4++) {
            float4 vv = vr[d4];
            acc[d4 * 4 + 0] += p * vv.x;
            acc[d4 * 4 + 1] += p * vv.y;
            acc[d4 * 4 + 2] += p * vv.z;
            acc[d4 * 4 + 3] += p * vv.w;
        }
        jx++; if (jx == 12) { jx = 0; jy++; }
    }

    const float inv = 1.f / lrow;
    float4* op = (float4*)(g_att + ((b * 64 + w) * 144 + i) * 384 + h * 32);
#pragma unroll
    for (int d4 = 0; d4 < 8; d4++)
        op[d4] = make_float4(acc[4 * d4 + 0] * inv, acc[4 * d4 + 1] * inv,
                             acc[4 * d4 + 2] * inv, acc[4 * d4 + 3] * inv);
}

// ---------------------------------------------------------------------------
// Kernel 3: output projection (tensor cores) + bias + roll(+6,+6) scatter.
// ---------------------------------------------------------------------------
__global__ __launch_bounds__(256, 1) void out_gemm_mma(const float* __restrict__ Wout,
                                                       const float* __restrict__ bout,
                                                       float* __restrict__ Out) {
    __shared__ __align__(16) __nv_bfloat16 Ah[128 * ASTR], Al[128 * ASTR];
    __shared__ __align__(16) __nv_bfloat16 Bh[32 * BSTR],  Bl[32 * BSTR];

    const int tid = threadIdx.x;
    const int m0 = blockIdx.y * 128;
    const int n0 = blockIdx.x * 128;
    const int wid = tid >> 5, lane = tid & 31;
    const int wm = (wid >> 1) * 32;
    const int wn = (wid & 1) * 64;

    float acc[2][8][4];
#pragma unroll
    for (int a = 0; a < 2; a++)
#pragma unroll
        for (int b = 0; b < 8; b++)
#pragma unroll
            for (int c = 0; c < 4; c++) acc[a][b][c] = 0.f;

    for (int k0 = 0; k0 < 384; k0 += 32) {
#pragma unroll
        for (int it = 0; it < 4; it++) {
            int id = tid + it * 256;
            int row = id >> 3, c4 = (id & 7) * 4;
            float4 v = *(const float4*)(g_att + (m0 + row) * 384 + k0 + c4);
            __nv_bfloat16 hx, hy, hz, hw, lx, ly, lz, lw;
            split2(v.x, hx, lx); split2(v.y, hy, ly);
            split2(v.z, hz, lz); split2(v.w, hw, lw);
            *(__nv_bfloat162*)(Ah + row * ASTR + c4)     = __nv_bfloat162(hx, hy);
            *(__nv_bfloat162*)(Ah + row * ASTR + c4 + 2) = __nv_bfloat162(hz, hw);
            *(__nv_bfloat162*)(Al + row * ASTR + c4)     = __nv_bfloat162(lx, ly);
            *(__nv_bfloat162*)(Al + row * ASTR + c4 + 2) = __nv_bfloat162(lz, lw);
        }
#pragma unroll
        for (int it = 0; it < 4; it++) {
            int id = tid + it * 256;
            int kr = id >> 5, n4 = (id & 31) * 4;
            float4 v = *(const float4*)(Wout + (k0 + kr) * 384 + n0 + n4);
            __nv_bfloat16 hx, hy, hz, hw, lx, ly, lz, lw;
            split2(v.x, hx, lx); split2(v.y, hy, ly);
            split2(v.z, hz, lz); split2(v.w, hw, lw);
            *(__nv_bfloat162*)(Bh + kr * BSTR + n4)     = __nv_bfloat162(hx, hy);
            *(__nv_bfloat162*)(Bh + kr * BSTR + n4 + 2) = __nv_bfloat162(hz, hw);
            *(__nv_bfloat162*)(Bl + kr * BSTR + n4)     = __nv_bfloat162(lx, ly);
            *(__nv_bfloat162*)(Bl + kr * BSTR + n4 + 2) = __nv_bfloat162(lz, lw);
        }
        __syncthreads();

#pragma unroll
        for (int ks = 0; ks < 2; ks++) {
            const int kk = ks * 16;
            uint32_t ah[2][4], al[2][4], bh[4][4], bl[4][4];
            const int arow = wm + (lane & 15);
            const int acol = kk + (lane >> 4) * 8;
#pragma unroll
            for (int mt = 0; mt < 2; mt++) {
                ldsmx4(ah[mt][0], ah[mt][1], ah[mt][2], ah[mt][3],
                       smem_u32(Ah + (arow + mt * 16) * ASTR + acol));
                ldsmx4(al[mt][0], al[mt][1], al[mt][2], al[mt][3],
                       smem_u32(Al + (arow + mt * 16) * ASTR + acol));
            }
            const int bk = kk + (lane & 15);
            const int bnb = wn + (lane >> 4) * 8;
#pragma unroll
            for (int g = 0; g < 4; g++) {
                ldsmx4t(bh[g][0], bh[g][1], bh[g][2], bh[g][3],
                        smem_u32(Bh + bk * BSTR + bnb + g * 16));
                ldsmx4t(bl[g][0], bl[g][1], bl[g][2], bl[g][3],
                        smem_u32(Bl + bk * BSTR + bnb + g * 16));
            }
#pragma unroll
            for (int mt = 0; mt < 2; mt++)
#pragma unroll
                for (int g = 0; g < 4; g++)
#pragma unroll
                    for (int hf = 0; hf < 2; hf++) {
                        float* c = acc[mt][2 * g + hf];
                        mma_bf16(c, ah[mt], bh[g][2 * hf], bh[g][2 * hf + 1]);
                        mma_bf16(c, ah[mt], bl[g][2 * hf], bl[g][2 * hf + 1]);
                        mma_bf16(c, al[mt], bh[g][2 * hf], bh[g][2 * hf + 1]);
                    }
        }
        __syncthreads();
    }

    // Epilogue: + bias, window-merge, roll(+6,+6) scatter
#pragma unroll
    for (int mt = 0; mt < 2; mt++) {
#pragma unroll
        for (int rr = 0; rr < 2; rr++) {
            int r = m0 + wm + mt * 16 + (lane >> 2) + rr * 8;
            int b = r / 9216; int rem = r - b * 9216;
            int w = rem / 144; int i = rem - w * 144;
            int iy = i / 12, ix = i - iy * 12;
            int y = (w >> 3) * 12 + iy + 6; if (y >= 96) y -= 96;
            int x = (w & 7) * 12 + ix + 6;  if (x >= 96) x -= 96;
            float* orow = Out + ((b * 96 + y) * 96 + x) * 384;
#pragma unroll
            for (int nt = 0; nt < 8; nt++) {
                int c = n0 + wn + nt * 8 + (lane & 3) * 2;
                float2 bi = *(const float2*)(bout + c);
                float2 v = make_float2(acc[mt][nt][rr * 2] + bi.x,
                                       acc[mt][nt][rr * 2 + 1] + bi.y);
                *(float2*)(orow + c) = v;
            }
        }
    }
}

// ---------------------------------------------------------------------------
extern "C" void kernel_launch(void* const* d_in, const int* in_sizes, int n_in,
                              void* d_out, int out_size) {
    (void)in_sizes; (void)n_in; (void)out_size;
    const float* x      = (const float*)d_in[0];
    const int*   pixmap = (const int*)d_in[1];
    const float* wqkv   = (const float*)d_in[2];
    const float* posemb = (const float*)d_in[3];
    const float* pixemb = (const float*)d_in[4];
    const float* wout   = (const float*)d_in[5];
    const float* bout   = (const float*)d_in[6];
    float* out = (float*)d_out;

    qkv_gemm_mma<<<dim3(QKV_N / 128, MROWS / 128), 256>>>(x, wqkv);
    attn_kernel<<<dim3(NW * NHEADS, BB), 144>>>(pixmap, posemb, pixemb);
    out_gemm_mma<<<dim3(INNER / 128, MROWS / 128), 256>>>(wout, bout, out);
}

// round 3
// speedup vs baseline: 1.4469x; 1.3748x over previous
#include <cuda_runtime.h>
#include <cuda_bf16.h>
#include <cstdint>

// Shapes
#define BB     8
#define NHEADS 12
#define HD     32
#define NW     64
#define WSQ    144
#define MROWS  73728        // BB*NW*WSQ
#define QKV_N  1152

// Scratch (allocation-free rule: __device__ globals)
__device__ float g_q[MROWS * 384];
__device__ float g_k[MROWS * 384];
__device__ float g_v[MROWS * 384];
__device__ __nv_bfloat16 g_xh[MROWS * 384];
__device__ __nv_bfloat16 g_xl[MROWS * 384];
__device__ __nv_bfloat16 g_atth[MROWS * 384];
__device__ __nv_bfloat16 g_attl[MROWS * 384];
__device__ __nv_bfloat16 g_wqh[384 * QKV_N];
__device__ __nv_bfloat16 g_wql[384 * QKV_N];
__device__ __nv_bfloat16 g_woh[384 * 384];
__device__ __nv_bfloat16 g_wol[384 * 384];

// ---------------------------------------------------------------------------
// helpers
// ---------------------------------------------------------------------------
__device__ __forceinline__ uint32_t smem_u32(const void* p) {
    return (uint32_t)__cvta_generic_to_shared(p);
}
__device__ __forceinline__ void ldsmx4(uint32_t& r0, uint32_t& r1, uint32_t& r2,
                                       uint32_t& r3, uint32_t a) {
    asm volatile("ldmatrix.sync.aligned.m8n8.x4.shared.b16 {%0,%1,%2,%3}, [%4];"
                 : "=r"(r0), "=r"(r1), "=r"(r2), "=r"(r3) : "r"(a));
}
__device__ __forceinline__ void ldsmx4t(uint32_t& r0, uint32_t& r1, uint32_t& r2,
                                        uint32_t& r3, uint32_t a) {
    asm volatile("ldmatrix.sync.aligned.m8n8.x4.trans.shared.b16 {%0,%1,%2,%3}, [%4];"
                 : "=r"(r0), "=r"(r1), "=r"(r2), "=r"(r3) : "r"(a));
}
__device__ __forceinline__ void mma_bf16(float* c, const uint32_t* a,
                                         uint32_t b0, uint32_t b1) {
    asm volatile(
        "mma.sync.aligned.m16n8k16.row.col.f32.bf16.bf16.f32 "
        "{%0,%1,%2,%3},{%4,%5,%6,%7},{%8,%9},{%0,%1,%2,%3};"
        : "+f"(c[0]), "+f"(c[1]), "+f"(c[2]), "+f"(c[3])
        : "r"(a[0]), "r"(a[1]), "r"(a[2]), "r"(a[3]), "r"(b0), "r"(b1));
}
__device__ __forceinline__ void split2(float f, __nv_bfloat16& h, __nv_bfloat16& l) {
    h = __float2bfloat16_rn(f);
    l = __float2bfloat16_rn(f - __bfloat162float(h));
}
__device__ __forceinline__ void cpasync16(void* s, const void* g) {
    asm volatile("cp.async.cg.shared.global [%0], [%1], 16;"
                 :: "r"(smem_u32(s)), "l"(g));
}

#define AST  40      // A smem row stride (bf16): 80 B = 5*16 -> conflict-free
#define BST  136     // B smem row stride (bf16): 272 B = 17*16 -> conflict-free
#define A_STAGE 5120 // 128*AST
#define B_STAGE 4352 // 32*BST
#define SMEM_BYTES ((4 * A_STAGE + 4 * B_STAGE) * 2)   // 75776

// ---------------------------------------------------------------------------
// Prep kernels: roll-gather + fp32 -> bf16 hi/lo split
// ---------------------------------------------------------------------------
__global__ void prep_x(const float* __restrict__ X) {
    const int r = blockIdx.x;
    int b = r / 9216; int rem = r - b * 9216;
    int w = rem / 144; int i = rem - w * 144;
    int y = (w >> 3) * 12 + i / 12 + 6; if (y >= 96) y -= 96;
    int x = (w & 7) * 12 + i % 12 + 6;  if (x >= 96) x -= 96;
    const float4* src = (const float4*)(X + ((b * 96 + y) * 96 + x) * 384);
    const int t = threadIdx.x;          // 96 threads, 4 floats each
    float4 v = src[t];
    __nv_bfloat16 hx, hy, hz, hw, lx, ly, lz, lw;
    split2(v.x, hx, lx); split2(v.y, hy, ly);
    split2(v.z, hz, lz); split2(v.w, hw, lw);
    int o = r * 384 + t * 4;
    *(__nv_bfloat162*)(g_xh + o)     = __nv_bfloat162(hx, hy);
    *(__nv_bfloat162*)(g_xh + o + 2) = __nv_bfloat162(hz, hw);
    *(__nv_bfloat162*)(g_xl + o)     = __nv_bfloat162(lx, ly);
    *(__nv_bfloat162*)(g_xl + o + 2) = __nv_bfloat162(lz, lw);
}

__global__ void prep_w(const float* __restrict__ wqkv, const float* __restrict__ wout) {
    const int id = blockIdx.x * 256 + threadIdx.x;  // float4 index
    float4 v;
    __nv_bfloat16* oh; __nv_bfloat16* ol; int o;
    if (id < 110592) {                        // 384*1152/4
        v = ((const float4*)wqkv)[id];
        oh = g_wqh; ol = g_wql; o = id * 4;
    } else {
        int id2 = id - 110592;                // < 36864
        v = ((const float4*)wout)[id2];
        oh = g_woh; ol = g_wol; o = id2 * 4;
    }
    __nv_bfloat16 hx, hy, hz, hw, lx, ly, lz, lw;
    split2(v.x, hx, lx); split2(v.y, hy, ly);
    split2(v.z, hz, lz); split2(v.w, hw, lw);
    *(__nv_bfloat162*)(oh + o)     = __nv_bfloat162(hx, hy);
    *(__nv_bfloat162*)(oh + o + 2) = __nv_bfloat162(hz, hw);
    *(__nv_bfloat162*)(ol + o)     = __nv_bfloat162(lx, ly);
    *(__nv_bfloat162*)(ol + o + 2) = __nv_bfloat162(lz, lw);
}

// ---------------------------------------------------------------------------
// Shared GEMM pieces: 128x128 tile, BK=32, 256 thr, 8 warps (4m x 2n, 32x64)
// ---------------------------------------------------------------------------
__device__ __forceinline__ void load_stage(
    const __nv_bfloat16* __restrict__ Agh, const __nv_bfloat16* __restrict__ Agl,
    const __nv_bfloat16* __restrict__ Bgh, const __nv_bfloat16* __restrict__ Bgl,
    __nv_bfloat16* Ah, __nv_bfloat16* Al, __nv_bfloat16* Bh, __nv_bfloat16* Bl,
    int m0, int n0, int ldb, int k0, int st, int tid)
{
    __nv_bfloat16* ash = Ah + st * A_STAGE;
    __nv_bfloat16* asl = Al + st * A_STAGE;
    __nv_bfloat16* bsh = Bh + st * B_STAGE;
    __nv_bfloat16* bsl = Bl + st * B_STAGE;
#pragma unroll
    for (int q = 0; q < 2; q++) {
        int c = tid * 2 + q;
        int row = c >> 2, ch = (c & 3) * 8;                 // A: 128 x 32
        int go = (m0 + row) * 384 + k0 + ch;
        int so = row * AST + ch;
        cpasync16(ash + so, Agh + go);
        cpasync16(asl + so, Agl + go);
    }
#pragma unroll
    for (int q = 0; q < 2; q++) {
        int c = tid * 2 + q;
        int row = c >> 4, ch = (c & 15) * 8;                // B: 32 x 128
        int go = (k0 + row) * ldb + n0 + ch;
        int so = row * BST + ch;
        cpasync16(bsh + so, Bgh + go);
        cpasync16(bsl + so, Bgl + go);
    }
}

__device__ __forceinline__ void compute_stage(
    const __nv_bfloat16* Ah, const __nv_bfloat16* Al,
    const __nv_bfloat16* Bh, const __nv_bfloat16* Bl,
    int wm, int wn, int lane, float acc[2][8][4])
{
#pragma unroll
    for (int ks = 0; ks < 2; ks++) {
        const int kk = ks * 16;
        uint32_t ah[2][4], al[2][4], bh[4][4], bl[4][4];
        const int arow = wm + (lane & 15);
        const int acol = kk + (lane >> 4) * 8;
#pragma unroll
        for (int mt = 0; mt < 2; mt++) {
            ldsmx4(ah[mt][0], ah[mt][1], ah[mt][2], ah[mt][3],
                   smem_u32(Ah + (arow + mt * 16) * AST + acol));
            ldsmx4(al[mt][0], al[mt][1], al[mt][2], al[mt][3],
                   smem_u32(Al + (arow + mt * 16) * AST + acol));
        }
        const int bk = kk + (lane & 15);
        const int bnb = wn + (lane >> 4) * 8;
#pragma unroll
        for (int g = 0; g < 4; g++) {
            ldsmx4t(bh[g][0], bh[g][1], bh[g][2], bh[g][3],
                    smem_u32(Bh + bk * BST + bnb + g * 16));
            ldsmx4t(bl[g][0], bl[g][1], bl[g][2], bl[g][3],
                    smem_u32(Bl + bk * BST + bnb + g * 16));
        }
#pragma unroll
        for (int mt = 0; mt < 2; mt++)
#pragma unroll
            for (int g = 0; g < 4; g++)
#pragma unroll
                for (int hf = 0; hf < 2; hf++) {
                    float* c = acc[mt][2 * g + hf];
                    mma_bf16(c, ah[mt], bh[g][2 * hf], bh[g][2 * hf + 1]);
                    mma_bf16(c, ah[mt], bl[g][2 * hf], bl[g][2 * hf + 1]);
                    mma_bf16(c, al[mt], bh[g][2 * hf], bh[g][2 * hf + 1]);
                }
    }
}

#define GEMM_MAINLOOP(AGH, AGL, BGH, BGL, LDB)                                   \
    extern __shared__ __align__(16) __nv_bfloat16 smem[];                        \
    __nv_bfloat16* Ah = smem;                                                    \
    __nv_bfloat16* Al = smem + 2 * A_STAGE;                                      \
    __nv_bfloat16* Bh = smem + 4 * A_STAGE;                                      \
    __nv_bfloat16* Bl = smem + 4 * A_STAGE + 2 * B_STAGE;                        \
    const int tid = threadIdx.x;                                                 \
    const int m0 = blockIdx.y * 128;                                             \
    const int n0 = blockIdx.x * 128;                                             \
    const int wid = tid >> 5, lane = tid & 31;                                   \
    const int wm = (wid >> 1) * 32;                                              \
    const int wn = (wid & 1) * 64;                                               \
    float acc[2][8][4];                                                          \
    _Pragma("unroll") for (int a_ = 0; a_ < 2; a_++)                             \
    _Pragma("unroll") for (int b_ = 0; b_ < 8; b_++)                             \
    _Pragma("unroll") for (int c_ = 0; c_ < 4; c_++) acc[a_][b_][c_] = 0.f;      \
    load_stage(AGH, AGL, BGH, BGL, Ah, Al, Bh, Bl, m0, n0, LDB, 0, 0, tid);      \
    asm volatile("cp.async.commit_group;" ::: "memory");                         \
    for (int it = 0; it < 12; it++) {                                            \
        if (it < 11) {                                                           \
            load_stage(AGH, AGL, BGH, BGL, Ah, Al, Bh, Bl, m0, n0, LDB,          \
                       (it + 1) * 32, (it + 1) & 1, tid);                        \
            asm volatile("cp.async.commit_group;" ::: "memory");                 \
            asm volatile("cp.async.wait_group 1;" ::: "memory");                 \
        } else {                                                                 \
            asm volatile("cp.async.wait_group 0;" ::: "memory");                 \
        }                                                                        \
        __syncthreads();                                                         \
        const int st = it & 1;                                                   \
        compute_stage(Ah + st * A_STAGE, Al + st * A_STAGE,                      \
                      Bh + st * B_STAGE, Bl + st * B_STAGE, wm, wn, lane, acc);  \
        __syncthreads();                                                         \
    }

// ---------------------------------------------------------------------------
// Kernel: QKV GEMM -> scatter to per-head layout [B,NW,HEADS,144,32]
// ---------------------------------------------------------------------------
__global__ __launch_bounds__(256, 1) void qkv_gemm_mma() {
    GEMM_MAINLOOP(g_xh, g_xl, g_wqh, g_wql, QKV_N)

    const int part = n0 / 384;
    float* outb = (part == 0) ? g_q : (part == 1 ? g_k : g_v);
    const int cbase = n0 - part * 384;

#pragma unroll
    for (int mt = 0; mt < 2; mt++) {
#pragma unroll
        for (int rr = 0; rr < 2; rr++) {
            int r = m0 + wm + mt * 16 + (lane >> 2) + rr * 8;
            int b = r / 9216; int rem = r - b * 9216;
            int w = rem / 144; int i = rem - w * 144;
            int bw12 = (b * 64 + w) * 12;
#pragma unroll
            for (int nt = 0; nt < 8; nt++) {
                int c = cbase + wn + nt * 8 + (lane & 3) * 2;
                int h = c >> 5, d = c & 31;
                float2 v = make_float2(acc[mt][nt][rr * 2], acc[mt][nt][rr * 2 + 1]);
                *(float2*)(outb + ((bw12 + h) * 144 + i) * 32 + d) = v;
            }
        }
    }
}

// ---------------------------------------------------------------------------
// Kernel: attention per (b, window, head), all masks fused, fp32 math,
// writes output as bf16 hi/lo for the out-proj GEMM.
// ---------------------------------------------------------------------------
__global__ __launch_bounds__(144) void attn_kernel(const int* __restrict__ pixmap,
                                                   const float* __restrict__ posemb,
                                                   const float* __restrict__ pixemb) {
    __shared__ float4 ks4[WSQ * 8];
    __shared__ float4 vs4[WSQ * 8];
    __shared__ float pmv[WSQ];
    __shared__ float pose[529];
    __shared__ float pes[2];

    const int tid = threadIdx.x;
    const int b = blockIdx.y;
    const int w = blockIdx.x / 12;
    const int h = blockIdx.x - w * 12;
    const int tbase = ((b * 64 + w) * 12 + h) * (WSQ * HD);

    const float4* kg = (const float4*)(g_k + tbase);
    const float4* vg = (const float4*)(g_v + tbase);
    for (int f = tid; f < WSQ * 8; f += 144) { ks4[f] = kg[f]; vs4[f] = vg[f]; }
    for (int f = tid; f < 529; f += 144) pose[f] = posemb[f];
    {
        int wy = w >> 3, wx = w & 7;
        int iy = tid / 12, ix = tid - iy * 12;
        pmv[tid] = (float)pixmap[(b * 96 + wy * 12 + iy) * 96 + wx * 12 + ix];
    }
    if (tid < 2) pes[tid] = pixemb[tid];
    __syncthreads();

    const int i = tid;
    float4 qr[8];
    const float4* qg = (const float4*)(g_q + tbase + i * 32);
#pragma unroll
    for (int d4 = 0; d4 < 8; d4++) qr[d4] = qg[d4];

    float acc[32];
#pragma unroll
    for (int d = 0; d < 32; d++) acc[d] = 0.f;
    float mrow = -1e30f, lrow = 0.f;

    const int iy = i / 12, ix = i - iy * 12;
    const float pmi = pmv[i];
    const bool ul = (w >> 3) == 7;
    const bool lr = (w & 7) == 7;
    const bool ih = (i >= 72);
    const bool ixh = (ix >= 6);
    const float pe0 = pes[0], pe1 = pes[1];
    const int pbase = (11 - iy) * 23 + (11 - ix);

    int jy = 0, jx = 0;
    for (int j = 0; j < 144; j++) {
        float s = 0.f;
        const float4* kr = ks4 + j * 8;
#pragma unroll
        for (int d4 = 0; d4 < 8; d4++) {
            float4 kv = kr[d4];
            s += qr[d4].x * kv.x + qr[d4].y * kv.y + qr[d4].z * kv.z + qr[d4].w * kv.w;
        }
        s *= 0.17677669529663689f;
        s += (pmi * pmv[j] != 0.f) ? pe1 : pe0;
        s += pose[pbase + jy * 23 + jx];
        bool masked = (ul && (ih != (j >= 72))) || (lr && (ixh != (jx >= 6)));
        if (masked) s = -1e30f;

        if (s > mrow) {
            float cf = __expf(mrow - s);
            mrow = s;
            lrow *= cf;
#pragma unroll
            for (int d = 0; d < 32; d++) acc[d] *= cf;
        }
        float p = __expf(s - mrow);
        lrow += p;
        const float4* vr = vs4 + j * 8;
#pragma unroll
        for (int d4 = 0; d4 < 8; d4++) {
            float4 vv = vr[d4];
            acc[d4 * 4 + 0] += p * vv.x;
            acc[d4 * 4 + 1] += p * vv.y;
            acc[d4 * 4 + 2] += p * vv.z;
            acc[d4 * 4 + 3] += p * vv.w;
        }
        jx++; if (jx == 12) { jx = 0; jy++; }
    }

    const float inv = 1.f / lrow;
    const int obase = ((b * 64 + w) * 144 + i) * 384 + h * 32;
#pragma unroll
    for (int d4 = 0; d4 < 8; d4++) {
        float f0 = acc[4 * d4 + 0] * inv, f1 = acc[4 * d4 + 1] * inv;
        float f2 = acc[4 * d4 + 2] * inv, f3 = acc[4 * d4 + 3] * inv;
        __nv_bfloat16 h0, h1, h2, h3, l0, l1, l2, l3;
        split2(f0, h0, l0); split2(f1, h1, l1);
        split2(f2, h2, l2); split2(f3, h3, l3);
        int o = obase + d4 * 4;
        *(__nv_bfloat162*)(g_atth + o)     = __nv_bfloat162(h0, h1);
        *(__nv_bfloat162*)(g_atth + o + 2) = __nv_bfloat162(h2, h3);
        *(__nv_bfloat162*)(g_attl + o)     = __nv_bfloat162(l0, l1);
        *(__nv_bfloat162*)(g_attl + o + 2) = __nv_bfloat162(l2, l3);
    }
}

// ---------------------------------------------------------------------------
// Kernel: output projection + bias + window-merge + roll(+6,+6) scatter
// ---------------------------------------------------------------------------
__global__ __launch_bounds__(256, 1) void out_gemm_mma(const float* __restrict__ bout,
                                                       float* __restrict__ Out) {
    GEMM_MAINLOOP(g_atth, g_attl, g_woh, g_wol, 384)

#pragma unroll
    for (int mt = 0; mt < 2; mt++) {
#pragma unroll
        for (int rr = 0; rr < 2; rr++) {
            int r = m0 + wm + mt * 16 + (lane >> 2) + rr * 8;
            int b = r / 9216; int rem = r - b * 9216;
            int w = rem / 144; int i = rem - w * 144;
            int iy = i / 12, ix = i - iy * 12;
            int y = (w >> 3) * 12 + iy + 6; if (y >= 96) y -= 96;
            int x = (w & 7) * 12 + ix + 6;  if (x >= 96) x -= 96;
            float* orow = Out + ((b * 96 + y) * 96 + x) * 384;
#pragma unroll
            for (int nt = 0; nt < 8; nt++) {
                int c = n0 + wn + nt * 8 + (lane & 3) * 2;
                float2 bi = *(const float2*)(bout + c);
                float2 v = make_float2(acc[mt][nt][rr * 2] + bi.x,
                                       acc[mt][nt][rr * 2 + 1] + bi.y);
                *(float2*)(orow + c) = v;
            }
        }
    }
}

// ---------------------------------------------------------------------------
extern "C" void kernel_launch(void* const* d_in, const int* in_sizes, int n_in,
                              void* d_out, int out_size) {
    (void)in_sizes; (void)n_in; (void)out_size;
    const float* x      = (const float*)d_in[0];
    const int*   pixmap = (const int*)d_in[1];
    const float* wqkv   = (const float*)d_in[2];
    const float* posemb = (const float*)d_in[3];
    const float* pixemb = (const float*)d_in[4];
    const float* wout   = (const float*)d_in[5];
    const float* bout   = (const float*)d_in[6];
    float* out = (float*)d_out;

    cudaFuncSetAttribute(qkv_gemm_mma, cudaFuncAttributeMaxDynamicSharedMemorySize,
                         SMEM_BYTES);
    cudaFuncSetAttribute(out_gemm_mma, cudaFuncAttributeMaxDynamicSharedMemorySize,
                         SMEM_BYTES);

    prep_x<<<MROWS, 96>>>(x);
    prep_w<<<576, 256>>>(wqkv, wout);
    qkv_gemm_mma<<<dim3(QKV_N / 128, MROWS / 128), 256, SMEM_BYTES>>>();
    attn_kernel<<<dim3(NW * NHEADS, BB), 144>>>(pixmap, posemb, pixemb);
    out_gemm_mma<<<dim3(384 / 128, MROWS / 128), 256, SMEM_BYTES>>>(bout, out);
}

// round 4
// speedup vs baseline: 1.7357x; 1.1995x over previous
#include <cuda_runtime.h>
#include <cuda_bf16.h>
#include <cstdint>

// Shapes
#define BB     8
#define NHEADS 12
#define HD     32
#define NW     64
#define WSQ    144
#define MROWS  73728        // BB*NW*WSQ
#define QKV_N  1152

// Scratch (allocation-free rule: __device__ globals)
__device__ float g_q[MROWS * 384];
__device__ float g_k[MROWS * 384];
__device__ float g_v[MROWS * 384];
__device__ __nv_bfloat16 g_xh[MROWS * 384];
__device__ __nv_bfloat16 g_xl[MROWS * 384];
__device__ __nv_bfloat16 g_atth[MROWS * 384];
__device__ __nv_bfloat16 g_attl[MROWS * 384];
__device__ __nv_bfloat16 g_wqh[384 * QKV_N];
__device__ __nv_bfloat16 g_wql[384 * QKV_N];
__device__ __nv_bfloat16 g_woh[384 * 384];
__device__ __nv_bfloat16 g_wol[384 * 384];

// ---------------------------------------------------------------------------
// helpers
// ---------------------------------------------------------------------------
__device__ __forceinline__ uint32_t smem_u32(const void* p) {
    return (uint32_t)__cvta_generic_to_shared(p);
}
__device__ __forceinline__ void ldsmx4(uint32_t& r0, uint32_t& r1, uint32_t& r2,
                                       uint32_t& r3, uint32_t a) {
    asm volatile("ldmatrix.sync.aligned.m8n8.x4.shared.b16 {%0,%1,%2,%3}, [%4];"
                 : "=r"(r0), "=r"(r1), "=r"(r2), "=r"(r3) : "r"(a));
}
__device__ __forceinline__ void ldsmx4t(uint32_t& r0, uint32_t& r1, uint32_t& r2,
                                        uint32_t& r3, uint32_t a) {
    asm volatile("ldmatrix.sync.aligned.m8n8.x4.trans.shared.b16 {%0,%1,%2,%3}, [%4];"
                 : "=r"(r0), "=r"(r1), "=r"(r2), "=r"(r3) : "r"(a));
}
__device__ __forceinline__ void mma_bf16(float* c, const uint32_t* a,
                                         uint32_t b0, uint32_t b1) {
    asm volatile(
        "mma.sync.aligned.m16n8k16.row.col.f32.bf16.bf16.f32 "
        "{%0,%1,%2,%3},{%4,%5,%6,%7},{%8,%9},{%0,%1,%2,%3};"
        : "+f"(c[0]), "+f"(c[1]), "+f"(c[2]), "+f"(c[3])
        : "r"(a[0]), "r"(a[1]), "r"(a[2]), "r"(a[3]), "r"(b0), "r"(b1));
}
__device__ __forceinline__ void split2(float f, __nv_bfloat16& h, __nv_bfloat16& l) {
    h = __float2bfloat16_rn(f);
    l = __float2bfloat16_rn(f - __bfloat162float(h));
}
__device__ __forceinline__ uint32_t packbf2(__nv_bfloat16 a, __nv_bfloat16 b) {
    __nv_bfloat162 v(a, b);
    return *(uint32_t*)&v;
}
__device__ __forceinline__ void cpasync16(void* s, const void* g) {
    asm volatile("cp.async.cg.shared.global [%0], [%1], 16;"
                 :: "r"(smem_u32(s)), "l"(g));
}

#define AST  40      // A smem row stride (bf16): 80 B = 5*16 -> conflict-free
#define BST  136     // B smem row stride (bf16): 272 B = 17*16 -> conflict-free
#define A_STAGE 5120 // 128*AST
#define B_STAGE 4352 // 32*BST
#define SMEM_BYTES ((4 * A_STAGE + 4 * B_STAGE) * 2)   // 75776

// ---------------------------------------------------------------------------
// Prep kernels: roll-gather + fp32 -> bf16 hi/lo split
// ---------------------------------------------------------------------------
__global__ void prep_x(const float* __restrict__ X) {
    const int r = blockIdx.x;
    int b = r / 9216; int rem = r - b * 9216;
    int w = rem / 144; int i = rem - w * 144;
    int y = (w >> 3) * 12 + i / 12 + 6; if (y >= 96) y -= 96;
    int x = (w & 7) * 12 + i % 12 + 6;  if (x >= 96) x -= 96;
    const float4* src = (const float4*)(X + ((b * 96 + y) * 96 + x) * 384);
    const int t = threadIdx.x;          // 96 threads, 4 floats each
    float4 v = src[t];
    __nv_bfloat16 hx, hy, hz, hw, lx, ly, lz, lw;
    split2(v.x, hx, lx); split2(v.y, hy, ly);
    split2(v.z, hz, lz); split2(v.w, hw, lw);
    int o = r * 384 + t * 4;
    *(__nv_bfloat162*)(g_xh + o)     = __nv_bfloat162(hx, hy);
    *(__nv_bfloat162*)(g_xh + o + 2) = __nv_bfloat162(hz, hw);
    *(__nv_bfloat162*)(g_xl + o)     = __nv_bfloat162(lx, ly);
    *(__nv_bfloat162*)(g_xl + o + 2) = __nv_bfloat162(lz, lw);
}

__global__ void prep_w(const float* __restrict__ wqkv, const float* __restrict__ wout) {
    const int id = blockIdx.x * 256 + threadIdx.x;  // float4 index
    float4 v;
    __nv_bfloat16* oh; __nv_bfloat16* ol; int o;
    if (id < 110592) {                        // 384*1152/4
        v = ((const float4*)wqkv)[id];
        oh = g_wqh; ol = g_wql; o = id * 4;
    } else {
        int id2 = id - 110592;                // < 36864
        v = ((const float4*)wout)[id2];
        oh = g_woh; ol = g_wol; o = id2 * 4;
    }
    __nv_bfloat16 hx, hy, hz, hw, lx, ly, lz, lw;
    split2(v.x, hx, lx); split2(v.y, hy, ly);
    split2(v.z, hz, lz); split2(v.w, hw, lw);
    *(__nv_bfloat162*)(oh + o)     = __nv_bfloat162(hx, hy);
    *(__nv_bfloat162*)(oh + o + 2) = __nv_bfloat162(hz, hw);
    *(__nv_bfloat162*)(ol + o)     = __nv_bfloat162(lx, ly);
    *(__nv_bfloat162*)(ol + o + 2) = __nv_bfloat162(lz, lw);
}

// ---------------------------------------------------------------------------
// Shared GEMM pieces: 128x128 tile, BK=32, 256 thr, 8 warps (4m x 2n, 32x64)
// ---------------------------------------------------------------------------
__device__ __forceinline__ void load_stage(
    const __nv_bfloat16* __restrict__ Agh, const __nv_bfloat16* __restrict__ Agl,
    const __nv_bfloat16* __restrict__ Bgh, const __nv_bfloat16* __restrict__ Bgl,
    __nv_bfloat16* Ah, __nv_bfloat16* Al, __nv_bfloat16* Bh, __nv_bfloat16* Bl,
    int m0, int n0, int ldb, int k0, int st, int tid)
{
    __nv_bfloat16* ash = Ah + st * A_STAGE;
    __nv_bfloat16* asl = Al + st * A_STAGE;
    __nv_bfloat16* bsh = Bh + st * B_STAGE;
    __nv_bfloat16* bsl = Bl + st * B_STAGE;
#pragma unroll
    for (int q = 0; q < 2; q++) {
        int c = tid * 2 + q;
        int row = c >> 2, ch = (c & 3) * 8;                 // A: 128 x 32
        int go = (m0 + row) * 384 + k0 + ch;
        int so = row * AST + ch;
        cpasync16(ash + so, Agh + go);
        cpasync16(asl + so, Agl + go);
    }
#pragma unroll
    for (int q = 0; q < 2; q++) {
        int c = tid * 2 + q;
        int row = c >> 4, ch = (c & 15) * 8;                // B: 32 x 128
        int go = (k0 + row) * ldb + n0 + ch;
        int so = row * BST + ch;
        cpasync16(bsh + so, Bgh + go);
        cpasync16(bsl + so, Bgl + go);
    }
}

__device__ __forceinline__ void compute_stage(
    const __nv_bfloat16* Ah, const __nv_bfloat16* Al,
    const __nv_bfloat16* Bh, const __nv_bfloat16* Bl,
    int wm, int wn, int lane, float acc[2][8][4])
{
#pragma unroll
    for (int ks = 0; ks < 2; ks++) {
        const int kk = ks * 16;
        uint32_t ah[2][4], al[2][4], bh[4][4], bl[4][4];
        const int arow = wm + (lane & 15);
        const int acol = kk + (lane >> 4) * 8;
#pragma unroll
        for (int mt = 0; mt < 2; mt++) {
            ldsmx4(ah[mt][0], ah[mt][1], ah[mt][2], ah[mt][3],
                   smem_u32(Ah + (arow + mt * 16) * AST + acol));
            ldsmx4(al[mt][0], al[mt][1], al[mt][2], al[mt][3],
                   smem_u32(Al + (arow + mt * 16) * AST + acol));
        }
        const int bk = kk + (lane & 15);
        const int bnb = wn + (lane >> 4) * 8;
#pragma unroll
        for (int g = 0; g < 4; g++) {
            ldsmx4t(bh[g][0], bh[g][1], bh[g][2], bh[g][3],
                    smem_u32(Bh + bk * BST + bnb + g * 16));
            ldsmx4t(bl[g][0], bl[g][1], bl[g][2], bl[g][3],
                    smem_u32(Bl + bk * BST + bnb + g * 16));
        }
#pragma unroll
        for (int mt = 0; mt < 2; mt++)
#pragma unroll
            for (int g = 0; g < 4; g++)
#pragma unroll
                for (int hf = 0; hf < 2; hf++) {
                    float* c = acc[mt][2 * g + hf];
                    mma_bf16(c, ah[mt], bh[g][2 * hf], bh[g][2 * hf + 1]);
                    mma_bf16(c, ah[mt], bl[g][2 * hf], bl[g][2 * hf + 1]);
                    mma_bf16(c, al[mt], bh[g][2 * hf], bh[g][2 * hf + 1]);
                }
    }
}

#define GEMM_MAINLOOP(AGH, AGL, BGH, BGL, LDB)                                   \
    extern __shared__ __align__(16) __nv_bfloat16 smem[];                        \
    __nv_bfloat16* Ah = smem;                                                    \
    __nv_bfloat16* Al = smem + 2 * A_STAGE;                                      \
    __nv_bfloat16* Bh = smem + 4 * A_STAGE;                                      \
    __nv_bfloat16* Bl = smem + 4 * A_STAGE + 2 * B_STAGE;                        \
    const int tid = threadIdx.x;                                                 \
    const int m0 = blockIdx.y * 128;                                             \
    const int n0 = blockIdx.x * 128;                                             \
    const int wid = tid >> 5, lane = tid & 31;                                   \
    const int wm = (wid >> 1) * 32;                                              \
    const int wn = (wid & 1) * 64;                                               \
    float acc[2][8][4];                                                          \
    _Pragma("unroll") for (int a_ = 0; a_ < 2; a_++)                             \
    _Pragma("unroll") for (int b_ = 0; b_ < 8; b_++)                             \
    _Pragma("unroll") for (int c_ = 0; c_ < 4; c_++) acc[a_][b_][c_] = 0.f;      \
    load_stage(AGH, AGL, BGH, BGL, Ah, Al, Bh, Bl, m0, n0, LDB, 0, 0, tid);      \
    asm volatile("cp.async.commit_group;" ::: "memory");                         \
    for (int it = 0; it < 12; it++) {                                            \
        if (it < 11) {                                                           \
            load_stage(AGH, AGL, BGH, BGL, Ah, Al, Bh, Bl, m0, n0, LDB,          \
                       (it + 1) * 32, (it + 1) & 1, tid);                        \
            asm volatile("cp.async.commit_group;" ::: "memory");                 \
            asm volatile("cp.async.wait_group 1;" ::: "memory");                 \
        } else {                                                                 \
            asm volatile("cp.async.wait_group 0;" ::: "memory");                 \
        }                                                                        \
        __syncthreads();                                                         \
        const int st = it & 1;                                                   \
        compute_stage(Ah + st * A_STAGE, Al + st * A_STAGE,                      \
                      Bh + st * B_STAGE, Bl + st * B_STAGE, wm, wn, lane, acc);  \
        __syncthreads();                                                         \
    }

// ---------------------------------------------------------------------------
// Kernel: QKV GEMM -> scatter to per-head layout [B,NW,HEADS,144,32]
// ---------------------------------------------------------------------------
__global__ __launch_bounds__(256, 1) void qkv_gemm_mma() {
    GEMM_MAINLOOP(g_xh, g_xl, g_wqh, g_wql, QKV_N)

    const int part = n0 / 384;
    float* outb = (part == 0) ? g_q : (part == 1 ? g_k : g_v);
    const int cbase = n0 - part * 384;

#pragma unroll
    for (int mt = 0; mt < 2; mt++) {
#pragma unroll
        for (int rr = 0; rr < 2; rr++) {
            int r = m0 + wm + mt * 16 + (lane >> 2) + rr * 8;
            int b = r / 9216; int rem = r - b * 9216;
            int w = rem / 144; int i = rem - w * 144;
            int bw12 = (b * 64 + w) * 12;
#pragma unroll
            for (int nt = 0; nt < 8; nt++) {
                int c = cbase + wn + nt * 8 + (lane & 3) * 2;
                int h = c >> 5, d = c & 31;
                float2 v = make_float2(acc[mt][nt][rr * 2], acc[mt][nt][rr * 2 + 1]);
                *(float2*)(outb + ((bw12 + h) * 144 + i) * 32 + d) = v;
            }
        }
    }
}

// ---------------------------------------------------------------------------
// Kernel: tensor-core attention. Block = (b, window, head), 9 warps,
// each warp owns 16 query rows. S=QK^T and P@V on mma (bf16 split-2),
// softmax + all masks fused on register fragments.
// ---------------------------------------------------------------------------
#define KTST 152    // K^T smem stride (bf16): 304 B = 19*16 -> conflict-free
#define VST  40     // V smem stride (bf16):   80 B = 5*16  -> conflict-free

__global__ __launch_bounds__(288, 1) void attn_mma(const int* __restrict__ pixmap,
                                                   const float* __restrict__ posemb,
                                                   const float* __restrict__ pixemb) {
    __shared__ __align__(16) __nv_bfloat16 KTh[32 * KTST], KTl[32 * KTST];
    __shared__ __align__(16) __nv_bfloat16 Vsh[144 * VST], Vsl[144 * VST];
    __shared__ float pose[529];
    __shared__ float pmv[WSQ];
    __shared__ float pes2[2];

    const int tid = threadIdx.x;
    const int b = blockIdx.y;
    const int w = blockIdx.x / 12;
    const int h = blockIdx.x - w * 12;
    const int tbase = ((b * 64 + w) * 12 + h) * (WSQ * HD);

    // K -> smem transposed (KT[d][j]) with hi/lo split
    for (int id = tid; id < 1152; id += 288) {
        int j = id >> 3, d4 = (id & 7) * 4;
        float4 v = *(const float4*)(g_k + tbase + j * 32 + d4);
        __nv_bfloat16 hh, ll;
        split2(v.x, hh, ll); KTh[(d4 + 0) * KTST + j] = hh; KTl[(d4 + 0) * KTST + j] = ll;
        split2(v.y, hh, ll); KTh[(d4 + 1) * KTST + j] = hh; KTl[(d4 + 1) * KTST + j] = ll;
        split2(v.z, hh, ll); KTh[(d4 + 2) * KTST + j] = hh; KTl[(d4 + 2) * KTST + j] = ll;
        split2(v.w, hh, ll); KTh[(d4 + 3) * KTST + j] = hh; KTl[(d4 + 3) * KTST + j] = ll;
    }
    // V -> smem row-major [j][d] with hi/lo split
    for (int id = tid; id < 1152; id += 288) {
        int j = id >> 3, d4 = (id & 7) * 4;
        float4 v = *(const float4*)(g_v + tbase + j * 32 + d4);
        __nv_bfloat16 h0, h1, h2, h3, l0, l1, l2, l3;
        split2(v.x, h0, l0); split2(v.y, h1, l1);
        split2(v.z, h2, l2); split2(v.w, h3, l3);
        int o = j * VST + d4;
        *(__nv_bfloat162*)(Vsh + o)     = __nv_bfloat162(h0, h1);
        *(__nv_bfloat162*)(Vsh + o + 2) = __nv_bfloat162(h2, h3);
        *(__nv_bfloat162*)(Vsl + o)     = __nv_bfloat162(l0, l1);
        *(__nv_bfloat162*)(Vsl + o + 2) = __nv_bfloat162(l2, l3);
    }
    for (int f = tid; f < 529; f += 288) pose[f] = posemb[f];
    if (tid < 144) {
        int wy = w >> 3, wx = w & 7;
        int iy = tid / 12, ix = tid - iy * 12;
        pmv[tid] = (float)pixmap[(b * 96 + wy * 12 + iy) * 96 + wx * 12 + ix];
    }
    if (tid < 2) pes2[tid] = pixemb[tid];
    __syncthreads();

    const int wr = tid >> 5;        // warp 0..8 -> query rows wr*16..+15
    const int lane = tid & 31;
    const int g = lane >> 2, t = lane & 3;
    const int i0 = wr * 16 + g, i1 = i0 + 8;

    // Q fragments (A operand), loaded direct from gmem, split in-register
    uint32_t qh[2][4], ql[2][4];
    {
        const float* qp = g_q + tbase;
#pragma unroll
        for (int kc = 0; kc < 2; kc++) {
            float2 v0 = *(const float2*)(qp + i0 * 32 + kc * 16 + 2 * t);
            float2 v1 = *(const float2*)(qp + i1 * 32 + kc * 16 + 2 * t);
            float2 v2 = *(const float2*)(qp + i0 * 32 + kc * 16 + 8 + 2 * t);
            float2 v3 = *(const float2*)(qp + i1 * 32 + kc * 16 + 8 + 2 * t);
            __nv_bfloat16 ha, la, hb, lb;
            split2(v0.x, ha, la); split2(v0.y, hb, lb);
            qh[kc][0] = packbf2(ha, hb); ql[kc][0] = packbf2(la, lb);
            split2(v1.x, ha, la); split2(v1.y, hb, lb);
            qh[kc][1] = packbf2(ha, hb); ql[kc][1] = packbf2(la, lb);
            split2(v2.x, ha, la); split2(v2.y, hb, lb);
            qh[kc][2] = packbf2(ha, hb); ql[kc][2] = packbf2(la, lb);
            split2(v3.x, ha, la); split2(v3.y, hb, lb);
            qh[kc][3] = packbf2(ha, hb); ql[kc][3] = packbf2(la, lb);
        }
    }

    // S = Q @ K^T : 18 n-tiles of 8 cols
    float sacc[18][4];
#pragma unroll
    for (int nt = 0; nt < 18; nt++)
#pragma unroll
        for (int c = 0; c < 4; c++) sacc[nt][c] = 0.f;

#pragma unroll
    for (int jg = 0; jg < 9; jg++) {
#pragma unroll
        for (int kc = 0; kc < 2; kc++) {
            uint32_t bh[4], bl[4];
            uint32_t ah_ = smem_u32(KTh + (kc * 16 + (lane & 15)) * KTST +
                                    jg * 16 + (lane >> 4) * 8);
            uint32_t al_ = smem_u32(KTl + (kc * 16 + (lane & 15)) * KTST +
                                    jg * 16 + (lane >> 4) * 8);
            ldsmx4t(bh[0], bh[1], bh[2], bh[3], ah_);
            ldsmx4t(bl[0], bl[1], bl[2], bl[3], al_);
            mma_bf16(sacc[2 * jg],     qh[kc], bh[0], bh[1]);
            mma_bf16(sacc[2 * jg],     qh[kc], bl[0], bl[1]);
            mma_bf16(sacc[2 * jg],     ql[kc], bh[0], bh[1]);
            mma_bf16(sacc[2 * jg + 1], qh[kc], bh[2], bh[3]);
            mma_bf16(sacc[2 * jg + 1], qh[kc], bl[2], bl[3]);
            mma_bf16(sacc[2 * jg + 1], ql[kc], bh[2], bh[3]);
        }
    }

    // softmax + masks on fragments (no max-subtraction: |s| bounded, masked -> p=0)
    const bool ul = (w >> 3) == 7;
    const bool lr = (w & 7) == 7;
    const float pmi0 = pmv[i0], pmi1 = pmv[i1];
    const int iy0 = i0 / 12, ix0 = i0 - iy0 * 12;
    const int iy1 = i1 / 12, ix1 = i1 - iy1 * 12;
    const int pb0 = (11 - iy0) * 23 + (11 - ix0);
    const int pb1 = (11 - iy1) * 23 + (11 - ix1);
    const bool ih0 = i0 >= 72, ih1 = i1 >= 72;
    const bool ixh0 = ix0 >= 6, ixh1 = ix1 >= 6;
    const float pe0 = pes2[0], pe1 = pes2[1];
    const float scale = 0.17677669529663689f;

    float rs0 = 0.f, rs1 = 0.f;
#pragma unroll
    for (int nt = 0; nt < 18; nt++) {
#pragma unroll
        for (int fc = 0; fc < 2; fc++) {
            int j = nt * 8 + 2 * t + fc;
            int jy = j / 12, jx = j - jy * 12;
            float pj = pmv[j];
            bool jh = j >= 72, jxh = jx >= 6;
            int poff = jy * 23 + jx;
            {
                float s = sacc[nt][fc] * scale;
                s += (pmi0 * pj != 0.f) ? pe1 : pe0;
                s += pose[pb0 + poff];
                bool m = (ul && (ih0 != jh)) || (lr && (ixh0 != jxh));
                float p = m ? 0.f : __expf(s);
                sacc[nt][fc] = p; rs0 += p;
            }
            {
                float s = sacc[nt][fc + 2] * scale;
                s += (pmi1 * pj != 0.f) ? pe1 : pe0;
                s += pose[pb1 + poff];
                bool m = (ul && (ih1 != jh)) || (lr && (ixh1 != jxh));
                float p = m ? 0.f : __expf(s);
                sacc[nt][fc + 2] = p; rs1 += p;
            }
        }
    }
    rs0 += __shfl_xor_sync(0xffffffff, rs0, 1);
    rs0 += __shfl_xor_sync(0xffffffff, rs0, 2);
    rs1 += __shfl_xor_sync(0xffffffff, rs1, 1);
    rs1 += __shfl_xor_sync(0xffffffff, rs1, 2);
    const float inv0 = 1.f / rs0, inv1 = 1.f / rs1;

    // O = P @ V : P fragments re-packed from S accumulators (C->A layout match)
    float oacc[4][4];
#pragma unroll
    for (int nt = 0; nt < 4; nt++)
#pragma unroll
        for (int c = 0; c < 4; c++) oacc[nt][c] = 0.f;

#pragma unroll
    for (int kc = 0; kc < 9; kc++) {
        uint32_t ph[4], pl[4];
        {
            __nv_bfloat16 ha, la, hb, lb;
            split2(sacc[2 * kc][0], ha, la); split2(sacc[2 * kc][1], hb, lb);
            ph[0] = packbf2(ha, hb); pl[0] = packbf2(la, lb);
            split2(sacc[2 * kc][2], ha, la); split2(sacc[2 * kc][3], hb, lb);
            ph[1] = packbf2(ha, hb); pl[1] = packbf2(la, lb);
            split2(sacc[2 * kc + 1][0], ha, la); split2(sacc[2 * kc + 1][1], hb, lb);
            ph[2] = packbf2(ha, hb); pl[2] = packbf2(la, lb);
            split2(sacc[2 * kc + 1][2], ha, la); split2(sacc[2 * kc + 1][3], hb, lb);
            ph[3] = packbf2(ha, hb); pl[3] = packbf2(la, lb);
        }
#pragma unroll
        for (int ng = 0; ng < 2; ng++) {
            uint32_t bh[4], bl[4];
            uint32_t ah_ = smem_u32(Vsh + (kc * 16 + (lane & 15)) * VST +
                                    ng * 16 + (lane >> 4) * 8);
            uint32_t al_ = smem_u32(Vsl + (kc * 16 + (lane & 15)) * VST +
                                    ng * 16 + (lane >> 4) * 8);
            ldsmx4t(bh[0], bh[1], bh[2], bh[3], ah_);
            ldsmx4t(bl[0], bl[1], bl[2], bl[3], al_);
            mma_bf16(oacc[2 * ng],     ph, bh[0], bh[1]);
            mma_bf16(oacc[2 * ng],     ph, bl[0], bl[1]);
            mma_bf16(oacc[2 * ng],     pl, bh[0], bh[1]);
            mma_bf16(oacc[2 * ng + 1], ph, bh[2], bh[3]);
            mma_bf16(oacc[2 * ng + 1], ph, bl[2], bl[3]);
            mma_bf16(oacc[2 * ng + 1], pl, bh[2], bh[3]);
        }
    }

    // write normalized output as bf16 hi/lo: [B,NW,144,384] row i, cols h*32+..
    const int orow0 = ((b * 64 + w) * 144 + i0) * 384 + h * 32;
    const int orow1 = ((b * 64 + w) * 144 + i1) * 384 + h * 32;
#pragma unroll
    for (int nt = 0; nt < 4; nt++) {
        int col = nt * 8 + 2 * t;
        __nv_bfloat16 ha, la, hb, lb;
        float f0 = oacc[nt][0] * inv0, f1 = oacc[nt][1] * inv0;
        split2(f0, ha, la); split2(f1, hb, lb);
        *(uint32_t*)(g_atth + orow0 + col) = packbf2(ha, hb);
        *(uint32_t*)(g_attl + orow0 + col) = packbf2(la, lb);
        float f2 = oacc[nt][2] * inv1, f3 = oacc[nt][3] * inv1;
        split2(f2, ha, la); split2(f3, hb, lb);
        *(uint32_t*)(g_atth + orow1 + col) = packbf2(ha, hb);
        *(uint32_t*)(g_attl + orow1 + col) = packbf2(la, lb);
    }
}

// ---------------------------------------------------------------------------
// Kernel: output projection + bias + window-merge + roll(+6,+6) scatter
// ---------------------------------------------------------------------------
__global__ __launch_bounds__(256, 1) void out_gemm_mma(const float* __restrict__ bout,
                                                       float* __restrict__ Out) {
    GEMM_MAINLOOP(g_atth, g_attl, g_woh, g_wol, 384)

#pragma unroll
    for (int mt = 0; mt < 2; mt++) {
#pragma unroll
        for (int rr = 0; rr < 2; rr++) {
            int r = m0 + wm + mt * 16 + (lane >> 2) + rr * 8;
            int b = r / 9216; int rem = r - b * 9216;
            int w = rem / 144; int i = rem - w * 144;
            int iy = i / 12, ix = i - iy * 12;
            int y = (w >> 3) * 12 + iy + 6; if (y >= 96) y -= 96;
            int x = (w & 7) * 12 + ix + 6;  if (x >= 96) x -= 96;
            float* orow = Out + ((b * 96 + y) * 96 + x) * 384;
#pragma unroll
            for (int nt = 0; nt < 8; nt++) {
                int c = n0 + wn + nt * 8 + (lane & 3) * 2;
                float2 bi = *(const float2*)(bout + c);
                float2 v = make_float2(acc[mt][nt][rr * 2] + bi.x,
                                       acc[mt][nt][rr * 2 + 1] + bi.y);
                *(float2*)(orow + c) = v;
            }
        }
    }
}

// ---------------------------------------------------------------------------
extern "C" void kernel_launch(void* const* d_in, const int* in_sizes, int n_in,
                              void* d_out, int out_size) {
    (void)in_sizes; (void)n_in; (void)out_size;
    const float* x      = (const float*)d_in[0];
    const int*   pixmap = (const int*)d_in[1];
    const float* wqkv   = (const float*)d_in[2];
    const float* posemb = (const float*)d_in[3];
    const float* pixemb = (const float*)d_in[4];
    const float* wout   = (const float*)d_in[5];
    const float* bout   = (const float*)d_in[6];
    float* out = (float*)d_out;

    cudaFuncSetAttribute(qkv_gemm_mma, cudaFuncAttributeMaxDynamicSharedMemorySize,
                         SMEM_BYTES);
    cudaFuncSetAttribute(out_gemm_mma, cudaFuncAttributeMaxDynamicSharedMemorySize,
                         SMEM_BYTES);

    prep_x<<<MROWS, 96>>>(x);
    prep_w<<<576, 256>>>(wqkv, wout);
    qkv_gemm_mma<<<dim3(QKV_N / 128, MROWS / 128), 256, SMEM_BYTES>>>();
    attn_mma<<<dim3(NW * NHEADS, BB), 288>>>(pixmap, posemb, pixemb);
    out_gemm_mma<<<dim3(384 / 128, MROWS / 128), 256, SMEM_BYTES>>>(bout, out);
}

// round 5
// speedup vs baseline: 1.8638x; 1.0738x over previous
#include <cuda_runtime.h>
#include <cuda_bf16.h>
#include <cstdint>

// Shapes
#define BB     8
#define NHEADS 12
#define HD     32
#define NW     64
#define WSQ    144
#define MROWS  73728        // BB*NW*WSQ
#define QKV_N  1152

// Scratch (allocation-free rule: __device__ globals)
__device__ __nv_bfloat16 g_qh[MROWS * 384];   // per-head [B,NW,H,144,32]
__device__ __nv_bfloat16 g_ql[MROWS * 384];
__device__ __nv_bfloat16 g_kth[MROWS * 384];  // per-head transposed [B,NW,H,32,144]
__device__ __nv_bfloat16 g_ktl[MROWS * 384];
__device__ __nv_bfloat16 g_vh[MROWS * 384];   // per-head [B,NW,H,144,32]
__device__ __nv_bfloat16 g_vl[MROWS * 384];
__device__ __nv_bfloat16 g_xh[MROWS * 384];
__device__ __nv_bfloat16 g_xl[MROWS * 384];
__device__ __nv_bfloat16 g_atth[MROWS * 384];
__device__ __nv_bfloat16 g_attl[MROWS * 384];
__device__ __nv_bfloat16 g_wqh[384 * QKV_N];
__device__ __nv_bfloat16 g_wql[384 * QKV_N];
__device__ __nv_bfloat16 g_woh[384 * 384];
__device__ __nv_bfloat16 g_wol[384 * 384];

// ---------------------------------------------------------------------------
// helpers
// ---------------------------------------------------------------------------
__device__ __forceinline__ uint32_t smem_u32(const void* p) {
    return (uint32_t)__cvta_generic_to_shared(p);
}
__device__ __forceinline__ void ldsmx4(uint32_t& r0, uint32_t& r1, uint32_t& r2,
                                       uint32_t& r3, uint32_t a) {
    asm volatile("ldmatrix.sync.aligned.m8n8.x4.shared.b16 {%0,%1,%2,%3}, [%4];"
                 : "=r"(r0), "=r"(r1), "=r"(r2), "=r"(r3) : "r"(a));
}
__device__ __forceinline__ void ldsmx4t(uint32_t& r0, uint32_t& r1, uint32_t& r2,
                                        uint32_t& r3, uint32_t a) {
    asm volatile("ldmatrix.sync.aligned.m8n8.x4.trans.shared.b16 {%0,%1,%2,%3}, [%4];"
                 : "=r"(r0), "=r"(r1), "=r"(r2), "=r"(r3) : "r"(a));
}
__device__ __forceinline__ void mma_bf16(float* c, const uint32_t* a,
                                         uint32_t b0, uint32_t b1) {
    asm volatile(
        "mma.sync.aligned.m16n8k16.row.col.f32.bf16.bf16.f32 "
        "{%0,%1,%2,%3},{%4,%5,%6,%7},{%8,%9},{%0,%1,%2,%3};"
        : "+f"(c[0]), "+f"(c[1]), "+f"(c[2]), "+f"(c[3])
        : "r"(a[0]), "r"(a[1]), "r"(a[2]), "r"(a[3]), "r"(b0), "r"(b1));
}
__device__ __forceinline__ void split2(float f, __nv_bfloat16& h, __nv_bfloat16& l) {
    h = __float2bfloat16_rn(f);
    l = __float2bfloat16_rn(f - __bfloat162float(h));
}
__device__ __forceinline__ uint32_t packbf2(__nv_bfloat16 a, __nv_bfloat16 b) {
    __nv_bfloat162 v(a, b);
    return *(uint32_t*)&v;
}
__device__ __forceinline__ void cpasync16(void* s, const void* g) {
    asm volatile("cp.async.cg.shared.global [%0], [%1], 16;"
                 :: "r"(smem_u32(s)), "l"(g));
}

#define AST  40      // A smem row stride (bf16): 80 B = 5*16 -> conflict-free
#define BST  136     // B smem row stride (bf16): 272 B = 17*16 -> conflict-free
#define A_STAGE 5120 // 128*AST
#define B_STAGE 4352 // 32*BST
#define SMEM_BYTES ((4 * A_STAGE + 4 * B_STAGE) * 2)   // 75776

// ---------------------------------------------------------------------------
// Prep kernels: roll-gather + fp32 -> bf16 hi/lo split
// ---------------------------------------------------------------------------
__global__ void prep_x(const float* __restrict__ X) {
    const int r = blockIdx.x;
    int b = r / 9216; int rem = r - b * 9216;
    int w = rem / 144; int i = rem - w * 144;
    int y = (w >> 3) * 12 + i / 12 + 6; if (y >= 96) y -= 96;
    int x = (w & 7) * 12 + i % 12 + 6;  if (x >= 96) x -= 96;
    const float4* src = (const float4*)(X + ((b * 96 + y) * 96 + x) * 384);
    const int t = threadIdx.x;          // 96 threads, 4 floats each
    float4 v = src[t];
    __nv_bfloat16 hx, hy, hz, hw, lx, ly, lz, lw;
    split2(v.x, hx, lx); split2(v.y, hy, ly);
    split2(v.z, hz, lz); split2(v.w, hw, lw);
    int o = r * 384 + t * 4;
    *(__nv_bfloat162*)(g_xh + o)     = __nv_bfloat162(hx, hy);
    *(__nv_bfloat162*)(g_xh + o + 2) = __nv_bfloat162(hz, hw);
    *(__nv_bfloat162*)(g_xl + o)     = __nv_bfloat162(lx, ly);
    *(__nv_bfloat162*)(g_xl + o + 2) = __nv_bfloat162(lz, lw);
}

__global__ void prep_w(const float* __restrict__ wqkv, const float* __restrict__ wout) {
    const int id = blockIdx.x * 256 + threadIdx.x;  // float4 index
    float4 v;
    __nv_bfloat16* oh; __nv_bfloat16* ol; int o;
    if (id < 110592) {                        // 384*1152/4
        v = ((const float4*)wqkv)[id];
        oh = g_wqh; ol = g_wql; o = id * 4;
    } else {
        int id2 = id - 110592;                // < 36864
        v = ((const float4*)wout)[id2];
        oh = g_woh; ol = g_wol; o = id2 * 4;
    }
    __nv_bfloat16 hx, hy, hz, hw, lx, ly, lz, lw;
    split2(v.x, hx, lx); split2(v.y, hy, ly);
    split2(v.z, hz, lz); split2(v.w, hw, lw);
    *(__nv_bfloat162*)(oh + o)     = __nv_bfloat162(hx, hy);
    *(__nv_bfloat162*)(oh + o + 2) = __nv_bfloat162(hz, hw);
    *(__nv_bfloat162*)(ol + o)     = __nv_bfloat162(lx, ly);
    *(__nv_bfloat162*)(ol + o + 2) = __nv_bfloat162(lz, lw);
}

// ---------------------------------------------------------------------------
// Shared GEMM pieces: 128x128 tile, BK=32, 256 thr, 8 warps (4m x 2n, 32x64)
// ---------------------------------------------------------------------------
__device__ __forceinline__ void load_stage(
    const __nv_bfloat16* __restrict__ Agh, const __nv_bfloat16* __restrict__ Agl,
    const __nv_bfloat16* __restrict__ Bgh, const __nv_bfloat16* __restrict__ Bgl,
    __nv_bfloat16* Ah, __nv_bfloat16* Al, __nv_bfloat16* Bh, __nv_bfloat16* Bl,
    int m0, int n0, int ldb, int k0, int st, int tid)
{
    __nv_bfloat16* ash = Ah + st * A_STAGE;
    __nv_bfloat16* asl = Al + st * A_STAGE;
    __nv_bfloat16* bsh = Bh + st * B_STAGE;
    __nv_bfloat16* bsl = Bl + st * B_STAGE;
#pragma unroll
    for (int q = 0; q < 2; q++) {
        int c = tid * 2 + q;
        int row = c >> 2, ch = (c & 3) * 8;                 // A: 128 x 32
        int go = (m0 + row) * 384 + k0 + ch;
        int so = row * AST + ch;
        cpasync16(ash + so, Agh + go);
        cpasync16(asl + so, Agl + go);
    }
#pragma unroll
    for (int q = 0; q < 2; q++) {
        int c = tid * 2 + q;
        int row = c >> 4, ch = (c & 15) * 8;                // B: 32 x 128
        int go = (k0 + row) * ldb + n0 + ch;
        int so = row * BST + ch;
        cpasync16(bsh + so, Bgh + go);
        cpasync16(bsl + so, Bgl + go);
    }
}

__device__ __forceinline__ void compute_stage(
    const __nv_bfloat16* Ah, const __nv_bfloat16* Al,
    const __nv_bfloat16* Bh, const __nv_bfloat16* Bl,
    int wm, int wn, int lane, float acc[2][8][4])
{
#pragma unroll
    for (int ks = 0; ks < 2; ks++) {
        const int kk = ks * 16;
        uint32_t ah[2][4], al[2][4], bh[4][4], bl[4][4];
        const int arow = wm + (lane & 15);
        const int acol = kk + (lane >> 4) * 8;
#pragma unroll
        for (int mt = 0; mt < 2; mt++) {
            ldsmx4(ah[mt][0], ah[mt][1], ah[mt][2], ah[mt][3],
                   smem_u32(Ah + (arow + mt * 16) * AST + acol));
            ldsmx4(al[mt][0], al[mt][1], al[mt][2], al[mt][3],
                   smem_u32(Al + (arow + mt * 16) * AST + acol));
        }
        const int bk = kk + (lane & 15);
        const int bnb = wn + (lane >> 4) * 8;
#pragma unroll
        for (int g = 0; g < 4; g++) {
            ldsmx4t(bh[g][0], bh[g][1], bh[g][2], bh[g][3],
                    smem_u32(Bh + bk * BST + bnb + g * 16));
            ldsmx4t(bl[g][0], bl[g][1], bl[g][2], bl[g][3],
                    smem_u32(Bl + bk * BST + bnb + g * 16));
        }
#pragma unroll
        for (int mt = 0; mt < 2; mt++)
#pragma unroll
            for (int g = 0; g < 4; g++)
#pragma unroll
                for (int hf = 0; hf < 2; hf++) {
                    float* c = acc[mt][2 * g + hf];
                    mma_bf16(c, ah[mt], bh[g][2 * hf], bh[g][2 * hf + 1]);
                    mma_bf16(c, ah[mt], bl[g][2 * hf], bl[g][2 * hf + 1]);
                    mma_bf16(c, al[mt], bh[g][2 * hf], bh[g][2 * hf + 1]);
                }
    }
}

#define GEMM_MAINLOOP(AGH, AGL, BGH, BGL, LDB)                                   \
    extern __shared__ __align__(16) __nv_bfloat16 smem[];                        \
    __nv_bfloat16* Ah = smem;                                                    \
    __nv_bfloat16* Al = smem + 2 * A_STAGE;                                      \
    __nv_bfloat16* Bh = smem + 4 * A_STAGE;                                      \
    __nv_bfloat16* Bl = smem + 4 * A_STAGE + 2 * B_STAGE;                        \
    const int tid = threadIdx.x;                                                 \
    const int m0 = blockIdx.y * 128;                                             \
    const int n0 = blockIdx.x * 128;                                             \
    const int wid = tid >> 5, lane = tid & 31;                                   \
    const int wm = (wid >> 1) * 32;                                              \
    const int wn = (wid & 1) * 64;                                               \
    float acc[2][8][4];                                                          \
    _Pragma("unroll") for (int a_ = 0; a_ < 2; a_++)                             \
    _Pragma("unroll") for (int b_ = 0; b_ < 8; b_++)                             \
    _Pragma("unroll") for (int c_ = 0; c_ < 4; c_++) acc[a_][b_][c_] = 0.f;      \
    load_stage(AGH, AGL, BGH, BGL, Ah, Al, Bh, Bl, m0, n0, LDB, 0, 0, tid);      \
    asm volatile("cp.async.commit_group;" ::: "memory");                         \
    for (int it = 0; it < 12; it++) {                                            \
        if (it < 11) {                                                           \
            load_stage(AGH, AGL, BGH, BGL, Ah, Al, Bh, Bl, m0, n0, LDB,          \
                       (it + 1) * 32, (it + 1) & 1, tid);                        \
            asm volatile("cp.async.commit_group;" ::: "memory");                 \
            asm volatile("cp.async.wait_group 1;" ::: "memory");                 \
        } else {                                                                 \
            asm volatile("cp.async.wait_group 0;" ::: "memory");                 \
        }                                                                        \
        __syncthreads();                                                         \
        const int st = it & 1;                                                   \
        compute_stage(Ah + st * A_STAGE, Al + st * A_STAGE,                      \
                      Bh + st * B_STAGE, Bl + st * B_STAGE, wm, wn, lane, acc);  \
        __syncthreads();                                                         \
    }

// ---------------------------------------------------------------------------
// Kernel: QKV GEMM -> emit attention-ready bf16 hi/lo:
//   Q,V row-major per-head [.,144,32]; K transposed per-head [.,32,144].
// ---------------------------------------------------------------------------
__global__ __launch_bounds__(256, 1) void qkv_gemm_mma() {
    GEMM_MAINLOOP(g_xh, g_xl, g_wqh, g_wql, QKV_N)

    const int part = n0 / 384;
    const int cbase = n0 - part * 384;

#pragma unroll
    for (int mt = 0; mt < 2; mt++) {
#pragma unroll
        for (int rr = 0; rr < 2; rr++) {
            int r = m0 + wm + mt * 16 + (lane >> 2) + rr * 8;
            int b = r / 9216; int rem = r - b * 9216;
            int w = rem / 144; int i = rem - w * 144;
            int bw12 = (b * 64 + w) * 12;
#pragma unroll
            for (int nt = 0; nt < 8; nt++) {
                int c = cbase + wn + nt * 8 + (lane & 3) * 2;
                int h = c >> 5, d = c & 31;
                float f0 = acc[mt][nt][rr * 2], f1 = acc[mt][nt][rr * 2 + 1];
                __nv_bfloat16 h0, l0, h1, l1;
                split2(f0, h0, l0); split2(f1, h1, l1);
                if (part == 1) {              // K: transposed [32][144]
                    int tk = (bw12 + h) * 4608 + d * 144 + i;
                    g_kth[tk] = h0; g_kth[tk + 144] = h1;
                    g_ktl[tk] = l0; g_ktl[tk + 144] = l1;
                } else {                      // Q / V: row-major [144][32]
                    int tq = ((bw12 + h) * 144 + i) * 32 + d;
                    __nv_bfloat16* oh = (part == 0) ? g_qh : g_vh;
                    __nv_bfloat16* ol = (part == 0) ? g_ql : g_vl;
                    *(uint32_t*)(oh + tq) = packbf2(h0, h1);
                    *(uint32_t*)(ol + tq) = packbf2(l0, l1);
                }
            }
        }
    }
}

// ---------------------------------------------------------------------------
// Kernel: tensor-core attention. Block = (b, window, head), 9 warps,
// each warp owns 16 query rows. All operands arrive pre-split bf16 via
// cp.async; softmax + masks fused on register fragments.
// ---------------------------------------------------------------------------
#define KTST 152    // K^T smem stride (bf16): 304 B = 19*16 -> conflict-free
#define VST  40     // V smem stride (bf16):   80 B = 5*16  -> conflict-free

__global__ __launch_bounds__(288, 1) void attn_mma(const int* __restrict__ pixmap,
                                                   const float* __restrict__ posemb,
                                                   const float* __restrict__ pixemb) {
    __shared__ __align__(16) __nv_bfloat16 KTh[32 * KTST], KTl[32 * KTST];
    __shared__ __align__(16) __nv_bfloat16 Vsh[144 * VST], Vsl[144 * VST];
    __shared__ float pose[529];
    __shared__ float pmv[WSQ];
    __shared__ float pes2[2];

    const int tid = threadIdx.x;
    const int b = blockIdx.y;
    const int w = blockIdx.x / 12;
    const int h = blockIdx.x - w * 12;
    const int tb2 = ((b * 64 + w) * 12 + h) * 4608;

    // K^T tiles: 32 rows x 144 bf16 = 18 chunks/row
#pragma unroll
    for (int q = 0; q < 2; q++) {
        int cix = tid + q * 288;                  // < 576
        int d = cix / 18, ch = (cix - d * 18) * 8;
        cpasync16(KTh + d * KTST + ch, g_kth + tb2 + d * 144 + ch);
        cpasync16(KTl + d * KTST + ch, g_ktl + tb2 + d * 144 + ch);
    }
    // V tiles: 144 rows x 32 bf16 = 4 chunks/row
#pragma unroll
    for (int q = 0; q < 2; q++) {
        int cix = tid + q * 288;                  // < 576
        int j = cix >> 2, ch = (cix & 3) * 8;
        cpasync16(Vsh + j * VST + ch, g_vh + tb2 + j * 32 + ch);
        cpasync16(Vsl + j * VST + ch, g_vl + tb2 + j * 32 + ch);
    }
    asm volatile("cp.async.commit_group;" ::: "memory");

    for (int f = tid; f < 529; f += 288) pose[f] = posemb[f];
    if (tid < 144) {
        int wy = w >> 3, wx = w & 7;
        int iy = tid / 12, ix = tid - iy * 12;
        pmv[tid] = (float)pixmap[(b * 96 + wy * 12 + iy) * 96 + wx * 12 + ix];
    }
    if (tid < 2) pes2[tid] = pixemb[tid];

    const int wr = tid >> 5;        // warp 0..8 -> query rows wr*16..+15
    const int lane = tid & 31;
    const int g = lane >> 2, t = lane & 3;
    const int i0 = wr * 16 + g, i1 = i0 + 8;

    // Q fragments: packed bf16x2 direct from gmem (pre-split)
    uint32_t qh[2][4], ql[2][4];
#pragma unroll
    for (int kc = 0; kc < 2; kc++) {
        int o0 = tb2 + i0 * 32 + kc * 16 + 2 * t;
        int o1 = tb2 + i1 * 32 + kc * 16 + 2 * t;
        qh[kc][0] = *(const uint32_t*)(g_qh + o0);
        ql[kc][0] = *(const uint32_t*)(g_ql + o0);
        qh[kc][1] = *(const uint32_t*)(g_qh + o1);
        ql[kc][1] = *(const uint32_t*)(g_ql + o1);
        qh[kc][2] = *(const uint32_t*)(g_qh + o0 + 8);
        ql[kc][2] = *(const uint32_t*)(g_ql + o0 + 8);
        qh[kc][3] = *(const uint32_t*)(g_qh + o1 + 8);
        ql[kc][3] = *(const uint32_t*)(g_ql + o1 + 8);
    }

    asm volatile("cp.async.wait_group 0;" ::: "memory");
    __syncthreads();

    // S = Q @ K^T : 18 n-tiles of 8 cols
    float sacc[18][4];
#pragma unroll
    for (int nt = 0; nt < 18; nt++)
#pragma unroll
        for (int c = 0; c < 4; c++) sacc[nt][c] = 0.f;

#pragma unroll
    for (int jg = 0; jg < 9; jg++) {
#pragma unroll
        for (int kc = 0; kc < 2; kc++) {
            uint32_t bh[4], bl[4];
            uint32_t ah_ = smem_u32(KTh + (kc * 16 + (lane & 15)) * KTST +
                                    jg * 16 + (lane >> 4) * 8);
            uint32_t al_ = smem_u32(KTl + (kc * 16 + (lane & 15)) * KTST +
                                    jg * 16 + (lane >> 4) * 8);
            ldsmx4t(bh[0], bh[1], bh[2], bh[3], ah_);
            ldsmx4t(bl[0], bl[1], bl[2], bl[3], al_);
            mma_bf16(sacc[2 * jg],     qh[kc], bh[0], bh[1]);
            mma_bf16(sacc[2 * jg],     qh[kc], bl[0], bl[1]);
            mma_bf16(sacc[2 * jg],     ql[kc], bh[0], bh[1]);
            mma_bf16(sacc[2 * jg + 1], qh[kc], bh[2], bh[3]);
            mma_bf16(sacc[2 * jg + 1], qh[kc], bl[2], bl[3]);
            mma_bf16(sacc[2 * jg + 1], ql[kc], bh[2], bh[3]);
        }
    }

    // softmax + masks on fragments (no max-subtraction: |s| bounded, masked -> p=0)
    const bool ul = (w >> 3) == 7;
    const bool lr = (w & 7) == 7;
    const float pmi0 = pmv[i0], pmi1 = pmv[i1];
    const int iy0 = i0 / 12, ix0 = i0 - iy0 * 12;
    const int iy1 = i1 / 12, ix1 = i1 - iy1 * 12;
    const int pb0 = (11 - iy0) * 23 + (11 - ix0);
    const int pb1 = (11 - iy1) * 23 + (11 - ix1);
    const bool ih0 = i0 >= 72, ih1 = i1 >= 72;
    const bool ixh0 = ix0 >= 6, ixh1 = ix1 >= 6;
    const float pe0 = pes2[0], pe1 = pes2[1];
    const float scale = 0.17677669529663689f;

    float rs0 = 0.f, rs1 = 0.f;
#pragma unroll
    for (int nt = 0; nt < 18; nt++) {
#pragma unroll
        for (int fc = 0; fc < 2; fc++) {
            int j = nt * 8 + 2 * t + fc;
            int jy = j / 12, jx = j - jy * 12;
            float pj = pmv[j];
            bool jh = j >= 72, jxh = jx >= 6;
            int poff = jy * 23 + jx;
            {
                float s = sacc[nt][fc] * scale;
                s += (pmi0 * pj != 0.f) ? pe1 : pe0;
                s += pose[pb0 + poff];
                bool m = (ul && (ih0 != jh)) || (lr && (ixh0 != jxh));
                float p = m ? 0.f : __expf(s);
                sacc[nt][fc] = p; rs0 += p;
            }
            {
                float s = sacc[nt][fc + 2] * scale;
                s += (pmi1 * pj != 0.f) ? pe1 : pe0;
                s += pose[pb1 + poff];
                bool m = (ul && (ih1 != jh)) || (lr && (ixh1 != jxh));
                float p = m ? 0.f : __expf(s);
                sacc[nt][fc + 2] = p; rs1 += p;
            }
        }
    }
    rs0 += __shfl_xor_sync(0xffffffff, rs0, 1);
    rs0 += __shfl_xor_sync(0xffffffff, rs0, 2);
    rs1 += __shfl_xor_sync(0xffffffff, rs1, 1);
    rs1 += __shfl_xor_sync(0xffffffff, rs1, 2);
    const float inv0 = 1.f / rs0, inv1 = 1.f / rs1;

    // O = P @ V : P fragments re-packed from S accumulators (C->A layout match)
    float oacc[4][4];
#pragma unroll
    for (int nt = 0; nt < 4; nt++)
#pragma unroll
        for (int c = 0; c < 4; c++) oacc[nt][c] = 0.f;

#pragma unroll
    for (int kc = 0; kc < 9; kc++) {
        uint32_t ph[4], pl[4];
        {
            __nv_bfloat16 ha, la, hb, lb;
            split2(sacc[2 * kc][0], ha, la); split2(sacc[2 * kc][1], hb, lb);
            ph[0] = packbf2(ha, hb); pl[0] = packbf2(la, lb);
            split2(sacc[2 * kc][2], ha, la); split2(sacc[2 * kc][3], hb, lb);
            ph[1] = packbf2(ha, hb); pl[1] = packbf2(la, lb);
            split2(sacc[2 * kc + 1][0], ha, la); split2(sacc[2 * kc + 1][1], hb, lb);
            ph[2] = packbf2(ha, hb); pl[2] = packbf2(la, lb);
            split2(sacc[2 * kc + 1][2], ha, la); split2(sacc[2 * kc + 1][3], hb, lb);
            ph[3] = packbf2(ha, hb); pl[3] = packbf2(la, lb);
        }
#pragma unroll
        for (int ng = 0; ng < 2; ng++) {
            uint32_t bh[4], bl[4];
            uint32_t ah_ = smem_u32(Vsh + (kc * 16 + (lane & 15)) * VST +
                                    ng * 16 + (lane >> 4) * 8);
            uint32_t al_ = smem_u32(Vsl + (kc * 16 + (lane & 15)) * VST +
                                    ng * 16 + (lane >> 4) * 8);
            ldsmx4t(bh[0], bh[1], bh[2], bh[3], ah_);
            ldsmx4t(bl[0], bl[1], bl[2], bl[3], al_);
            mma_bf16(oacc[2 * ng],     ph, bh[0], bh[1]);
            mma_bf16(oacc[2 * ng],     ph, bl[0], bl[1]);
            mma_bf16(oacc[2 * ng],     pl, bh[0], bh[1]);
            mma_bf16(oacc[2 * ng + 1], ph, bh[2], bh[3]);
            mma_bf16(oacc[2 * ng + 1], ph, bl[2], bl[3]);
            mma_bf16(oacc[2 * ng + 1], pl, bh[2], bh[3]);
        }
    }

    // write normalized output as bf16 hi/lo: [B,NW,144,384] row i, cols h*32+..
    const int orow0 = ((b * 64 + w) * 144 + i0) * 384 + h * 32;
    const int orow1 = ((b * 64 + w) * 144 + i1) * 384 + h * 32;
#pragma unroll
    for (int nt = 0; nt < 4; nt++) {
        int col = nt * 8 + 2 * t;
        __nv_bfloat16 ha, la, hb, lb;
        float f0 = oacc[nt][0] * inv0, f1 = oacc[nt][1] * inv0;
        split2(f0, ha, la); split2(f1, hb, lb);
        *(uint32_t*)(g_atth + orow0 + col) = packbf2(ha, hb);
        *(uint32_t*)(g_attl + orow0 + col) = packbf2(la, lb);
        float f2 = oacc[nt][2] * inv1, f3 = oacc[nt][3] * inv1;
        split2(f2, ha, la); split2(f3, hb, lb);
        *(uint32_t*)(g_atth + orow1 + col) = packbf2(ha, hb);
        *(uint32_t*)(g_attl + orow1 + col) = packbf2(la, lb);
    }
}

// ---------------------------------------------------------------------------
// Kernel: output projection + bias + window-merge + roll(+6,+6) scatter
// ---------------------------------------------------------------------------
__global__ __launch_bounds__(256, 1) void out_gemm_mma(const float* __restrict__ bout,
                                                       float* __restrict__ Out) {
    GEMM_MAINLOOP(g_atth, g_attl, g_woh, g_wol, 384)

#pragma unroll
    for (int mt = 0; mt < 2; mt++) {
#pragma unroll
        for (int rr = 0; rr < 2; rr++) {
            int r = m0 + wm + mt * 16 + (lane >> 2) + rr * 8;
            int b = r / 9216; int rem = r - b * 9216;
            int w = rem / 144; int i = rem - w * 144;
            int iy = i / 12, ix = i - iy * 12;
            int y = (w >> 3) * 12 + iy + 6; if (y >= 96) y -= 96;
            int x = (w & 7) * 12 + ix + 6;  if (x >= 96) x -= 96;
            float* orow = Out + ((b * 96 + y) * 96 + x) * 384;
#pragma unroll
            for (int nt = 0; nt < 8; nt++) {
                int c = n0 + wn + nt * 8 + (lane & 3) * 2;
                float2 bi = *(const float2*)(bout + c);
                float2 v = make_float2(acc[mt][nt][rr * 2] + bi.x,
                                       acc[mt][nt][rr * 2 + 1] + bi.y);
                *(float2*)(orow + c) = v;
            }
        }
    }
}

// ---------------------------------------------------------------------------
extern "C" void kernel_launch(void* const* d_in, const int* in_sizes, int n_in,
                              void* d_out, int out_size) {
    (void)in_sizes; (void)n_in; (void)out_size;
    const float* x      = (const float*)d_in[0];
    const int*   pixmap = (const int*)d_in[1];
    const float* wqkv   = (const float*)d_in[2];
    const float* posemb = (const float*)d_in[3];
    const float* pixemb = (const float*)d_in[4];
    const float* wout   = (const float*)d_in[5];
    const float* bout   = (const float*)d_in[6];
    float* out = (float*)d_out;

    cudaFuncSetAttribute(qkv_gemm_mma, cudaFuncAttributeMaxDynamicSharedMemorySize,
                         SMEM_BYTES);
    cudaFuncSetAttribute(out_gemm_mma, cudaFuncAttributeMaxDynamicSharedMemorySize,
                         SMEM_BYTES);

    prep_x<<<MROWS, 96>>>(x);
    prep_w<<<576, 256>>>(wqkv, wout);
    qkv_gemm_mma<<<dim3(QKV_N / 128, MROWS / 128), 256, SMEM_BYTES>>>();
    attn_mma<<<dim3(NW * NHEADS, BB), 288>>>(pixmap, posemb, pixemb);
    out_gemm_mma<<<dim3(384 / 128, MROWS / 128), 256, SMEM_BYTES>>>(bout, out);
}

// round 6
// speedup vs baseline: 1.9720x; 1.0581x over previous
#include <cuda_runtime.h>
#include <cuda_bf16.h>
#include <cstdint>

// Shapes
#define BB     8
#define NHEADS 12
#define HD     32
#define NW     64
#define WSQ    144
#define MROWS  73728        // BB*NW*WSQ
#define QKV_N  1152

// Scratch (allocation-free rule: __device__ globals)
__device__ __nv_bfloat16 g_qh[MROWS * 384];   // per-head [B,NW,H,144,32]
__device__ __nv_bfloat16 g_ql[MROWS * 384];
__device__ __nv_bfloat16 g_kth[MROWS * 384];  // per-head transposed [B,NW,H,32,144]
__device__ __nv_bfloat16 g_ktl[MROWS * 384];
__device__ __nv_bfloat16 g_vh[MROWS * 384];   // per-head [B,NW,H,144,32]
__device__ __nv_bfloat16 g_vl[MROWS * 384];
__device__ __nv_bfloat16 g_xh[MROWS * 384];
__device__ __nv_bfloat16 g_xl[MROWS * 384];
__device__ __nv_bfloat16 g_atth[MROWS * 384];
__device__ __nv_bfloat16 g_attl[MROWS * 384];
__device__ __nv_bfloat16 g_wqh[384 * QKV_N];
__device__ __nv_bfloat16 g_wql[384 * QKV_N];
__device__ __nv_bfloat16 g_woh[384 * 384];
__device__ __nv_bfloat16 g_wol[384 * 384];

// ---------------------------------------------------------------------------
// helpers
// ---------------------------------------------------------------------------
__device__ __forceinline__ uint32_t smem_u32(const void* p) {
    return (uint32_t)__cvta_generic_to_shared(p);
}
__device__ __forceinline__ void ldsmx4(uint32_t& r0, uint32_t& r1, uint32_t& r2,
                                       uint32_t& r3, uint32_t a) {
    asm volatile("ldmatrix.sync.aligned.m8n8.x4.shared.b16 {%0,%1,%2,%3}, [%4];"
                 : "=r"(r0), "=r"(r1), "=r"(r2), "=r"(r3) : "r"(a));
}
__device__ __forceinline__ void ldsmx4t(uint32_t& r0, uint32_t& r1, uint32_t& r2,
                                        uint32_t& r3, uint32_t a) {
    asm volatile("ldmatrix.sync.aligned.m8n8.x4.trans.shared.b16 {%0,%1,%2,%3}, [%4];"
                 : "=r"(r0), "=r"(r1), "=r"(r2), "=r"(r3) : "r"(a));
}
__device__ __forceinline__ void mma_bf16(float* c, const uint32_t* a,
                                         uint32_t b0, uint32_t b1) {
    asm volatile(
        "mma.sync.aligned.m16n8k16.row.col.f32.bf16.bf16.f32 "
        "{%0,%1,%2,%3},{%4,%5,%6,%7},{%8,%9},{%0,%1,%2,%3};"
        : "+f"(c[0]), "+f"(c[1]), "+f"(c[2]), "+f"(c[3])
        : "r"(a[0]), "r"(a[1]), "r"(a[2]), "r"(a[3]), "r"(b0), "r"(b1));
}
__device__ __forceinline__ void split2(float f, __nv_bfloat16& h, __nv_bfloat16& l) {
    h = __float2bfloat16_rn(f);
    l = __float2bfloat16_rn(f - __bfloat162float(h));
}
__device__ __forceinline__ uint32_t packbf2(__nv_bfloat16 a, __nv_bfloat16 b) {
    __nv_bfloat162 v(a, b);
    return *(uint32_t*)&v;
}
__device__ __forceinline__ void cpasync16(void* s, const void* g) {
    asm volatile("cp.async.cg.shared.global [%0], [%1], 16;"
                 :: "r"(smem_u32(s)), "l"(g));
}

#define AST  40      // A smem row stride (bf16): 80 B = 5*16 -> conflict-free
#define BST  136     // B smem row stride (bf16): 272 B = 17*16 -> conflict-free
#define A_STAGE 5120 // 128*AST
#define B_STAGE 4352 // 32*BST
#define SMEM_BYTES ((4 * A_STAGE + 4 * B_STAGE) * 2)   // 75776

// ---------------------------------------------------------------------------
// Prep kernels: roll-gather + fp32 -> bf16 hi/lo split
// ---------------------------------------------------------------------------
__global__ void prep_x(const float* __restrict__ X) {
    const int r = blockIdx.x;
    int b = r / 9216; int rem = r - b * 9216;
    int w = rem / 144; int i = rem - w * 144;
    int y = (w >> 3) * 12 + i / 12 + 6; if (y >= 96) y -= 96;
    int x = (w & 7) * 12 + i % 12 + 6;  if (x >= 96) x -= 96;
    const float4* src = (const float4*)(X + ((b * 96 + y) * 96 + x) * 384);
    const int t = threadIdx.x;          // 96 threads, 4 floats each
    float4 v = src[t];
    __nv_bfloat16 hx, hy, hz, hw, lx, ly, lz, lw;
    split2(v.x, hx, lx); split2(v.y, hy, ly);
    split2(v.z, hz, lz); split2(v.w, hw, lw);
    int o = r * 384 + t * 4;
    *(__nv_bfloat162*)(g_xh + o)     = __nv_bfloat162(hx, hy);
    *(__nv_bfloat162*)(g_xh + o + 2) = __nv_bfloat162(hz, hw);
    *(__nv_bfloat162*)(g_xl + o)     = __nv_bfloat162(lx, ly);
    *(__nv_bfloat162*)(g_xl + o + 2) = __nv_bfloat162(lz, lw);
}

__global__ void prep_w(const float* __restrict__ wqkv, const float* __restrict__ wout) {
    const int id = blockIdx.x * 256 + threadIdx.x;  // float4 index
    float4 v;
    __nv_bfloat16* oh; __nv_bfloat16* ol; int o;
    if (id < 110592) {                        // 384*1152/4
        v = ((const float4*)wqkv)[id];
        oh = g_wqh; ol = g_wql; o = id * 4;
    } else {
        int id2 = id - 110592;                // < 36864
        v = ((const float4*)wout)[id2];
        oh = g_woh; ol = g_wol; o = id2 * 4;
    }
    __nv_bfloat16 hx, hy, hz, hw, lx, ly, lz, lw;
    split2(v.x, hx, lx); split2(v.y, hy, ly);
    split2(v.z, hz, lz); split2(v.w, hw, lw);
    *(__nv_bfloat162*)(oh + o)     = __nv_bfloat162(hx, hy);
    *(__nv_bfloat162*)(oh + o + 2) = __nv_bfloat162(hz, hw);
    *(__nv_bfloat162*)(ol + o)     = __nv_bfloat162(lx, ly);
    *(__nv_bfloat162*)(ol + o + 2) = __nv_bfloat162(lz, lw);
}

// ---------------------------------------------------------------------------
// Shared GEMM pieces: 128x128 tile, BK=32, 256 thr, 8 warps (4m x 2n, 32x64)
// ---------------------------------------------------------------------------
__device__ __forceinline__ void load_stage(
    const __nv_bfloat16* __restrict__ Agh, const __nv_bfloat16* __restrict__ Agl,
    const __nv_bfloat16* __restrict__ Bgh, const __nv_bfloat16* __restrict__ Bgl,
    __nv_bfloat16* Ah, __nv_bfloat16* Al, __nv_bfloat16* Bh, __nv_bfloat16* Bl,
    int m0, int n0, int ldb, int k0, int st, int tid)
{
    __nv_bfloat16* ash = Ah + st * A_STAGE;
    __nv_bfloat16* asl = Al + st * A_STAGE;
    __nv_bfloat16* bsh = Bh + st * B_STAGE;
    __nv_bfloat16* bsl = Bl + st * B_STAGE;
#pragma unroll
    for (int q = 0; q < 2; q++) {
        int c = tid * 2 + q;
        int row = c >> 2, ch = (c & 3) * 8;                 // A: 128 x 32
        int go = (m0 + row) * 384 + k0 + ch;
        int so = row * AST + ch;
        cpasync16(ash + so, Agh + go);
        cpasync16(asl + so, Agl + go);
    }
#pragma unroll
    for (int q = 0; q < 2; q++) {
        int c = tid * 2 + q;
        int row = c >> 4, ch = (c & 15) * 8;                // B: 32 x 128
        int go = (k0 + row) * ldb + n0 + ch;
        int so = row * BST + ch;
        cpasync16(bsh + so, Bgh + go);
        cpasync16(bsl + so, Bgl + go);
    }
}

__device__ __forceinline__ void compute_stage(
    const __nv_bfloat16* Ah, const __nv_bfloat16* Al,
    const __nv_bfloat16* Bh, const __nv_bfloat16* Bl,
    int wm, int wn, int lane, float acc[2][8][4])
{
#pragma unroll
    for (int ks = 0; ks < 2; ks++) {
        const int kk = ks * 16;
        uint32_t ah[2][4], al[2][4], bh[4][4], bl[4][4];
        const int arow = wm + (lane & 15);
        const int acol = kk + (lane >> 4) * 8;
#pragma unroll
        for (int mt = 0; mt < 2; mt++) {
            ldsmx4(ah[mt][0], ah[mt][1], ah[mt][2], ah[mt][3],
                   smem_u32(Ah + (arow + mt * 16) * AST + acol));
            ldsmx4(al[mt][0], al[mt][1], al[mt][2], al[mt][3],
                   smem_u32(Al + (arow + mt * 16) * AST + acol));
        }
        const int bk = kk + (lane & 15);
        const int bnb = wn + (lane >> 4) * 8;
#pragma unroll
        for (int g = 0; g < 4; g++) {
            ldsmx4t(bh[g][0], bh[g][1], bh[g][2], bh[g][3],
                    smem_u32(Bh + bk * BST + bnb + g * 16));
            ldsmx4t(bl[g][0], bl[g][1], bl[g][2], bl[g][3],
                    smem_u32(Bl + bk * BST + bnb + g * 16));
        }
#pragma unroll
        for (int mt = 0; mt < 2; mt++)
#pragma unroll
            for (int g = 0; g < 4; g++)
#pragma unroll
                for (int hf = 0; hf < 2; hf++) {
                    float* c = acc[mt][2 * g + hf];
                    mma_bf16(c, ah[mt], bh[g][2 * hf], bh[g][2 * hf + 1]);
                    mma_bf16(c, ah[mt], bl[g][2 * hf], bl[g][2 * hf + 1]);
                    mma_bf16(c, al[mt], bh[g][2 * hf], bh[g][2 * hf + 1]);
                }
    }
}

#define GEMM_MAINLOOP(AGH, AGL, BGH, BGL, LDB)                                   \
    extern __shared__ __align__(16) __nv_bfloat16 smem[];                        \
    __nv_bfloat16* Ah = smem;                                                    \
    __nv_bfloat16* Al = smem + 2 * A_STAGE;                                      \
    __nv_bfloat16* Bh = smem + 4 * A_STAGE;                                      \
    __nv_bfloat16* Bl = smem + 4 * A_STAGE + 2 * B_STAGE;                        \
    const int tid = threadIdx.x;                                                 \
    const int m0 = blockIdx.y * 128;                                             \
    const int n0 = blockIdx.x * 128;                                             \
    const int wid = tid >> 5, lane = tid & 31;                                   \
    const int wm = (wid >> 1) * 32;                                              \
    const int wn = (wid & 1) * 64;                                               \
    float acc[2][8][4];                                                          \
    _Pragma("unroll") for (int a_ = 0; a_ < 2; a_++)                             \
    _Pragma("unroll") for (int b_ = 0; b_ < 8; b_++)                             \
    _Pragma("unroll") for (int c_ = 0; c_ < 4; c_++) acc[a_][b_][c_] = 0.f;      \
    load_stage(AGH, AGL, BGH, BGL, Ah, Al, Bh, Bl, m0, n0, LDB, 0, 0, tid);      \
    asm volatile("cp.async.commit_group;" ::: "memory");                         \
    for (int it = 0; it < 12; it++) {                                            \
        if (it < 11) {                                                           \
            load_stage(AGH, AGL, BGH, BGL, Ah, Al, Bh, Bl, m0, n0, LDB,          \
                       (it + 1) * 32, (it + 1) & 1, tid);                        \
            asm volatile("cp.async.commit_group;" ::: "memory");                 \
            asm volatile("cp.async.wait_group 1;" ::: "memory");                 \
        } else {                                                                 \
            asm volatile("cp.async.wait_group 0;" ::: "memory");                 \
        }                                                                        \
        __syncthreads();                                                         \
        const int st = it & 1;                                                   \
        compute_stage(Ah + st * A_STAGE, Al + st * A_STAGE,                      \
                      Bh + st * B_STAGE, Bl + st * B_STAGE, wm, wn, lane, acc);  \
        __syncthreads();                                                         \
    }

// ---------------------------------------------------------------------------
// Kernel: QKV GEMM -> emit attention-ready bf16 hi/lo:
//   Q,V row-major per-head [.,144,32]; K transposed per-head [.,32,144].
// ---------------------------------------------------------------------------
__global__ __launch_bounds__(256, 1) void qkv_gemm_mma() {
    GEMM_MAINLOOP(g_xh, g_xl, g_wqh, g_wql, QKV_N)

    const int part = n0 / 384;
    const int cbase = n0 - part * 384;

#pragma unroll
    for (int mt = 0; mt < 2; mt++) {
#pragma unroll
        for (int rr = 0; rr < 2; rr++) {
            int r = m0 + wm + mt * 16 + (lane >> 2) + rr * 8;
            int b = r / 9216; int rem = r - b * 9216;
            int w = rem / 144; int i = rem - w * 144;
            int bw12 = (b * 64 + w) * 12;
#pragma unroll
            for (int nt = 0; nt < 8; nt++) {
                int c = cbase + wn + nt * 8 + (lane & 3) * 2;
                int h = c >> 5, d = c & 31;
                float f0 = acc[mt][nt][rr * 2], f1 = acc[mt][nt][rr * 2 + 1];
                __nv_bfloat16 h0, l0, h1, l1;
                split2(f0, h0, l0); split2(f1, h1, l1);
                if (part == 1) {              // K: transposed [32][144]
                    int tk = (bw12 + h) * 4608 + d * 144 + i;
                    g_kth[tk] = h0; g_kth[tk + 144] = h1;
                    g_ktl[tk] = l0; g_ktl[tk + 144] = l1;
                } else {                      // Q / V: row-major [144][32]
                    int tq = ((bw12 + h) * 144 + i) * 32 + d;
                    __nv_bfloat16* oh = (part == 0) ? g_qh : g_vh;
                    __nv_bfloat16* ol = (part == 0) ? g_ql : g_vl;
                    *(uint32_t*)(oh + tq) = packbf2(h0, h1);
                    *(uint32_t*)(ol + tq) = packbf2(l0, l1);
                }
            }
        }
    }
}

// ---------------------------------------------------------------------------
// Kernel: flash-chunked tensor-core attention. Block = (b, window, head),
// 9 warps x 16 query rows. j processed in 9 chunks of 16: S-chunk mma ->
// softmax (max-free) -> P@V chunk mma. Low regs -> 2 CTAs/SM.
// ---------------------------------------------------------------------------
#define KTST 152    // K^T smem stride (bf16): 304 B = 19*16 -> conflict-free
#define VST  40     // V smem stride (bf16):   80 B = 5*16  -> conflict-free

__global__ __launch_bounds__(288, 2) void attn_mma(const int* __restrict__ pixmap,
                                                   const float* __restrict__ posemb,
                                                   const float* __restrict__ pixemb) {
    __shared__ __align__(16) __nv_bfloat16 KTh[32 * KTST], KTl[32 * KTST];
    __shared__ __align__(16) __nv_bfloat16 Vsh[144 * VST], Vsl[144 * VST];
    __shared__ float pose[529];
    __shared__ float pmv[WSQ];
    __shared__ int   jinfo[WSQ];     // poff | jh<<16 | jxh<<17
    __shared__ float pes2[2];

    const int tid = threadIdx.x;
    const int b = blockIdx.y;
    const int w = blockIdx.x / 12;
    const int h = blockIdx.x - w * 12;
    const int tb2 = ((b * 64 + w) * 12 + h) * 4608;

    // K^T tiles: 32 rows x 144 bf16 = 18 chunks/row
#pragma unroll
    for (int q = 0; q < 2; q++) {
        int cix = tid + q * 288;                  // < 576
        int d = cix / 18, ch = (cix - d * 18) * 8;
        cpasync16(KTh + d * KTST + ch, g_kth + tb2 + d * 144 + ch);
        cpasync16(KTl + d * KTST + ch, g_ktl + tb2 + d * 144 + ch);
    }
    // V tiles: 144 rows x 32 bf16 = 4 chunks/row
#pragma unroll
    for (int q = 0; q < 2; q++) {
        int cix = tid + q * 288;                  // < 576
        int j = cix >> 2, ch = (cix & 3) * 8;
        cpasync16(Vsh + j * VST + ch, g_vh + tb2 + j * 32 + ch);
        cpasync16(Vsl + j * VST + ch, g_vl + tb2 + j * 32 + ch);
    }
    asm volatile("cp.async.commit_group;" ::: "memory");

    for (int f = tid; f < 529; f += 288) pose[f] = posemb[f];
    if (tid < 144) {
        int wy = w >> 3, wx = w & 7;
        int iy = tid / 12, ix = tid - iy * 12;
        pmv[tid] = (float)pixmap[(b * 96 + wy * 12 + iy) * 96 + wx * 12 + ix];
        jinfo[tid] = (iy * 23 + ix) | ((tid >= 72) << 16) | ((ix >= 6) << 17);
    }
    if (tid < 2) pes2[tid] = pixemb[tid];

    const int wr = tid >> 5;        // warp 0..8 -> query rows wr*16..+15
    const int lane = tid & 31;
    const int g = lane >> 2, t = lane & 3;
    const int i0 = wr * 16 + g, i1 = i0 + 8;

    // Q fragments: packed bf16x2 direct from gmem (pre-split)
    uint32_t qh[2][4], ql[2][4];
#pragma unroll
    for (int kc = 0; kc < 2; kc++) {
        int o0 = tb2 + i0 * 32 + kc * 16 + 2 * t;
        int o1 = tb2 + i1 * 32 + kc * 16 + 2 * t;
        qh[kc][0] = *(const uint32_t*)(g_qh + o0);
        ql[kc][0] = *(const uint32_t*)(g_ql + o0);
        qh[kc][1] = *(const uint32_t*)(g_qh + o1);
        ql[kc][1] = *(const uint32_t*)(g_ql + o1);
        qh[kc][2] = *(const uint32_t*)(g_qh + o0 + 8);
        ql[kc][2] = *(const uint32_t*)(g_ql + o0 + 8);
        qh[kc][3] = *(const uint32_t*)(g_qh + o1 + 8);
        ql[kc][3] = *(const uint32_t*)(g_ql + o1 + 8);
    }

    asm volatile("cp.async.wait_group 0;" ::: "memory");
    __syncthreads();

    // per-row constants
    const bool ul = (w >> 3) == 7;
    const bool lr = (w & 7) == 7;
    const float pmi0 = pmv[i0], pmi1 = pmv[i1];
    const int iy0 = i0 / 12, ix0 = i0 - iy0 * 12;
    const int iy1 = i1 / 12, ix1 = i1 - iy1 * 12;
    const float* pr0 = pose + (11 - iy0) * 23 + (11 - ix0);
    const float* pr1 = pose + (11 - iy1) * 23 + (11 - ix1);
    const bool ih0 = i0 >= 72, ih1 = i1 >= 72;
    const bool ixh0 = ix0 >= 6, ixh1 = ix1 >= 6;
    const float pe0 = pes2[0], pe1 = pes2[1];
    const float scale = 0.17677669529663689f;

    float oacc[4][4];
#pragma unroll
    for (int nt = 0; nt < 4; nt++)
#pragma unroll
        for (int c = 0; c < 4; c++) oacc[nt][c] = 0.f;
    float rs0 = 0.f, rs1 = 0.f;

#pragma unroll
    for (int jc = 0; jc < 9; jc++) {
        // ---- S chunk: rows i0/i1, cols jc*16 .. +15
        float sc[2][4];
#pragma unroll
        for (int u = 0; u < 2; u++)
#pragma unroll
            for (int c = 0; c < 4; c++) sc[u][c] = 0.f;
#pragma unroll
        for (int kc = 0; kc < 2; kc++) {
            uint32_t bh[4], bl[4];
            uint32_t ah_ = smem_u32(KTh + (kc * 16 + (lane & 15)) * KTST +
                                    jc * 16 + (lane >> 4) * 8);
            uint32_t al_ = smem_u32(KTl + (kc * 16 + (lane & 15)) * KTST +
                                    jc * 16 + (lane >> 4) * 8);
            ldsmx4t(bh[0], bh[1], bh[2], bh[3], ah_);
            ldsmx4t(bl[0], bl[1], bl[2], bl[3], al_);
            mma_bf16(sc[0], qh[kc], bh[0], bh[1]);
            mma_bf16(sc[0], qh[kc], bl[0], bl[1]);
            mma_bf16(sc[0], ql[kc], bh[0], bh[1]);
            mma_bf16(sc[1], qh[kc], bh[2], bh[3]);
            mma_bf16(sc[1], qh[kc], bl[2], bl[3]);
            mma_bf16(sc[1], ql[kc], bh[2], bh[3]);
        }

        // ---- softmax chunk (max-free; masked -> 0)
#pragma unroll
        for (int u = 0; u < 2; u++) {
#pragma unroll
            for (int fc = 0; fc < 2; fc++) {
                int j = jc * 16 + u * 8 + 2 * t + fc;
                int ji = jinfo[j];
                float pj = pmv[j];
                int poff = ji & 0xffff;
                bool jh = ji & 0x10000, jxh = ji & 0x20000;
                {
                    float s = sc[u][fc] * scale;
                    s += (pmi0 * pj != 0.f) ? pe1 : pe0;
                    s += pr0[poff];
                    bool m = (ul && (ih0 != jh)) || (lr && (ixh0 != jxh));
                    float p = m ? 0.f : __expf(s);
                    sc[u][fc] = p; rs0 += p;
                }
                {
                    float s = sc[u][fc + 2] * scale;
                    s += (pmi1 * pj != 0.f) ? pe1 : pe0;
                    s += pr1[poff];
                    bool m = (ul && (ih1 != jh)) || (lr && (ixh1 != jxh));
                    float p = m ? 0.f : __expf(s);
                    sc[u][fc + 2] = p; rs1 += p;
                }
            }
        }

        // ---- P chunk -> A fragments, accumulate P@V
        uint32_t ph[4], pl[4];
        {
            __nv_bfloat16 ha, la, hb, lb;
            split2(sc[0][0], ha, la); split2(sc[0][1], hb, lb);
            ph[0] = packbf2(ha, hb); pl[0] = packbf2(la, lb);
            split2(sc[0][2], ha, la); split2(sc[0][3], hb, lb);
            ph[1] = packbf2(ha, hb); pl[1] = packbf2(la, lb);
            split2(sc[1][0], ha, la); split2(sc[1][1], hb, lb);
            ph[2] = packbf2(ha, hb); pl[2] = packbf2(la, lb);
            split2(sc[1][2], ha, la); split2(sc[1][3], hb, lb);
            ph[3] = packbf2(ha, hb); pl[3] = packbf2(la, lb);
        }
#pragma unroll
        for (int ng = 0; ng < 2; ng++) {
            uint32_t bh[4], bl[4];
            uint32_t ah_ = smem_u32(Vsh + (jc * 16 + (lane & 15)) * VST +
                                    ng * 16 + (lane >> 4) * 8);
            uint32_t al_ = smem_u32(Vsl + (jc * 16 + (lane & 15)) * VST +
                                    ng * 16 + (lane >> 4) * 8);
            ldsmx4t(bh[0], bh[1], bh[2], bh[3], ah_);
            ldsmx4t(bl[0], bl[1], bl[2], bl[3], al_);
            mma_bf16(oacc[2 * ng],     ph, bh[0], bh[1]);
            mma_bf16(oacc[2 * ng],     ph, bl[0], bl[1]);
            mma_bf16(oacc[2 * ng],     pl, bh[0], bh[1]);
            mma_bf16(oacc[2 * ng + 1], ph, bh[2], bh[3]);
            mma_bf16(oacc[2 * ng + 1], ph, bl[2], bl[3]);
            mma_bf16(oacc[2 * ng + 1], pl, bh[2], bh[3]);
        }
    }

    rs0 += __shfl_xor_sync(0xffffffff, rs0, 1);
    rs0 += __shfl_xor_sync(0xffffffff, rs0, 2);
    rs1 += __shfl_xor_sync(0xffffffff, rs1, 1);
    rs1 += __shfl_xor_sync(0xffffffff, rs1, 2);
    const float inv0 = 1.f / rs0, inv1 = 1.f / rs1;

    // write normalized output as bf16 hi/lo: [B,NW,144,384] row i, cols h*32+..
    const int orow0 = ((b * 64 + w) * 144 + i0) * 384 + h * 32;
    const int orow1 = ((b * 64 + w) * 144 + i1) * 384 + h * 32;
#pragma unroll
    for (int nt = 0; nt < 4; nt++) {
        int col = nt * 8 + 2 * t;
        __nv_bfloat16 ha, la, hb, lb;
        float f0 = oacc[nt][0] * inv0, f1 = oacc[nt][1] * inv0;
        split2(f0, ha, la); split2(f1, hb, lb);
        *(uint32_t*)(g_atth + orow0 + col) = packbf2(ha, hb);
        *(uint32_t*)(g_attl + orow0 + col) = packbf2(la, lb);
        float f2 = oacc[nt][2] * inv1, f3 = oacc[nt][3] * inv1;
        split2(f2, ha, la); split2(f3, hb, lb);
        *(uint32_t*)(g_atth + orow1 + col) = packbf2(ha, hb);
        *(uint32_t*)(g_attl + orow1 + col) = packbf2(la, lb);
    }
}

// ---------------------------------------------------------------------------
// Kernel: output projection + bias + window-merge + roll(+6,+6) scatter
// ---------------------------------------------------------------------------
__global__ __launch_bounds__(256, 1) void out_gemm_mma(const float* __restrict__ bout,
                                                       float* __restrict__ Out) {
    GEMM_MAINLOOP(g_atth, g_attl, g_woh, g_wol, 384)

#pragma unroll
    for (int mt = 0; mt < 2; mt++) {
#pragma unroll
        for (int rr = 0; rr < 2; rr++) {
            int r = m0 + wm + mt * 16 + (lane >> 2) + rr * 8;
            int b = r / 9216; int rem = r - b * 9216;
            int w = rem / 144; int i = rem - w * 144;
            int iy = i / 12, ix = i - iy * 12;
            int y = (w >> 3) * 12 + iy + 6; if (y >= 96) y -= 96;
            int x = (w & 7) * 12 + ix + 6;  if (x >= 96) x -= 96;
            float* orow = Out + ((b * 96 + y) * 96 + x) * 384;
#pragma unroll
            for (int nt = 0; nt < 8; nt++) {
                int c = n0 + wn + nt * 8 + (lane & 3) * 2;
                float2 bi = *(const float2*)(bout + c);
                float2 v = make_float2(acc[mt][nt][rr * 2] + bi.x,
                                       acc[mt][nt][rr * 2 + 1] + bi.y);
                *(float2*)(orow + c) = v;
            }
        }
    }
}

// ---------------------------------------------------------------------------
extern "C" void kernel_launch(void* const* d_in, const int* in_sizes, int n_in,
                              void* d_out, int out_size) {
    (void)in_sizes; (void)n_in; (void)out_size;
    const float* x      = (const float*)d_in[0];
    const int*   pixmap = (const int*)d_in[1];
    const float* wqkv   = (const float*)d_in[2];
    const float* posemb = (const float*)d_in[3];
    const float* pixemb = (const float*)d_in[4];
    const float* wout   = (const float*)d_in[5];
    const float* bout   = (const float*)d_in[6];
    float* out = (float*)d_out;

    cudaFuncSetAttribute(qkv_gemm_mma, cudaFuncAttributeMaxDynamicSharedMemorySize,
                         SMEM_BYTES);
    cudaFuncSetAttribute(out_gemm_mma, cudaFuncAttributeMaxDynamicSharedMemorySize,
                         SMEM_BYTES);

    prep_x<<<MROWS, 96>>>(x);
    prep_w<<<576, 256>>>(wqkv, wout);
    qkv_gemm_mma<<<dim3(QKV_N / 128, MROWS / 128), 256, SMEM_BYTES>>>();
    attn_mma<<<dim3(NW * NHEADS, BB), 288>>>(pixmap, posemb, pixemb);
    out_gemm_mma<<<dim3(384 / 128, MROWS / 128), 256, SMEM_BYTES>>>(bout, out);
}

// round 7
// speedup vs baseline: 2.0213x; 1.0250x over previous
#include <cuda_runtime.h>
#include <cuda_bf16.h>
#include <cstdint>

// Shapes
#define BB     8
#define NHEADS 12
#define HD     32
#define NW     64
#define WSQ    144
#define MROWS  73728        // BB*NW*WSQ
#define QKV_N  1152

// Scratch (allocation-free rule: __device__ globals)
__device__ __nv_bfloat16 g_qh[MROWS * 384];   // per-head [B,NW,H,144,32]
__device__ __nv_bfloat16 g_ql[MROWS * 384];
__device__ __nv_bfloat16 g_kth[MROWS * 384];  // per-head transposed [B,NW,H,32,144]
__device__ __nv_bfloat16 g_ktl[MROWS * 384];
__device__ __nv_bfloat16 g_vh[MROWS * 384];   // per-head [B,NW,H,144,32]
__device__ __nv_bfloat16 g_vl[MROWS * 384];
__device__ __nv_bfloat16 g_xh[MROWS * 384];
__device__ __nv_bfloat16 g_xl[MROWS * 384];
__device__ __nv_bfloat16 g_atth[MROWS * 384];
__device__ __nv_bfloat16 g_attl[MROWS * 384];
__device__ __nv_bfloat16 g_wqh[384 * QKV_N];
__device__ __nv_bfloat16 g_wql[384 * QKV_N];
__device__ __nv_bfloat16 g_woh[384 * 384];
__device__ __nv_bfloat16 g_wol[384 * 384];

// ---------------------------------------------------------------------------
// helpers
// ---------------------------------------------------------------------------
__device__ __forceinline__ uint32_t smem_u32(const void* p) {
    return (uint32_t)__cvta_generic_to_shared(p);
}
__device__ __forceinline__ void ldsmx4(uint32_t& r0, uint32_t& r1, uint32_t& r2,
                                       uint32_t& r3, uint32_t a) {
    asm volatile("ldmatrix.sync.aligned.m8n8.x4.shared.b16 {%0,%1,%2,%3}, [%4];"
                 : "=r"(r0), "=r"(r1), "=r"(r2), "=r"(r3) : "r"(a));
}
__device__ __forceinline__ void ldsmx4t(uint32_t& r0, uint32_t& r1, uint32_t& r2,
                                        uint32_t& r3, uint32_t a) {
    asm volatile("ldmatrix.sync.aligned.m8n8.x4.trans.shared.b16 {%0,%1,%2,%3}, [%4];"
                 : "=r"(r0), "=r"(r1), "=r"(r2), "=r"(r3) : "r"(a));
}
__device__ __forceinline__ void mma_bf16(float* c, const uint32_t* a,
                                         uint32_t b0, uint32_t b1) {
    asm volatile(
        "mma.sync.aligned.m16n8k16.row.col.f32.bf16.bf16.f32 "
        "{%0,%1,%2,%3},{%4,%5,%6,%7},{%8,%9},{%0,%1,%2,%3};"
        : "+f"(c[0]), "+f"(c[1]), "+f"(c[2]), "+f"(c[3])
        : "r"(a[0]), "r"(a[1]), "r"(a[2]), "r"(a[3]), "r"(b0), "r"(b1));
}
__device__ __forceinline__ void split2(float f, __nv_bfloat16& h, __nv_bfloat16& l) {
    h = __float2bfloat16_rn(f);
    l = __float2bfloat16_rn(f - __bfloat162float(h));
}
__device__ __forceinline__ uint32_t packbf2(__nv_bfloat16 a, __nv_bfloat16 b) {
    __nv_bfloat162 v(a, b);
    return *(uint32_t*)&v;
}
__device__ __forceinline__ void cpasync16(void* s, const void* g) {
    asm volatile("cp.async.cg.shared.global [%0], [%1], 16;"
                 :: "r"(smem_u32(s)), "l"(g));
}

#define AST  40      // A smem row stride (bf16): 80 B = 5*16 -> conflict-free
#define BST  136     // B smem row stride (bf16): 272 B = 17*16 -> conflict-free
#define A_STAGE 5120 // 128*AST
#define B_STAGE 4352 // 32*BST
#define NST  4       // pipeline stages
#define SMEM_BYTES ((2 * NST * A_STAGE + 2 * NST * B_STAGE) * 2)   // 151552

// ---------------------------------------------------------------------------
// Prep kernels: roll-gather + fp32 -> bf16 hi/lo split
// ---------------------------------------------------------------------------
__global__ __launch_bounds__(256) void prep_x(const float* __restrict__ X) {
    const int id = blockIdx.x * 256 + threadIdx.x;   // float4 id, < 7077888
    const int r = id / 96, t = id - r * 96;
    int b = r / 9216; int rem = r - b * 9216;
    int w = rem / 144; int i = rem - w * 144;
    int y = (w >> 3) * 12 + i / 12 + 6; if (y >= 96) y -= 96;
    int x = (w & 7) * 12 + i % 12 + 6;  if (x >= 96) x -= 96;
    float4 v = *((const float4*)(X + ((b * 96 + y) * 96 + x) * 384) + t);
    __nv_bfloat16 hx, hy, hz, hw, lx, ly, lz, lw;
    split2(v.x, hx, lx); split2(v.y, hy, ly);
    split2(v.z, hz, lz); split2(v.w, hw, lw);
    int o = r * 384 + t * 4;
    *(__nv_bfloat162*)(g_xh + o)     = __nv_bfloat162(hx, hy);
    *(__nv_bfloat162*)(g_xh + o + 2) = __nv_bfloat162(hz, hw);
    *(__nv_bfloat162*)(g_xl + o)     = __nv_bfloat162(lx, ly);
    *(__nv_bfloat162*)(g_xl + o + 2) = __nv_bfloat162(lz, lw);
}

__global__ void prep_w(const float* __restrict__ wqkv, const float* __restrict__ wout) {
    const int id = blockIdx.x * 256 + threadIdx.x;  // float4 index
    float4 v;
    __nv_bfloat16* oh; __nv_bfloat16* ol; int o;
    if (id < 110592) {                        // 384*1152/4
        v = ((const float4*)wqkv)[id];
        oh = g_wqh; ol = g_wql; o = id * 4;
    } else {
        int id2 = id - 110592;                // < 36864
        v = ((const float4*)wout)[id2];
        oh = g_woh; ol = g_wol; o = id2 * 4;
    }
    __nv_bfloat16 hx, hy, hz, hw, lx, ly, lz, lw;
    split2(v.x, hx, lx); split2(v.y, hy, ly);
    split2(v.z, hz, lz); split2(v.w, hw, lw);
    *(__nv_bfloat162*)(oh + o)     = __nv_bfloat162(hx, hy);
    *(__nv_bfloat162*)(oh + o + 2) = __nv_bfloat162(hz, hw);
    *(__nv_bfloat162*)(ol + o)     = __nv_bfloat162(lx, ly);
    *(__nv_bfloat162*)(ol + o + 2) = __nv_bfloat162(lz, lw);
}

// ---------------------------------------------------------------------------
// Shared GEMM pieces: 128x128 tile, BK=32, 256 thr, 8 warps (4m x 2n, 32x64)
// 4-stage cp.async pipeline, one __syncthreads per K-iteration.
// ---------------------------------------------------------------------------
__device__ __forceinline__ void load_stage(
    const __nv_bfloat16* __restrict__ Agh, const __nv_bfloat16* __restrict__ Agl,
    const __nv_bfloat16* __restrict__ Bgh, const __nv_bfloat16* __restrict__ Bgl,
    __nv_bfloat16* Ah, __nv_bfloat16* Al, __nv_bfloat16* Bh, __nv_bfloat16* Bl,
    int m0, int n0, int ldb, int k0, int st, int tid)
{
    __nv_bfloat16* ash = Ah + st * A_STAGE;
    __nv_bfloat16* asl = Al + st * A_STAGE;
    __nv_bfloat16* bsh = Bh + st * B_STAGE;
    __nv_bfloat16* bsl = Bl + st * B_STAGE;
#pragma unroll
    for (int q = 0; q < 2; q++) {
        int c = tid * 2 + q;
        int row = c >> 2, ch = (c & 3) * 8;                 // A: 128 x 32
        int go = (m0 + row) * 384 + k0 + ch;
        int so = row * AST + ch;
        cpasync16(ash + so, Agh + go);
        cpasync16(asl + so, Agl + go);
    }
#pragma unroll
    for (int q = 0; q < 2; q++) {
        int c = tid * 2 + q;
        int row = c >> 4, ch = (c & 15) * 8;                // B: 32 x 128
        int go = (k0 + row) * ldb + n0 + ch;
        int so = row * BST + ch;
        cpasync16(bsh + so, Bgh + go);
        cpasync16(bsl + so, Bgl + go);
    }
}

__device__ __forceinline__ void compute_stage(
    const __nv_bfloat16* Ah, const __nv_bfloat16* Al,
    const __nv_bfloat16* Bh, const __nv_bfloat16* Bl,
    int wm, int wn, int lane, float acc[2][8][4])
{
#pragma unroll
    for (int ks = 0; ks < 2; ks++) {
        const int kk = ks * 16;
        uint32_t ah[2][4], al[2][4], bh[4][4], bl[4][4];
        const int arow = wm + (lane & 15);
        const int acol = kk + (lane >> 4) * 8;
#pragma unroll
        for (int mt = 0; mt < 2; mt++) {
            ldsmx4(ah[mt][0], ah[mt][1], ah[mt][2], ah[mt][3],
                   smem_u32(Ah + (arow + mt * 16) * AST + acol));
            ldsmx4(al[mt][0], al[mt][1], al[mt][2], al[mt][3],
                   smem_u32(Al + (arow + mt * 16) * AST + acol));
        }
        const int bk = kk + (lane & 15);
        const int bnb = wn + (lane >> 4) * 8;
#pragma unroll
        for (int g = 0; g < 4; g++) {
            ldsmx4t(bh[g][0], bh[g][1], bh[g][2], bh[g][3],
                    smem_u32(Bh + bk * BST + bnb + g * 16));
            ldsmx4t(bl[g][0], bl[g][1], bl[g][2], bl[g][3],
                    smem_u32(Bl + bk * BST + bnb + g * 16));
        }
#pragma unroll
        for (int mt = 0; mt < 2; mt++)
#pragma unroll
            for (int g = 0; g < 4; g++)
#pragma unroll
                for (int hf = 0; hf < 2; hf++) {
                    float* c = acc[mt][2 * g + hf];
                    mma_bf16(c, ah[mt], bh[g][2 * hf], bh[g][2 * hf + 1]);
                    mma_bf16(c, ah[mt], bl[g][2 * hf], bl[g][2 * hf + 1]);
                    mma_bf16(c, al[mt], bh[g][2 * hf], bh[g][2 * hf + 1]);
                }
    }
}

#define GEMM_MAINLOOP(AGH, AGL, BGH, BGL, LDB)                                   \
    extern __shared__ __align__(16) __nv_bfloat16 smem[];                        \
    __nv_bfloat16* Ah = smem;                                                    \
    __nv_bfloat16* Al = smem + NST * A_STAGE;                                    \
    __nv_bfloat16* Bh = smem + 2 * NST * A_STAGE;                                \
    __nv_bfloat16* Bl = smem + 2 * NST * A_STAGE + NST * B_STAGE;                \
    const int tid = threadIdx.x;                                                 \
    const int m0 = blockIdx.y * 128;                                             \
    const int n0 = blockIdx.x * 128;                                             \
    const int wid = tid >> 5, lane = tid & 31;                                   \
    const int wm = (wid >> 1) * 32;                                              \
    const int wn = (wid & 1) * 64;                                               \
    float acc[2][8][4];                                                          \
    _Pragma("unroll") for (int a_ = 0; a_ < 2; a_++)                             \
    _Pragma("unroll") for (int b_ = 0; b_ < 8; b_++)                             \
    _Pragma("unroll") for (int c_ = 0; c_ < 4; c_++) acc[a_][b_][c_] = 0.f;      \
    _Pragma("unroll") for (int s_ = 0; s_ < NST - 1; s_++) {                     \
        load_stage(AGH, AGL, BGH, BGL, Ah, Al, Bh, Bl, m0, n0, LDB,              \
                   s_ * 32, s_, tid);                                            \
        asm volatile("cp.async.commit_group;" ::: "memory");                     \
    }                                                                            \
    for (int it = 0; it < 12; it++) {                                            \
        asm volatile("cp.async.wait_group %0;" :: "n"(NST - 2) : "memory");      \
        __syncthreads();                                                         \
        if (it < 12 - (NST - 1)) {                                               \
            load_stage(AGH, AGL, BGH, BGL, Ah, Al, Bh, Bl, m0, n0, LDB,          \
                       (it + NST - 1) * 32, (it + NST - 1) & (NST - 1), tid);    \
        }                                                                        \
        asm volatile("cp.async.commit_group;" ::: "memory");                     \
        const int st = it & (NST - 1);                                           \
        compute_stage(Ah + st * A_STAGE, Al + st * A_STAGE,                      \
                      Bh + st * B_STAGE, Bl + st * B_STAGE, wm, wn, lane, acc);  \
    }

// ---------------------------------------------------------------------------
// Kernel: QKV GEMM -> emit attention-ready bf16 hi/lo:
//   Q,V row-major per-head [.,144,32]; K transposed per-head [.,32,144].
// ---------------------------------------------------------------------------
__global__ __launch_bounds__(256, 1) void qkv_gemm_mma() {
    GEMM_MAINLOOP(g_xh, g_xl, g_wqh, g_wql, QKV_N)

    const int part = n0 / 384;
    const int cbase = n0 - part * 384;

#pragma unroll
    for (int mt = 0; mt < 2; mt++) {
#pragma unroll
        for (int rr = 0; rr < 2; rr++) {
            int r = m0 + wm + mt * 16 + (lane >> 2) + rr * 8;
            int b = r / 9216; int rem = r - b * 9216;
            int w = rem / 144; int i = rem - w * 144;
            int bw12 = (b * 64 + w) * 12;
#pragma unroll
            for (int nt = 0; nt < 8; nt++) {
                int c = cbase + wn + nt * 8 + (lane & 3) * 2;
                int h = c >> 5, d = c & 31;
                float f0 = acc[mt][nt][rr * 2], f1 = acc[mt][nt][rr * 2 + 1];
                __nv_bfloat16 h0, l0, h1, l1;
                split2(f0, h0, l0); split2(f1, h1, l1);
                if (part == 1) {              // K: transposed [32][144]
                    int tk = (bw12 + h) * 4608 + d * 144 + i;
                    g_kth[tk] = h0; g_kth[tk + 144] = h1;
                    g_ktl[tk] = l0; g_ktl[tk + 144] = l1;
                } else {                      // Q / V: row-major [144][32]
                    int tq = ((bw12 + h) * 144 + i) * 32 + d;
                    __nv_bfloat16* oh = (part == 0) ? g_qh : g_vh;
                    __nv_bfloat16* ol = (part == 0) ? g_ql : g_vl;
                    *(uint32_t*)(oh + tq) = packbf2(h0, h1);
                    *(uint32_t*)(ol + tq) = packbf2(l0, l1);
                }
            }
        }
    }
}

// ---------------------------------------------------------------------------
// Kernel: flash-chunked tensor-core attention. Block = (b, window, head),
// 9 warps x 16 query rows. j processed in 9 chunks of 16: S-chunk mma ->
// softmax (max-free) -> P@V chunk mma. Low regs -> 2 CTAs/SM.
// ---------------------------------------------------------------------------
#define KTST 152    // K^T smem stride (bf16): 304 B = 19*16 -> conflict-free
#define VST  40     // V smem stride (bf16):   80 B = 5*16  -> conflict-free

__global__ __launch_bounds__(288, 2) void attn_mma(const int* __restrict__ pixmap,
                                                   const float* __restrict__ posemb,
                                                   const float* __restrict__ pixemb) {
    __shared__ __align__(16) __nv_bfloat16 KTh[32 * KTST], KTl[32 * KTST];
    __shared__ __align__(16) __nv_bfloat16 Vsh[144 * VST], Vsl[144 * VST];
    __shared__ float pose[529];
    __shared__ float pmv[WSQ];
    __shared__ int   jinfo[WSQ];     // poff | jh<<16 | jxh<<17
    __shared__ float pes2[2];

    const int tid = threadIdx.x;
    const int b = blockIdx.y;
    const int w = blockIdx.x / 12;
    const int h = blockIdx.x - w * 12;
    const int tb2 = ((b * 64 + w) * 12 + h) * 4608;

    // K^T tiles: 32 rows x 144 bf16 = 18 chunks/row
#pragma unroll
    for (int q = 0; q < 2; q++) {
        int cix = tid + q * 288;                  // < 576
        int d = cix / 18, ch = (cix - d * 18) * 8;
        cpasync16(KTh + d * KTST + ch, g_kth + tb2 + d * 144 + ch);
        cpasync16(KTl + d * KTST + ch, g_ktl + tb2 + d * 144 + ch);
    }
    // V tiles: 144 rows x 32 bf16 = 4 chunks/row
#pragma unroll
    for (int q = 0; q < 2; q++) {
        int cix = tid + q * 288;                  // < 576
        int j = cix >> 2, ch = (cix & 3) * 8;
        cpasync16(Vsh + j * VST + ch, g_vh + tb2 + j * 32 + ch);
        cpasync16(Vsl + j * VST + ch, g_vl + tb2 + j * 32 + ch);
    }
    asm volatile("cp.async.commit_group;" ::: "memory");

    for (int f = tid; f < 529; f += 288) pose[f] = posemb[f];
    if (tid < 144) {
        int wy = w >> 3, wx = w & 7;
        int iy = tid / 12, ix = tid - iy * 12;
        pmv[tid] = (float)pixmap[(b * 96 + wy * 12 + iy) * 96 + wx * 12 + ix];
        jinfo[tid] = (iy * 23 + ix) | ((tid >= 72) << 16) | ((ix >= 6) << 17);
    }
    if (tid < 2) pes2[tid] = pixemb[tid];

    const int wr = tid >> 5;        // warp 0..8 -> query rows wr*16..+15
    const int lane = tid & 31;
    const int g = lane >> 2, t = lane & 3;
    const int i0 = wr * 16 + g, i1 = i0 + 8;

    // Q fragments: packed bf16x2 direct from gmem (pre-split)
    uint32_t qh[2][4], ql[2][4];
#pragma unroll
    for (int kc = 0; kc < 2; kc++) {
        int o0 = tb2 + i0 * 32 + kc * 16 + 2 * t;
        int o1 = tb2 + i1 * 32 + kc * 16 + 2 * t;
        qh[kc][0] = *(const uint32_t*)(g_qh + o0);
        ql[kc][0] = *(const uint32_t*)(g_ql + o0);
        qh[kc][1] = *(const uint32_t*)(g_qh + o1);
        ql[kc][1] = *(const uint32_t*)(g_ql + o1);
        qh[kc][2] = *(const uint32_t*)(g_qh + o0 + 8);
        ql[kc][2] = *(const uint32_t*)(g_ql + o0 + 8);
        qh[kc][3] = *(const uint32_t*)(g_qh + o1 + 8);
        ql[kc][3] = *(const uint32_t*)(g_ql + o1 + 8);
    }

    asm volatile("cp.async.wait_group 0;" ::: "memory");
    __syncthreads();

    // per-row constants
    const bool ul = (w >> 3) == 7;
    const bool lr = (w & 7) == 7;
    const float pmi0 = pmv[i0], pmi1 = pmv[i1];
    const int iy0 = i0 / 12, ix0 = i0 - iy0 * 12;
    const int iy1 = i1 / 12, ix1 = i1 - iy1 * 12;
    const float* pr0 = pose + (11 - iy0) * 23 + (11 - ix0);
    const float* pr1 = pose + (11 - iy1) * 23 + (11 - ix1);
    const bool ih0 = i0 >= 72, ih1 = i1 >= 72;
    const bool ixh0 = ix0 >= 6, ixh1 = ix1 >= 6;
    const float pe0 = pes2[0], pe1 = pes2[1];
    const float scale = 0.17677669529663689f;

    float oacc[4][4];
#pragma unroll
    for (int nt = 0; nt < 4; nt++)
#pragma unroll
        for (int c = 0; c < 4; c++) oacc[nt][c] = 0.f;
    float rs0 = 0.f, rs1 = 0.f;

#pragma unroll
    for (int jc = 0; jc < 9; jc++) {
        // ---- S chunk: rows i0/i1, cols jc*16 .. +15
        float sc[2][4];
#pragma unroll
        for (int u = 0; u < 2; u++)
#pragma unroll
            for (int c = 0; c < 4; c++) sc[u][c] = 0.f;
#pragma unroll
        for (int kc = 0; kc < 2; kc++) {
            uint32_t bh[4], bl[4];
            uint32_t ah_ = smem_u32(KTh + (kc * 16 + (lane & 15)) * KTST +
                                    jc * 16 + (lane >> 4) * 8);
            uint32_t al_ = smem_u32(KTl + (kc * 16 + (lane & 15)) * KTST +
                                    jc * 16 + (lane >> 4) * 8);
            ldsmx4t(bh[0], bh[1], bh[2], bh[3], ah_);
            ldsmx4t(bl[0], bl[1], bl[2], bl[3], al_);
            mma_bf16(sc[0], qh[kc], bh[0], bh[1]);
            mma_bf16(sc[0], qh[kc], bl[0], bl[1]);
            mma_bf16(sc[0], ql[kc], bh[0], bh[1]);
            mma_bf16(sc[1], qh[kc], bh[2], bh[3]);
            mma_bf16(sc[1], qh[kc], bl[2], bl[3]);
            mma_bf16(sc[1], ql[kc], bh[2], bh[3]);
        }

        // ---- softmax chunk (max-free; masked -> 0)
#pragma unroll
        for (int u = 0; u < 2; u++) {
#pragma unroll
            for (int fc = 0; fc < 2; fc++) {
                int j = jc * 16 + u * 8 + 2 * t + fc;
                int ji = jinfo[j];
                float pj = pmv[j];
                int poff = ji & 0xffff;
                bool jh = ji & 0x10000, jxh = ji & 0x20000;
                {
                    float s = sc[u][fc] * scale;
                    s += (pmi0 * pj != 0.f) ? pe1 : pe0;
                    s += pr0[poff];
                    bool m = (ul && (ih0 != jh)) || (lr && (ixh0 != jxh));
                    float p = m ? 0.f : __expf(s);
                    sc[u][fc] = p; rs0 += p;
                }
                {
                    float s = sc[u][fc + 2] * scale;
                    s += (pmi1 * pj != 0.f) ? pe1 : pe0;
                    s += pr1[poff];
                    bool m = (ul && (ih1 != jh)) || (lr && (ixh1 != jxh));
                    float p = m ? 0.f : __expf(s);
                    sc[u][fc + 2] = p; rs1 += p;
                }
            }
        }

        // ---- P chunk -> A fragments, accumulate P@V
        uint32_t ph[4], pl[4];
        {
            __nv_bfloat16 ha, la, hb, lb;
            split2(sc[0][0], ha, la); split2(sc[0][1], hb, lb);
            ph[0] = packbf2(ha, hb); pl[0] = packbf2(la, lb);
            split2(sc[0][2], ha, la); split2(sc[0][3], hb, lb);
            ph[1] = packbf2(ha, hb); pl[1] = packbf2(la, lb);
            split2(sc[1][0], ha, la); split2(sc[1][1], hb, lb);
            ph[2] = packbf2(ha, hb); pl[2] = packbf2(la, lb);
            split2(sc[1][2], ha, la); split2(sc[1][3], hb, lb);
            ph[3] = packbf2(ha, hb); pl[3] = packbf2(la, lb);
        }
#pragma unroll
        for (int ng = 0; ng < 2; ng++) {
            uint32_t bh[4], bl[4];
            uint32_t ah_ = smem_u32(Vsh + (jc * 16 + (lane & 15)) * VST +
                                    ng * 16 + (lane >> 4) * 8);
            uint32_t al_ = smem_u32(Vsl + (jc * 16 + (lane & 15)) * VST +
                                    ng * 16 + (lane >> 4) * 8);
            ldsmx4t(bh[0], bh[1], bh[2], bh[3], ah_);
            ldsmx4t(bl[0], bl[1], bl[2], bl[3], al_);
            mma_bf16(oacc[2 * ng],     ph, bh[0], bh[1]);
            mma_bf16(oacc[2 * ng],     ph, bl[0], bl[1]);
            mma_bf16(oacc[2 * ng],     pl, bh[0], bh[1]);
            mma_bf16(oacc[2 * ng + 1], ph, bh[2], bh[3]);
            mma_bf16(oacc[2 * ng + 1], ph, bl[2], bl[3]);
            mma_bf16(oacc[2 * ng + 1], pl, bh[2], bh[3]);
        }
    }

    rs0 += __shfl_xor_sync(0xffffffff, rs0, 1);
    rs0 += __shfl_xor_sync(0xffffffff, rs0, 2);
    rs1 += __shfl_xor_sync(0xffffffff, rs1, 1);
    rs1 += __shfl_xor_sync(0xffffffff, rs1, 2);
    const float inv0 = 1.f / rs0, inv1 = 1.f / rs1;

    // write normalized output as bf16 hi/lo: [B,NW,144,384] row i, cols h*32+..
    const int orow0 = ((b * 64 + w) * 144 + i0) * 384 + h * 32;
    const int orow1 = ((b * 64 + w) * 144 + i1) * 384 + h * 32;
#pragma unroll
    for (int nt = 0; nt < 4; nt++) {
        int col = nt * 8 + 2 * t;
        __nv_bfloat16 ha, la, hb, lb;
        float f0 = oacc[nt][0] * inv0, f1 = oacc[nt][1] * inv0;
        split2(f0, ha, la); split2(f1, hb, lb);
        *(uint32_t*)(g_atth + orow0 + col) = packbf2(ha, hb);
        *(uint32_t*)(g_attl + orow0 + col) = packbf2(la, lb);
        float f2 = oacc[nt][2] * inv1, f3 = oacc[nt][3] * inv1;
        split2(f2, ha, la); split2(f3, hb, lb);
        *(uint32_t*)(g_atth + orow1 + col) = packbf2(ha, hb);
        *(uint32_t*)(g_attl + orow1 + col) = packbf2(la, lb);
    }
}

// ---------------------------------------------------------------------------
// Kernel: output projection + bias + window-merge + roll(+6,+6) scatter
// ---------------------------------------------------------------------------
__global__ __launch_bounds__(256, 1) void out_gemm_mma(const float* __restrict__ bout,
                                                       float* __restrict__ Out) {
    GEMM_MAINLOOP(g_atth, g_attl, g_woh, g_wol, 384)

#pragma unroll
    for (int mt = 0; mt < 2; mt++) {
#pragma unroll
        for (int rr = 0; rr < 2; rr++) {
            int r = m0 + wm + mt * 16 + (lane >> 2) + rr * 8;
            int b = r / 9216; int rem = r - b * 9216;
            int w = rem / 144; int i = rem - w * 144;
            int iy = i / 12, ix = i - iy * 12;
            int y = (w >> 3) * 12 + iy + 6; if (y >= 96) y -= 96;
            int x = (w & 7) * 12 + ix + 6;  if (x >= 96) x -= 96;
            float* orow = Out + ((b * 96 + y) * 96 + x) * 384;
#pragma unroll
            for (int nt = 0; nt < 8; nt++) {
                int c = n0 + wn + nt * 8 + (lane & 3) * 2;
                float2 bi = *(const float2*)(bout + c);
                float2 v = make_float2(acc[mt][nt][rr * 2] + bi.x,
                                       acc[mt][nt][rr * 2 + 1] + bi.y);
                *(float2*)(orow + c) = v;
            }
        }
    }
}

// ---------------------------------------------------------------------------
extern "C" void kernel_launch(void* const* d_in, const int* in_sizes, int n_in,
                              void* d_out, int out_size) {
    (void)in_sizes; (void)n_in; (void)out_size;
    const float* x      = (const float*)d_in[0];
    const int*   pixmap = (const int*)d_in[1];
    const float* wqkv   = (const float*)d_in[2];
    const float* posemb = (const float*)d_in[3];
    const float* pixemb = (const float*)d_in[4];
    const float* wout   = (const float*)d_in[5];
    const float* bout   = (const float*)d_in[6];
    float* out = (float*)d_out;

    cudaFuncSetAttribute(qkv_gemm_mma, cudaFuncAttributeMaxDynamicSharedMemorySize,
                         SMEM_BYTES);
    cudaFuncSetAttribute(out_gemm_mma, cudaFuncAttributeMaxDynamicSharedMemorySize,
                         SMEM_BYTES);

    prep_x<<<27648, 256>>>(x);
    prep_w<<<576, 256>>>(wqkv, wout);
    qkv_gemm_mma<<<dim3(QKV_N / 128, MROWS / 128), 256, SMEM_BYTES>>>();
    attn_mma<<<dim3(NW * NHEADS, BB), 288>>>(pixmap, posemb, pixemb);
    out_gemm_mma<<<dim3(384 / 128, MROWS / 128), 256, SMEM_BYTES>>>(bout, out);
}

// round 9
// speedup vs baseline: 2.6992x; 1.3354x over previous
#include <cuda_runtime.h>
#include <cuda_bf16.h>
#include <cuda_fp16.h>
#include <cstdint>

// Shapes
#define BB     8
#define NHEADS 12
#define HD     32
#define NW     64
#define WSQ    144
#define MROWS  73728        // BB*NW*WSQ
#define QKV_N  1152

// Scratch (allocation-free rule: __device__ globals)
__device__ __nv_bfloat16 g_qh[MROWS * 384];   // per-head [B,NW,H,144,32]
__device__ __nv_bfloat16 g_ql[MROWS * 384];
__device__ __nv_bfloat16 g_kth[MROWS * 384];  // per-head transposed [B,NW,H,32,144]
__device__ __nv_bfloat16 g_ktl[MROWS * 384];
__device__ __nv_bfloat16 g_vh[MROWS * 384];   // per-head [B,NW,H,144,32]
__device__ __nv_bfloat16 g_vl[MROWS * 384];
__device__ __half g_xh[MROWS * 384];          // fp16 split-2 (A operand)
__device__ __half g_xl[MROWS * 384];
__device__ __half g_atth[MROWS * 384];
__device__ __half g_attl[MROWS * 384];
__device__ __half g_wqh[384 * QKV_N];         // fp16 hi-only (B operand)
__device__ __half g_woh[384 * 384];

// ---------------------------------------------------------------------------
// helpers
// ---------------------------------------------------------------------------
__device__ __forceinline__ uint32_t smem_u32(const void* p) {
    return (uint32_t)__cvta_generic_to_shared(p);
}
__device__ __forceinline__ void ldsmx4(uint32_t& r0, uint32_t& r1, uint32_t& r2,
                                       uint32_t& r3, uint32_t a) {
    asm volatile("ldmatrix.sync.aligned.m8n8.x4.shared.b16 {%0,%1,%2,%3}, [%4];"
                 : "=r"(r0), "=r"(r1), "=r"(r2), "=r"(r3) : "r"(a));
}
__device__ __forceinline__ void ldsmx4t(uint32_t& r0, uint32_t& r1, uint32_t& r2,
                                        uint32_t& r3, uint32_t a) {
    asm volatile("ldmatrix.sync.aligned.m8n8.x4.trans.shared.b16 {%0,%1,%2,%3}, [%4];"
                 : "=r"(r0), "=r"(r1), "=r"(r2), "=r"(r3) : "r"(a));
}
__device__ __forceinline__ void mma_f16(float* c, const uint32_t* a,
                                        uint32_t b0, uint32_t b1) {
    asm volatile(
        "mma.sync.aligned.m16n8k16.row.col.f32.f16.f16.f32 "
        "{%0,%1,%2,%3},{%4,%5,%6,%7},{%8,%9},{%0,%1,%2,%3};"
        : "+f"(c[0]), "+f"(c[1]), "+f"(c[2]), "+f"(c[3])
        : "r"(a[0]), "r"(a[1]), "r"(a[2]), "r"(a[3]), "r"(b0), "r"(b1));
}
__device__ __forceinline__ void mma_bf16(float* c, const uint32_t* a,
                                         uint32_t b0, uint32_t b1) {
    asm volatile(
        "mma.sync.aligned.m16n8k16.row.col.f32.bf16.bf16.f32 "
        "{%0,%1,%2,%3},{%4,%5,%6,%7},{%8,%9},{%0,%1,%2,%3};"
        : "+f"(c[0]), "+f"(c[1]), "+f"(c[2]), "+f"(c[3])
        : "r"(a[0]), "r"(a[1]), "r"(a[2]), "r"(a[3]), "r"(b0), "r"(b1));
}
__device__ __forceinline__ void split2(float f, __nv_bfloat16& h, __nv_bfloat16& l) {
    h = __float2bfloat16_rn(f);
    l = __float2bfloat16_rn(f - __bfloat162float(h));
}
__device__ __forceinline__ void split2h(float f, __half& h, __half& l) {
    h = __float2half_rn(f);
    l = __float2half_rn(f - __half2float(h));
}
__device__ __forceinline__ uint32_t packbf2(__nv_bfloat16 a, __nv_bfloat16 b) {
    __nv_bfloat162 v(a, b);
    return *(uint32_t*)&v;
}
__device__ __forceinline__ uint32_t packh2(__half a, __half b) {
    __half2 v = __halves2half2(a, b);
    return *(uint32_t*)&v;
}
__device__ __forceinline__ void cpasync16(void* s, const void* g) {
    asm volatile("cp.async.cg.shared.global [%0], [%1], 16;"
                 :: "r"(smem_u32(s)), "l"(g));
}

#define AST  40      // A smem row stride (fp16 elems): 80 B -> conflict-free
#define BST  136     // B smem row stride: 272 B -> conflict-free
#define A_STAGE 5120 // 128*AST
#define B_STAGE 4352 // 32*BST
#define NST  4
#define SMEM_BYTES ((2 * NST * A_STAGE + NST * B_STAGE) * 2)   // 116736

// ---------------------------------------------------------------------------
// Prep kernels: roll-gather + fp32 -> fp16 split
// ---------------------------------------------------------------------------
__global__ __launch_bounds__(256) void prep_x(const float* __restrict__ X) {
    const int id = blockIdx.x * 256 + threadIdx.x;   // float4 id
    const int r = id / 96, t = id - r * 96;
    int b = r / 9216; int rem = r - b * 9216;
    int w = rem / 144; int i = rem - w * 144;
    int y = (w >> 3) * 12 + i / 12 + 6; if (y >= 96) y -= 96;
    int x = (w & 7) * 12 + i % 12 + 6;  if (x >= 96) x -= 96;
    float4 v = *((const float4*)(X + ((b * 96 + y) * 96 + x) * 384) + t);
    __half hx, hy, hz, hw, lx, ly, lz, lw;
    split2h(v.x, hx, lx); split2h(v.y, hy, ly);
    split2h(v.z, hz, lz); split2h(v.w, hw, lw);
    int o = r * 384 + t * 4;
    *(uint32_t*)(g_xh + o)     = packh2(hx, hy);
    *(uint32_t*)(g_xh + o + 2) = packh2(hz, hw);
    *(uint32_t*)(g_xl + o)     = packh2(lx, ly);
    *(uint32_t*)(g_xl + o + 2) = packh2(lz, lw);
}

__global__ __launch_bounds__(256) void prep_w(const float* __restrict__ wqkv,
                                              const float* __restrict__ wout) {
    const int id = blockIdx.x * 256 + threadIdx.x;  // float4 index
    float4 v;
    __half* oh; int o;
    if (id < 110592) {                        // 384*1152/4
        v = ((const float4*)wqkv)[id];
        oh = g_wqh; o = id * 4;
    } else {
        int id2 = id - 110592;                // < 36864
        v = ((const float4*)wout)[id2];
        oh = g_woh; o = id2 * 4;
    }
    *(uint32_t*)(oh + o)     = packh2(__float2half_rn(v.x), __float2half_rn(v.y));
    *(uint32_t*)(oh + o + 2) = packh2(__float2half_rn(v.z), __float2half_rn(v.w));
}

// ---------------------------------------------------------------------------
// GEMM: 128x128 tile, BK=32, 256 thr, 8 warps (4m x 2n, 32x64 warp tile).
// fp16 2-mma scheme: C += Ah*Bh + Al*Bh  (B lo term dropped, ~2^-12 rel).
// 4-stage cp.async pipeline.
// ---------------------------------------------------------------------------
__device__ __forceinline__ void load_stage(
    const __half* __restrict__ Agh, const __half* __restrict__ Agl,
    const __half* __restrict__ Bgh,
    __half* Ah, __half* Al, __half* Bh,
    int m0, int n0, int ldb, int k0, int st, int tid)
{
    __half* ash = Ah + st * A_STAGE;
    __half* asl = Al + st * A_STAGE;
    __half* bsh = Bh + st * B_STAGE;
#pragma unroll
    for (int q = 0; q < 2; q++) {
        int c = tid * 2 + q;
        int row = c >> 2, ch = (c & 3) * 8;                 // A: 128 x 32
        int go = (m0 + row) * 384 + k0 + ch;
        int so = row * AST + ch;
        cpasync16(ash + so, Agh + go);
        cpasync16(asl + so, Agl + go);
    }
#pragma unroll
    for (int q = 0; q < 2; q++) {
        int c = tid * 2 + q;
        int row = c >> 4, ch = (c & 15) * 8;                // B: 32 x 128
        int go = (k0 + row) * ldb + n0 + ch;
        int so = row * BST + ch;
        cpasync16(bsh + so, Bgh + go);
    }
}

__device__ __forceinline__ void compute_stage(
    const __half* Ah, const __half* Al, const __half* Bh,
    int wm, int wn, int lane, float acc[2][8][4])
{
#pragma unroll
    for (int ks = 0; ks < 2; ks++) {
        const int kk = ks * 16;
        uint32_t ah[2][4], al[2][4], bh[4][4];
        const int arow = wm + (lane & 15);
        const int acol = kk + (lane >> 4) * 8;
#pragma unroll
        for (int mt = 0; mt < 2; mt++) {
            ldsmx4(ah[mt][0], ah[mt][1], ah[mt][2], ah[mt][3],
                   smem_u32(Ah + (arow + mt * 16) * AST + acol));
            ldsmx4(al[mt][0], al[mt][1], al[mt][2], al[mt][3],
                   smem_u32(Al + (arow + mt * 16) * AST + acol));
        }
        const int bk = kk + (lane & 15);
        const int bnb = wn + (lane >> 4) * 8;
#pragma unroll
        for (int g = 0; g < 4; g++) {
            ldsmx4t(bh[g][0], bh[g][1], bh[g][2], bh[g][3],
                    smem_u32(Bh + bk * BST + bnb + g * 16));
        }
#pragma unroll
        for (int mt = 0; mt < 2; mt++)
#pragma unroll
            for (int g = 0; g < 4; g++)
#pragma unroll
                for (int hf = 0; hf < 2; hf++) {
                    float* c = acc[mt][2 * g + hf];
                    mma_f16(c, ah[mt], bh[g][2 * hf], bh[g][2 * hf + 1]);
                    mma_f16(c, al[mt], bh[g][2 * hf], bh[g][2 * hf + 1]);
                }
    }
}

#define GEMM_MAINLOOP(AGH, AGL, BGH, LDB)                                        \
    extern __shared__ __align__(16) __half smem[];                               \
    __half* Ah = smem;                                                           \
    __half* Al = smem + NST * A_STAGE;                                           \
    __half* Bh = smem + 2 * NST * A_STAGE;                                       \
    const int tid = threadIdx.x;                                                 \
    const int m0 = blockIdx.y * 128;                                             \
    const int n0 = blockIdx.x * 128;                                             \
    const int wid = tid >> 5, lane = tid & 31;                                   \
    const int wm = (wid >> 1) * 32;                                              \
    const int wn = (wid & 1) * 64;                                               \
    float acc[2][8][4];                                                          \
    _Pragma("unroll") for (int a_ = 0; a_ < 2; a_++)                             \
    _Pragma("unroll") for (int b_ = 0; b_ < 8; b_++)                             \
    _Pragma("unroll") for (int c_ = 0; c_ < 4; c_++) acc[a_][b_][c_] = 0.f;      \
    _Pragma("unroll") for (int s_ = 0; s_ < NST - 1; s_++) {                     \
        load_stage(AGH, AGL, BGH, Ah, Al, Bh, m0, n0, LDB, s_ * 32, s_, tid);    \
        asm volatile("cp.async.commit_group;" ::: "memory");                     \
    }                                                                            \
    for (int it = 0; it < 12; it++) {                                            \
        asm volatile("cp.async.wait_group %0;" :: "n"(NST - 2) : "memory");      \
        __syncthreads();                                                         \
        if (it < 12 - (NST - 1)) {                                               \
            load_stage(AGH, AGL, BGH, Ah, Al, Bh, m0, n0, LDB,                   \
                       (it + NST - 1) * 32, (it + NST - 1) & (NST - 1), tid);    \
        }                                                                        \
        asm volatile("cp.async.commit_group;" ::: "memory");                     \
        const int st = it & (NST - 1);                                           \
        compute_stage(Ah + st * A_STAGE, Al + st * A_STAGE,                      \
                      Bh + st * B_STAGE, wm, wn, lane, acc);                     \
    }

// ---------------------------------------------------------------------------
// Kernel: QKV GEMM -> emit attention-ready bf16 hi/lo:
//   Q,V row-major per-head [.,144,32]; K transposed per-head [.,32,144].
// ---------------------------------------------------------------------------
__global__ __launch_bounds__(256, 1) void qkv_gemm_mma() {
    GEMM_MAINLOOP(g_xh, g_xl, g_wqh, QKV_N)

    const int part = n0 / 384;
    const int cbase = n0 - part * 384;

#pragma unroll
    for (int mt = 0; mt < 2; mt++) {
#pragma unroll
        for (int rr = 0; rr < 2; rr++) {
            int r = m0 + wm + mt * 16 + (lane >> 2) + rr * 8;
            int b = r / 9216; int rem = r - b * 9216;
            int w = rem / 144; int i = rem - w * 144;
            int bw12 = (b * 64 + w) * 12;
#pragma unroll
            for (int nt = 0; nt < 8; nt++) {
                int c = cbase + wn + nt * 8 + (lane & 3) * 2;
                int h = c >> 5, d = c & 31;
                float f0 = acc[mt][nt][rr * 2], f1 = acc[mt][nt][rr * 2 + 1];
                __nv_bfloat16 h0, l0, h1, l1;
                split2(f0, h0, l0); split2(f1, h1, l1);
                if (part == 1) {              // K: transposed [32][144]
                    int tk = (bw12 + h) * 4608 + d * 144 + i;
                    g_kth[tk] = h0; g_kth[tk + 144] = h1;
                    g_ktl[tk] = l0; g_ktl[tk + 144] = l1;
                } else {                      // Q / V: row-major [144][32]
                    int tq = ((bw12 + h) * 144 + i) * 32 + d;
                    __nv_bfloat16* oh = (part == 0) ? g_qh : g_vh;
                    __nv_bfloat16* ol = (part == 0) ? g_ql : g_vl;
                    *(uint32_t*)(oh + tq) = packbf2(h0, h1);
                    *(uint32_t*)(ol + tq) = packbf2(l0, l1);
                }
            }
        }
    }
}

// ---------------------------------------------------------------------------
// Kernel: flash-chunked tensor-core attention. Block = (b, window, head),
// 9 warps x 16 query rows. Mask/pix folded into smem tables; masked entries
// become -1e30 so __expf() naturally yields 0.
// ---------------------------------------------------------------------------
#define KTST 152
#define VST  40

__global__ __launch_bounds__(288, 2) void attn_mma(const int* __restrict__ pixmap,
                                                   const float* __restrict__ posemb,
                                                   const float* __restrict__ pixemb) {
    __shared__ __align__(16) __nv_bfloat16 KTh[32 * KTST], KTl[32 * KTST];
    __shared__ __align__(16) __nv_bfloat16 Vsh[144 * VST], Vsl[144 * VST];
    __shared__ float pose[529];
    __shared__ float pmv[WSQ];
    __shared__ float MASKT[4 * WSQ];   // [(p*2+q)*144 + j] = mask(-1e30) + pe0
    __shared__ float PIXD[WSQ];        // (pm[j]!=0) * (pe1 - pe0)
    __shared__ int   jinfo[WSQ];       // jy*23 + jx

    const int tid = threadIdx.x;
    const int b = blockIdx.y;
    const int w = blockIdx.x / 12;
    const int h = blockIdx.x - w * 12;
    const int tb2 = ((b * 64 + w) * 12 + h) * 4608;
    const bool ul = (w >> 3) == 7;
    const bool lr = (w & 7) == 7;

#pragma unroll
    for (int q = 0; q < 2; q++) {
        int cix = tid + q * 288;
        int d = cix / 18, ch = (cix - d * 18) * 8;
        cpasync16(KTh + d * KTST + ch, g_kth + tb2 + d * 144 + ch);
        cpasync16(KTl + d * KTST + ch, g_ktl + tb2 + d * 144 + ch);
    }
#pragma unroll
    for (int q = 0; q < 2; q++) {
        int cix = tid + q * 288;
        int j = cix >> 2, ch = (cix & 3) * 8;
        cpasync16(Vsh + j * VST + ch, g_vh + tb2 + j * 32 + ch);
        cpasync16(Vsl + j * VST + ch, g_vl + tb2 + j * 32 + ch);
    }
    asm volatile("cp.async.commit_group;" ::: "memory");

    for (int f = tid; f < 529; f += 288) pose[f] = posemb[f];
    if (tid < 144) {
        int wy = w >> 3, wx = w & 7;
        int iy = tid / 12, ix = tid - iy * 12;
        float pm = (float)pixmap[(b * 96 + wy * 12 + iy) * 96 + wx * 12 + ix];
        pmv[tid] = pm;
        jinfo[tid] = iy * 23 + ix;
        float pe0 = pixemb[0], pe1 = pixemb[1];
        PIXD[tid] = (pm != 0.f) ? (pe1 - pe0) : 0.f;
        bool jh = tid >= 72, jxh = ix >= 6;
#pragma unroll
        for (int p = 0; p < 2; p++)
#pragma unroll
            for (int q = 0; q < 2; q++) {
                bool m = (ul && (jh != (bool)p)) || (lr && (jxh != (bool)q));
                MASKT[(p * 2 + q) * 144 + tid] = (m ? -1e30f : 0.f) + pe0;
            }
    }

    const int wr = tid >> 5;
    const int lane = tid & 31;
    const int g = lane >> 2, t = lane & 3;
    const int i0 = wr * 16 + g, i1 = i0 + 8;

    uint32_t qh[2][4], ql[2][4];
#pragma unroll
    for (int kc = 0; kc < 2; kc++) {
        int o0 = tb2 + i0 * 32 + kc * 16 + 2 * t;
        int o1 = tb2 + i1 * 32 + kc * 16 + 2 * t;
        qh[kc][0] = *(const uint32_t*)(g_qh + o0);
        ql[kc][0] = *(const uint32_t*)(g_ql + o0);
        qh[kc][1] = *(const uint32_t*)(g_qh + o1);
        ql[kc][1] = *(const uint32_t*)(g_ql + o1);
        qh[kc][2] = *(const uint32_t*)(g_qh + o0 + 8);
        ql[kc][2] = *(const uint32_t*)(g_ql + o0 + 8);
        qh[kc][3] = *(const uint32_t*)(g_qh + o1 + 8);
        ql[kc][3] = *(const uint32_t*)(g_ql + o1 + 8);
    }

    asm volatile("cp.async.wait_group 0;" ::: "memory");
    __syncthreads();

    const int iy0 = i0 / 12, ix0 = i0 - iy0 * 12;
    const int iy1 = i1 / 12, ix1 = i1 - iy1 * 12;
    const float* pr0 = pose + (11 - iy0) * 23 + (11 - ix0);
    const float* pr1 = pose + (11 - iy1) * 23 + (11 - ix1);
    const float* mr0 = MASKT + ((i0 >= 72 ? 2 : 0) + (ix0 >= 6 ? 1 : 0)) * 144;
    const float* mr1 = MASKT + ((i1 >= 72 ? 2 : 0) + (ix1 >= 6 ? 1 : 0)) * 144;
    const bool a0 = pmv[i0] != 0.f, a1 = pmv[i1] != 0.f;
    const float scale = 0.17677669529663689f;

    float oacc[4][4];
#pragma unroll
    for (int nt = 0; nt < 4; nt++)
#pragma unroll
        for (int c = 0; c < 4; c++) oacc[nt][c] = 0.f;
    float rs0 = 0.f, rs1 = 0.f;

#pragma unroll
    for (int jc = 0; jc < 9; jc++) {
        float sc[2][4];
#pragma unroll
        for (int u = 0; u < 2; u++)
#pragma unroll
            for (int c = 0; c < 4; c++) sc[u][c] = 0.f;
#pragma unroll
        for (int kc = 0; kc < 2; kc++) {
            uint32_t bh[4], bl[4];
            uint32_t ah_ = smem_u32(KTh + (kc * 16 + (lane & 15)) * KTST +
                                    jc * 16 + (lane >> 4) * 8);
            uint32_t al_ = smem_u32(KTl + (kc * 16 + (lane & 15)) * KTST +
                                    jc * 16 + (lane >> 4) * 8);
            ldsmx4t(bh[0], bh[1], bh[2], bh[3], ah_);
            ldsmx4t(bl[0], bl[1], bl[2], bl[3], al_);
            mma_bf16(sc[0], qh[kc], bh[0], bh[1]);
            mma_bf16(sc[0], qh[kc], bl[0], bl[1]);
            mma_bf16(sc[0], ql[kc], bh[0], bh[1]);
            mma_bf16(sc[1], qh[kc], bh[2], bh[3]);
            mma_bf16(sc[1], qh[kc], bl[2], bl[3]);
            mma_bf16(sc[1], ql[kc], bh[2], bh[3]);
        }

#pragma unroll
        for (int u = 0; u < 2; u++) {
#pragma unroll
            for (int fc = 0; fc < 2; fc++) {
                int j = jc * 16 + u * 8 + 2 * t + fc;
                int poff = jinfo[j];
                float pix = PIXD[j];
                {
                    float s = sc[u][fc] * scale + mr0[j] + (a0 ? pix : 0.f)
                              + pr0[poff];
                    float p = __expf(s);
                    sc[u][fc] = p; rs0 += p;
                }
                {
                    float s = sc[u][fc + 2] * scale + mr1[j] + (a1 ? pix : 0.f)
                              + pr1[poff];
                    float p = __expf(s);
                    sc[u][fc + 2] = p; rs1 += p;
                }
            }
        }

        uint32_t ph[4], pl[4];
        {
            __nv_bfloat16 ha, la, hb, lb;
            split2(sc[0][0], ha, la); split2(sc[0][1], hb, lb);
            ph[0] = packbf2(ha, hb); pl[0] = packbf2(la, lb);
            split2(sc[0][2], ha, la); split2(sc[0][3], hb, lb);
            ph[1] = packbf2(ha, hb); pl[1] = packbf2(la, lb);
            split2(sc[1][0], ha, la); split2(sc[1][1], hb, lb);
            ph[2] = packbf2(ha, hb); pl[2] = packbf2(la, lb);
            split2(sc[1][2], ha, la); split2(sc[1][3], hb, lb);
            ph[3] = packbf2(ha, hb); pl[3] = packbf2(la, lb);
        }
#pragma unroll
        for (int ng = 0; ng < 2; ng++) {
            uint32_t bh[4], bl[4];
            uint32_t ah_ = smem_u32(Vsh + (jc * 16 + (lane & 15)) * VST +
                                    ng * 16 + (lane >> 4) * 8);
            uint32_t al_ = smem_u32(Vsl + (jc * 16 + (lane & 15)) * VST +
                                    ng * 16 + (lane >> 4) * 8);
            ldsmx4t(bh[0], bh[1], bh[2], bh[3], ah_);
            ldsmx4t(bl[0], bl[1], bl[2], bl[3], al_);
            mma_bf16(oacc[2 * ng],     ph, bh[0], bh[1]);
            mma_bf16(oacc[2 * ng],     ph, bl[0], bl[1]);
            mma_bf16(oacc[2 * ng],     pl, bh[0], bh[1]);
            mma_bf16(oacc[2 * ng + 1], ph, bh[2], bh[3]);
            mma_bf16(oacc[2 * ng + 1], ph, bl[2], bl[3]);
            mma_bf16(oacc[2 * ng + 1], pl, bh[2], bh[3]);
        }
    }

    rs0 += __shfl_xor_sync(0xffffffff, rs0, 1);
    rs0 += __shfl_xor_sync(0xffffffff, rs0, 2);
    rs1 += __shfl_xor_sync(0xffffffff, rs1, 1);
    rs1 += __shfl_xor_sync(0xffffffff, rs1, 2);
    const float inv0 = 1.f / rs0, inv1 = 1.f / rs1;

    // write normalized output as fp16 hi/lo for the out-proj GEMM
    const int orow0 = ((b * 64 + w) * 144 + i0) * 384 + h * 32;
    const int orow1 = ((b * 64 + w) * 144 + i1) * 384 + h * 32;
#pragma unroll
    for (int nt = 0; nt < 4; nt++) {
        int col = nt * 8 + 2 * t;
        __half ha, la, hb, lb;
        float f0 = oacc[nt][0] * inv0, f1 = oacc[nt][1] * inv0;
        split2h(f0, ha, la); split2h(f1, hb, lb);
        *(uint32_t*)(g_atth + orow0 + col) = packh2(ha, hb);
        *(uint32_t*)(g_attl + orow0 + col) = packh2(la, lb);
        float f2 = oacc[nt][2] * inv1, f3 = oacc[nt][3] * inv1;
        split2h(f2, ha, la); split2h(f3, hb, lb);
        *(uint32_t*)(g_atth + orow1 + col) = packh2(ha, hb);
        *(uint32_t*)(g_attl + orow1 + col) = packh2(la, lb);
    }
}

// ---------------------------------------------------------------------------
// Kernel: output projection + bias + window-merge + roll(+6,+6) scatter
// ---------------------------------------------------------------------------
__global__ __launch_bounds__(256, 1) void out_gemm_mma(const float* __restrict__ bout,
                                                       float* __restrict__ Out) {
    GEMM_MAINLOOP(g_atth, g_attl, g_woh, 384)

#pragma unroll
    for (int mt = 0; mt < 2; mt++) {
#pragma unroll
        for (int rr = 0; rr < 2; rr++) {
            int r = m0 + wm + mt * 16 + (lane >> 2) + rr * 8;
            int b = r / 9216; int rem = r - b * 9216;
            int w = rem / 144; int i = rem - w * 144;
            int iy = i / 12, ix = i - iy * 12;
            int y = (w >> 3) * 12 + iy + 6; if (y >= 96) y -= 96;
            int x = (w & 7) * 12 + ix + 6;  if (x >= 96) x -= 96;
            float* orow = Out + ((b * 96 + y) * 96 + x) * 384;
#pragma unroll
            for (int nt = 0; nt < 8; nt++) {
                int c = n0 + wn + nt * 8 + (lane & 3) * 2;
                float2 bi = *(const float2*)(bout + c);
                float2 v = make_float2(acc[mt][nt][rr * 2] + bi.x,
                                       acc[mt][nt][rr * 2 + 1] + bi.y);
                *(float2*)(orow + c) = v;
            }
        }
    }
}

// ---------------------------------------------------------------------------
extern "C" void kernel_launch(void* const* d_in, const int* in_sizes, int n_in,
                              void* d_out, int out_size) {
    (void)in_sizes; (void)n_in; (void)out_size;
    const float* x      = (const float*)d_in[0];
    const int*   pixmap = (const int*)d_in[1];
    const float* wqkv   = (const float*)d_in[2];
    const float* posemb = (const float*)d_in[3];
    const float* pixemb = (const float*)d_in[4];
    const float* wout   = (const float*)d_in[5];
    const float* bout   = (const float*)d_in[6];
    float* out = (float*)d_out;

    cudaFuncSetAttribute(qkv_gemm_mma, cudaFuncAttributeMaxDynamicSharedMemorySize,
                         SMEM_BYTES);
    cudaFuncSetAttribute(out_gemm_mma, cudaFuncAttributeMaxDynamicSharedMemorySize,
                         SMEM_BYTES);

    prep_x<<<27648, 256>>>(x);
    prep_w<<<576, 256>>>(wqkv, wout);
    qkv_gemm_mma<<<dim3(QKV_N / 128, MROWS / 128), 256, SMEM_BYTES>>>();
    attn_mma<<<dim3(NW * NHEADS, BB), 288>>>(pixmap, posemb, pixemb);
    out_gemm_mma<<<dim3(384 / 128, MROWS / 128), 256, SMEM_BYTES>>>(bout, out);
}

// round 10
// speedup vs baseline: 3.0939x; 1.1462x over previous
#include <cuda_runtime.h>
#include <cuda_bf16.h>
#include <cuda_fp16.h>
#include <cstdint>

// Shapes
#define BB     8
#define NHEADS 12
#define HD     32
#define NW     64
#define WSQ    144
#define MROWS  73728        // BB*NW*WSQ
#define QKV_N  1152
#define LOG2E  1.4426950408889634f

// Scratch (allocation-free rule: __device__ globals)
__device__ __nv_bfloat16 g_qh[MROWS * 384];   // per-head [B,NW,H,144,32]
__device__ __nv_bfloat16 g_ql[MROWS * 384];
__device__ __nv_bfloat16 g_kh[MROWS * 384];   // per-head [B,NW,H,144,32] (row-major!)
__device__ __nv_bfloat16 g_kl[MROWS * 384];
__device__ __half        g_vh[MROWS * 384];   // per-head, fp16 hi only
__device__ __half g_xh[MROWS * 384];          // fp16 split-2 (A operand)
__device__ __half g_xl[MROWS * 384];
__device__ __half g_atth[MROWS * 384];        // fp16 hi only (out-proj A)
__device__ __half g_wqh[384 * QKV_N];         // fp16 hi-only (B operand)
__device__ __half g_woh[384 * 384];

// ---------------------------------------------------------------------------
// helpers
// ---------------------------------------------------------------------------
__device__ __forceinline__ uint32_t smem_u32(const void* p) {
    return (uint32_t)__cvta_generic_to_shared(p);
}
__device__ __forceinline__ void ldsmx4(uint32_t& r0, uint32_t& r1, uint32_t& r2,
                                       uint32_t& r3, uint32_t a) {
    asm volatile("ldmatrix.sync.aligned.m8n8.x4.shared.b16 {%0,%1,%2,%3}, [%4];"
                 : "=r"(r0), "=r"(r1), "=r"(r2), "=r"(r3) : "r"(a));
}
__device__ __forceinline__ void ldsmx4t(uint32_t& r0, uint32_t& r1, uint32_t& r2,
                                        uint32_t& r3, uint32_t a) {
    asm volatile("ldmatrix.sync.aligned.m8n8.x4.trans.shared.b16 {%0,%1,%2,%3}, [%4];"
                 : "=r"(r0), "=r"(r1), "=r"(r2), "=r"(r3) : "r"(a));
}
__device__ __forceinline__ void mma_f16(float* c, const uint32_t* a,
                                        uint32_t b0, uint32_t b1) {
    asm volatile(
        "mma.sync.aligned.m16n8k16.row.col.f32.f16.f16.f32 "
        "{%0,%1,%2,%3},{%4,%5,%6,%7},{%8,%9},{%0,%1,%2,%3};"
        : "+f"(c[0]), "+f"(c[1]), "+f"(c[2]), "+f"(c[3])
        : "r"(a[0]), "r"(a[1]), "r"(a[2]), "r"(a[3]), "r"(b0), "r"(b1));
}
__device__ __forceinline__ void mma_bf16(float* c, const uint32_t* a,
                                         uint32_t b0, uint32_t b1) {
    asm volatile(
        "mma.sync.aligned.m16n8k16.row.col.f32.bf16.bf16.f32 "
        "{%0,%1,%2,%3},{%4,%5,%6,%7},{%8,%9},{%0,%1,%2,%3};"
        : "+f"(c[0]), "+f"(c[1]), "+f"(c[2]), "+f"(c[3])
        : "r"(a[0]), "r"(a[1]), "r"(a[2]), "r"(a[3]), "r"(b0), "r"(b1));
}
__device__ __forceinline__ void split2(float f, __nv_bfloat16& h, __nv_bfloat16& l) {
    h = __float2bfloat16_rn(f);
    l = __float2bfloat16_rn(f - __bfloat162float(h));
}
__device__ __forceinline__ void split2h(float f, __half& h, __half& l) {
    h = __float2half_rn(f);
    l = __float2half_rn(f - __half2float(h));
}
__device__ __forceinline__ uint32_t packbf2(__nv_bfloat16 a, __nv_bfloat16 b) {
    __nv_bfloat162 v(a, b);
    return *(uint32_t*)&v;
}
__device__ __forceinline__ uint32_t packh2(__half a, __half b) {
    __half2 v = __halves2half2(a, b);
    return *(uint32_t*)&v;
}
__device__ __forceinline__ void cpasync16(void* s, const void* g) {
    asm volatile("cp.async.cg.shared.global [%0], [%1], 16;"
                 :: "r"(smem_u32(s)), "l"(g));
}
__device__ __forceinline__ float ex2f(float x) {
    float r;
    asm("ex2.approx.f32 %0, %1;" : "=f"(r) : "f"(x));
    return r;
}

#define AST  40      // A smem row stride (fp16 elems): 80 B -> conflict-free
#define BST  136     // B smem row stride: 272 B -> conflict-free
#define A_STAGE 5120 // 128*AST
#define B_STAGE 4352 // 32*BST
#define NST  4
#define SMEM_QKV ((2 * NST * A_STAGE + NST * B_STAGE) * 2)   // 116736
#define SMEM_OUT ((NST * A_STAGE + NST * B_STAGE) * 2)       // 75776

// ---------------------------------------------------------------------------
// Prep kernels: roll-gather + fp32 -> fp16 split
// ---------------------------------------------------------------------------
__global__ __launch_bounds__(256) void prep_x(const float* __restrict__ X) {
    const int id = blockIdx.x * 256 + threadIdx.x;   // float4 id
    const int r = id / 96, t = id - r * 96;
    int b = r / 9216; int rem = r - b * 9216;
    int w = rem / 144; int i = rem - w * 144;
    int y = (w >> 3) * 12 + i / 12 + 6; if (y >= 96) y -= 96;
    int x = (w & 7) * 12 + i % 12 + 6;  if (x >= 96) x -= 96;
    float4 v = *((const float4*)(X + ((b * 96 + y) * 96 + x) * 384) + t);
    __half hx, hy, hz, hw, lx, ly, lz, lw;
    split2h(v.x, hx, lx); split2h(v.y, hy, ly);
    split2h(v.z, hz, lz); split2h(v.w, hw, lw);
    int o = r * 384 + t * 4;
    *(uint32_t*)(g_xh + o)     = packh2(hx, hy);
    *(uint32_t*)(g_xh + o + 2) = packh2(hz, hw);
    *(uint32_t*)(g_xl + o)     = packh2(lx, ly);
    *(uint32_t*)(g_xl + o + 2) = packh2(lz, lw);
}

__global__ __launch_bounds__(256) void prep_w(const float* __restrict__ wqkv,
                                              const float* __restrict__ wout) {
    const int id = blockIdx.x * 256 + threadIdx.x;  // float4 index
    float4 v;
    __half* oh; int o;
    if (id < 110592) {                        // 384*1152/4
        v = ((const float4*)wqkv)[id];
        oh = g_wqh; o = id * 4;
    } else {
        int id2 = id - 110592;                // < 36864
        v = ((const float4*)wout)[id2];
        oh = g_woh; o = id2 * 4;
    }
    *(uint32_t*)(oh + o)     = packh2(__float2half_rn(v.x), __float2half_rn(v.y));
    *(uint32_t*)(oh + o + 2) = packh2(__float2half_rn(v.z), __float2half_rn(v.w));
}

// ---------------------------------------------------------------------------
// GEMM: 128x128 tile, BK=32, 256 thr, 8 warps (4m x 2n, 32x64 warp tile).
// UAL=true: C += Ah*Bh + Al*Bh (2 mmas). UAL=false: C += Ah*Bh (1 mma).
// 4-stage cp.async pipeline.
// ---------------------------------------------------------------------------
template<bool UAL>
__device__ __forceinline__ void load_stage(
    const __half* __restrict__ Agh, const __half* __restrict__ Agl,
    const __half* __restrict__ Bgh,
    __half* Ah, __half* Al, __half* Bh,
    int m0, int n0, int ldb, int k0, int st, int tid)
{
    __half* ash = Ah + st * A_STAGE;
    __half* bsh = Bh + st * B_STAGE;
#pragma unroll
    for (int q = 0; q < 2; q++) {
        int c = tid * 2 + q;
        int row = c >> 2, ch = (c & 3) * 8;                 // A: 128 x 32
        int go = (m0 + row) * 384 + k0 + ch;
        int so = row * AST + ch;
        cpasync16(ash + so, Agh + go);
        if (UAL) cpasync16(Al + st * A_STAGE + so, Agl + go);
    }
#pragma unroll
    for (int q = 0; q < 2; q++) {
        int c = tid * 2 + q;
        int row = c >> 4, ch = (c & 15) * 8;                // B: 32 x 128
        int go = (k0 + row) * ldb + n0 + ch;
        cpasync16(bsh + row * BST + ch, Bgh + go);
    }
}

template<bool UAL>
__device__ __forceinline__ void compute_stage(
    const __half* Ah, const __half* Al, const __half* Bh,
    int wm, int wn, int lane, float acc[2][8][4])
{
#pragma unroll
    for (int ks = 0; ks < 2; ks++) {
        const int kk = ks * 16;
        uint32_t ah[2][4], al[2][4], bh[4][4];
        const int arow = wm + (lane & 15);
        const int acol = kk + (lane >> 4) * 8;
#pragma unroll
        for (int mt = 0; mt < 2; mt++) {
            ldsmx4(ah[mt][0], ah[mt][1], ah[mt][2], ah[mt][3],
                   smem_u32(Ah + (arow + mt * 16) * AST + acol));
            if (UAL)
                ldsmx4(al[mt][0], al[mt][1], al[mt][2], al[mt][3],
                       smem_u32(Al + (arow + mt * 16) * AST + acol));
        }
        const int bk = kk + (lane & 15);
        const int bnb = wn + (lane >> 4) * 8;
#pragma unroll
        for (int g = 0; g < 4; g++) {
            ldsmx4t(bh[g][0], bh[g][1], bh[g][2], bh[g][3],
                    smem_u32(Bh + bk * BST + bnb + g * 16));
        }
#pragma unroll
        for (int mt = 0; mt < 2; mt++)
#pragma unroll
            for (int g = 0; g < 4; g++)
#pragma unroll
                for (int hf = 0; hf < 2; hf++) {
                    float* c = acc[mt][2 * g + hf];
                    mma_f16(c, ah[mt], bh[g][2 * hf], bh[g][2 * hf + 1]);
                    if (UAL) mma_f16(c, al[mt], bh[g][2 * hf], bh[g][2 * hf + 1]);
                }
    }
}

#define GEMM_MAINLOOP(UAL, AGH, AGL, BGH, LDB)                                   \
    extern __shared__ __align__(16) __half smem[];                               \
    __half* Ah = smem;                                                           \
    __half* Al = smem + NST * A_STAGE;                                           \
    __half* Bh = smem + (UAL ? 2 : 1) * NST * A_STAGE;                           \
    const int tid = threadIdx.x;                                                 \
    const int m0 = blockIdx.y * 128;                                             \
    const int n0 = blockIdx.x * 128;                                             \
    const int wid = tid >> 5, lane = tid & 31;                                   \
    const int wm = (wid >> 1) * 32;                                              \
    const int wn = (wid & 1) * 64;                                               \
    float acc[2][8][4];                                                          \
    _Pragma("unroll") for (int a_ = 0; a_ < 2; a_++)                             \
    _Pragma("unroll") for (int b_ = 0; b_ < 8; b_++)                             \
    _Pragma("unroll") for (int c_ = 0; c_ < 4; c_++) acc[a_][b_][c_] = 0.f;      \
    _Pragma("unroll") for (int s_ = 0; s_ < NST - 1; s_++) {                     \
        load_stage<UAL>(AGH, AGL, BGH, Ah, Al, Bh, m0, n0, LDB, s_ * 32, s_, tid);\
        asm volatile("cp.async.commit_group;" ::: "memory");                     \
    }                                                                            \
    for (int it = 0; it < 12; it++) {                                            \
        asm volatile("cp.async.wait_group %0;" :: "n"(NST - 2) : "memory");      \
        __syncthreads();                                                         \
        if (it < 12 - (NST - 1)) {                                               \
            load_stage<UAL>(AGH, AGL, BGH, Ah, Al, Bh, m0, n0, LDB,              \
                            (it + NST - 1) * 32, (it + NST - 1) & (NST - 1), tid);\
        }                                                                        \
        asm volatile("cp.async.commit_group;" ::: "memory");                     \
        const int st = it & (NST - 1);                                           \
        compute_stage<UAL>(Ah + st * A_STAGE, Al + st * A_STAGE,                 \
                           Bh + st * B_STAGE, wm, wn, lane, acc);                \
    }

// ---------------------------------------------------------------------------
// Kernel: QKV GEMM -> Q,K bf16 hi/lo row-major per-head; V fp16 hi row-major.
// ---------------------------------------------------------------------------
__global__ __launch_bounds__(256, 1) void qkv_gemm_mma() {
    GEMM_MAINLOOP(true, g_xh, g_xl, g_wqh, QKV_N)

    const int part = n0 / 384;
    const int cbase = n0 - part * 384;

#pragma unroll
    for (int mt = 0; mt < 2; mt++) {
#pragma unroll
        for (int rr = 0; rr < 2; rr++) {
            int r = m0 + wm + mt * 16 + (lane >> 2) + rr * 8;
            int b = r / 9216; int rem = r - b * 9216;
            int w = rem / 144; int i = rem - w * 144;
            int bw12 = (b * 64 + w) * 12;
#pragma unroll
            for (int nt = 0; nt < 8; nt++) {
                int c = cbase + wn + nt * 8 + (lane & 3) * 2;
                int h = c >> 5, d = c & 31;
                int tq = ((bw12 + h) * 144 + i) * 32 + d;
                float f0 = acc[mt][nt][rr * 2], f1 = acc[mt][nt][rr * 2 + 1];
                if (part == 2) {              // V: fp16 hi only
                    *(uint32_t*)(g_vh + tq) =
                        packh2(__float2half_rn(f0), __float2half_rn(f1));
                } else {                      // Q / K: bf16 hi/lo
                    __nv_bfloat16 h0, l0, h1, l1;
                    split2(f0, h0, l0); split2(f1, h1, l1);
                    __nv_bfloat16* oh = (part == 0) ? g_qh : g_kh;
                    __nv_bfloat16* ol = (part == 0) ? g_ql : g_kl;
                    *(uint32_t*)(oh + tq) = packbf2(h0, h1);
                    *(uint32_t*)(ol + tq) = packbf2(l0, l1);
                }
            }
        }
    }
}

// ---------------------------------------------------------------------------
// Kernel: flash-chunked tensor-core attention.
// S: bf16 split-2 (3 mmas), K row-major consumed via non-trans ldmatrix.
// PV: fp16 (P split-2, V hi) -> 2 mmas. Softmax: single EX2 via folded tables.
// ---------------------------------------------------------------------------
#define VST  40

__global__ __launch_bounds__(288, 2) void attn_mma(const int* __restrict__ pixmap,
                                                   const float* __restrict__ posemb,
                                                   const float* __restrict__ pixemb) {
    __shared__ __align__(16) __nv_bfloat16 Ksh[144 * VST], Ksl[144 * VST];
    __shared__ __align__(16) __half Vsh[144 * VST];
    __shared__ float pose[529];        // pre-scaled by log2e
    __shared__ float pmv[WSQ];
    __shared__ float MASKP[8 * WSQ];   // [(cls*2+act)*144+j], log2e-domain
    __shared__ int   jinfo[WSQ];

    const int tid = threadIdx.x;
    const int b = blockIdx.y;
    const int w = blockIdx.x / 12;
    const int h = blockIdx.x - w * 12;
    const int tb2 = ((b * 64 + w) * 12 + h) * 4608;
    const bool ul = (w >> 3) == 7;
    const bool lr = (w & 7) == 7;

#pragma unroll
    for (int q = 0; q < 2; q++) {
        int cix = tid + q * 288;                 // < 576
        int j = cix >> 2, ch = (cix & 3) * 8;
        cpasync16(Ksh + j * VST + ch, g_kh + tb2 + j * 32 + ch);
        cpasync16(Ksl + j * VST + ch, g_kl + tb2 + j * 32 + ch);
        cpasync16(Vsh + j * VST + ch, g_vh + tb2 + j * 32 + ch);
    }
    asm volatile("cp.async.commit_group;" ::: "memory");

    for (int f = tid; f < 529; f += 288) pose[f] = posemb[f] * LOG2E;
    if (tid < 144) {
        int wy = w >> 3, wx = w & 7;
        int iy = tid / 12, ix = tid - iy * 12;
        float pm = (float)pixmap[(b * 96 + wy * 12 + iy) * 96 + wx * 12 + ix];
        pmv[tid] = pm;
        jinfo[tid] = iy * 23 + ix;
        float pe0 = pixemb[0] * LOG2E, pe1 = pixemb[1] * LOG2E;
        bool jh = tid >= 72, jxh = ix >= 6;
#pragma unroll
        for (int cls = 0; cls < 4; cls++) {
            bool m = (ul && (jh != (bool)(cls >> 1))) || (lr && (jxh != (bool)(cls & 1)));
            float base = m ? -1e30f : 0.f;
            MASKP[(cls * 2 + 0) * 144 + tid] = base + pe0;
            MASKP[(cls * 2 + 1) * 144 + tid] = base + ((pm != 0.f) ? pe1 : pe0);
        }
    }

    const int wr = tid >> 5;
    const int lane = tid & 31;
    const int g = lane >> 2, t = lane & 3;
    const int i0 = wr * 16 + g, i1 = i0 + 8;

    // Q fragments: packed bf16x2 direct from gmem (pre-split)
    uint32_t qh[2][4], ql[2][4];
#pragma unroll
    for (int kc = 0; kc < 2; kc++) {
        int o0 = tb2 + i0 * 32 + kc * 16 + 2 * t;
        int o1 = tb2 + i1 * 32 + kc * 16 + 2 * t;
        qh[kc][0] = *(const uint32_t*)(g_qh + o0);
        ql[kc][0] = *(const uint32_t*)(g_ql + o0);
        qh[kc][1] = *(const uint32_t*)(g_qh + o1);
        ql[kc][1] = *(const uint32_t*)(g_ql + o1);
        qh[kc][2] = *(const uint32_t*)(g_qh + o0 + 8);
        ql[kc][2] = *(const uint32_t*)(g_ql + o0 + 8);
        qh[kc][3] = *(const uint32_t*)(g_qh + o1 + 8);
        ql[kc][3] = *(const uint32_t*)(g_ql + o1 + 8);
    }

    asm volatile("cp.async.wait_group 0;" ::: "memory");
    __syncthreads();

    const int iy0 = i0 / 12, ix0 = i0 - iy0 * 12;
    const int iy1 = i1 / 12, ix1 = i1 - iy1 * 12;
    const float* pr0 = pose + (11 - iy0) * 23 + (11 - ix0);
    const float* pr1 = pose + (11 - iy1) * 23 + (11 - ix1);
    const int a0 = (pmv[i0] != 0.f) ? 1 : 0;
    const int a1 = (pmv[i1] != 0.f) ? 1 : 0;
    const float* mr0 = MASKP + (((i0 >= 72 ? 2 : 0) + (ix0 >= 6 ? 1 : 0)) * 2 + a0) * 144;
    const float* mr1 = MASKP + (((i1 >= 72 ? 2 : 0) + (ix1 >= 6 ? 1 : 0)) * 2 + a1) * 144;
    const float scale2 = 0.17677669529663689f * LOG2E;

    float oacc[4][4];
#pragma unroll
    for (int nt = 0; nt < 4; nt++)
#pragma unroll
        for (int c = 0; c < 4; c++) oacc[nt][c] = 0.f;
    float rs0 = 0.f, rs1 = 0.f;

#pragma unroll
    for (int jc = 0; jc < 9; jc++) {
        // ---- S chunk via non-trans ldmatrix on row-major K [n=j][k=d]
        float sc[2][4];
#pragma unroll
        for (int u = 0; u < 2; u++)
#pragma unroll
            for (int c = 0; c < 4; c++) sc[u][c] = 0.f;

        const int jr = jc * 16 + ((lane >> 4) & 1) * 8 + (lane & 7);
        const int dbl = ((lane >> 3) & 1) * 8;
#pragma unroll
        for (int kc = 0; kc < 2; kc++) {
            uint32_t bh[4], bl[4];
            uint32_t ah_ = smem_u32(Ksh + jr * VST + kc * 16 + dbl);
            uint32_t al_ = smem_u32(Ksl + jr * VST + kc * 16 + dbl);
            ldsmx4(bh[0], bh[1], bh[2], bh[3], ah_);
            ldsmx4(bl[0], bl[1], bl[2], bl[3], al_);
            mma_bf16(sc[0], qh[kc], bh[0], bh[1]);
            mma_bf16(sc[0], qh[kc], bl[0], bl[1]);
            mma_bf16(sc[0], ql[kc], bh[0], bh[1]);
            mma_bf16(sc[1], qh[kc], bh[2], bh[3]);
            mma_bf16(sc[1], qh[kc], bl[2], bl[3]);
            mma_bf16(sc[1], ql[kc], bh[2], bh[3]);
        }

        // ---- softmax chunk: p = ex2(sc*scale2 + MASKP[sel][j] + pose'[poff])
#pragma unroll
        for (int u = 0; u < 2; u++) {
#pragma unroll
            for (int fc = 0; fc < 2; fc++) {
                int j = jc * 16 + u * 8 + 2 * t + fc;
                int poff = jinfo[j];
                {
                    float p = ex2f(sc[u][fc] * scale2 + mr0[j] + pr0[poff]);
                    sc[u][fc] = p; rs0 += p;
                }
                {
                    float p = ex2f(sc[u][fc + 2] * scale2 + mr1[j] + pr1[poff]);
                    sc[u][fc + 2] = p; rs1 += p;
                }
            }
        }

        // ---- P -> fp16 split A fragments, accumulate P@V (2 fp16 mmas/ng)
        uint32_t ph[4], pl[4];
        {
            __half ha, la, hb, lb;
            split2h(sc[0][0], ha, la); split2h(sc[0][1], hb, lb);
            ph[0] = packh2(ha, hb); pl[0] = packh2(la, lb);
            split2h(sc[0][2], ha, la); split2h(sc[0][3], hb, lb);
            ph[1] = packh2(ha, hb); pl[1] = packh2(la, lb);
            split2h(sc[1][0], ha, la); split2h(sc[1][1], hb, lb);
            ph[2] = packh2(ha, hb); pl[2] = packh2(la, lb);
            split2h(sc[1][2], ha, la); split2h(sc[1][3], hb, lb);
            ph[3] = packh2(ha, hb); pl[3] = packh2(la, lb);
        }
#pragma unroll
        for (int ng = 0; ng < 2; ng++) {
            uint32_t bv[4];
            uint32_t av_ = smem_u32(Vsh + (jc * 16 + (lane & 15)) * VST +
                                    ng * 16 + (lane >> 4) * 8);
            ldsmx4t(bv[0], bv[1], bv[2], bv[3], av_);
            mma_f16(oacc[2 * ng],     ph, bv[0], bv[1]);
            mma_f16(oacc[2 * ng],     pl, bv[0], bv[1]);
            mma_f16(oacc[2 * ng + 1], ph, bv[2], bv[3]);
            mma_f16(oacc[2 * ng + 1], pl, bv[2], bv[3]);
        }
    }

    rs0 += __shfl_xor_sync(0xffffffff, rs0, 1);
    rs0 += __shfl_xor_sync(0xffffffff, rs0, 2);
    rs1 += __shfl_xor_sync(0xffffffff, rs1, 1);
    rs1 += __shfl_xor_sync(0xffffffff, rs1, 2);
    const float inv0 = 1.f / rs0, inv1 = 1.f / rs1;

    // write normalized output as fp16 hi for the out-proj GEMM
    const int orow0 = ((b * 64 + w) * 144 + i0) * 384 + h * 32;
    const int orow1 = ((b * 64 + w) * 144 + i1) * 384 + h * 32;
#pragma unroll
    for (int nt = 0; nt < 4; nt++) {
        int col = nt * 8 + 2 * t;
        *(uint32_t*)(g_atth + orow0 + col) =
            packh2(__float2half_rn(oacc[nt][0] * inv0),
                   __float2half_rn(oacc[nt][1] * inv0));
        *(uint32_t*)(g_atth + orow1 + col) =
            packh2(__float2half_rn(oacc[nt][2] * inv1),
                   __float2half_rn(oacc[nt][3] * inv1));
    }
}

// ---------------------------------------------------------------------------
// Kernel: output projection (single fp16 mma) + bias + roll(+6,+6) scatter
// ---------------------------------------------------------------------------
__global__ __launch_bounds__(256, 1) void out_gemm_mma(const float* __restrict__ bout,
                                                       float* __restrict__ Out) {
    GEMM_MAINLOOP(false, g_atth, g_atth, g_woh, 384)

#pragma unroll
    for (int mt = 0; mt < 2; mt++) {
#pragma unroll
        for (int rr = 0; rr < 2; rr++) {
            int r = m0 + wm + mt * 16 + (lane >> 2) + rr * 8;
            int b = r / 9216; int rem = r - b * 9216;
            int w = rem / 144; int i = rem - w * 144;
            int iy = i / 12, ix = i - iy * 12;
            int y = (w >> 3) * 12 + iy + 6; if (y >= 96) y -= 96;
            int x = (w & 7) * 12 + ix + 6;  if (x >= 96) x -= 96;
            float* orow = Out + ((b * 96 + y) * 96 + x) * 384;
#pragma unroll
            for (int nt = 0; nt < 8; nt++) {
                int c = n0 + wn + nt * 8 + (lane & 3) * 2;
                float2 bi = *(const float2*)(bout + c);
                float2 v = make_float2(acc[mt][nt][rr * 2] + bi.x,
                                       acc[mt][nt][rr * 2 + 1] + bi.y);
                *(float2*)(orow + c) = v;
            }
        }
    }
}

// ---------------------------------------------------------------------------
extern "C" void kernel_launch(void* const* d_in, const int* in_sizes, int n_in,
                              void* d_out, int out_size) {
    (void)in_sizes; (void)n_in; (void)out_size;
    const float* x      = (const float*)d_in[0];
    const int*   pixmap = (const int*)d_in[1];
    const float* wqkv   = (const float*)d_in[2];
    const float* posemb = (const float*)d_in[3];
    const float* pixemb = (const float*)d_in[4];
    const float* wout   = (const float*)d_in[5];
    const float* bout   = (const float*)d_in[6];
    float* out = (float*)d_out;

    cudaFuncSetAttribute(qkv_gemm_mma, cudaFuncAttributeMaxDynamicSharedMemorySize,
                         SMEM_QKV);
    cudaFuncSetAttribute(out_gemm_mma, cudaFuncAttributeMaxDynamicSharedMemorySize,
                         SMEM_OUT);

    prep_x<<<27648, 256>>>(x);
    prep_w<<<576, 256>>>(wqkv, wout);
    qkv_gemm_mma<<<dim3(QKV_N / 128, MROWS / 128), 256, SMEM_QKV>>>();
    attn_mma<<<dim3(NW * NHEADS, BB), 288>>>(pixmap, posemb, pixemb);
    out_gemm_mma<<<dim3(384 / 128, MROWS / 128), 256, SMEM_OUT>>>(bout, out);
}

// round 11
// speedup vs baseline: 3.4927x; 1.1289x over previous
#include <cuda_runtime.h>
#include <cuda_bf16.h>
#include <cuda_fp16.h>
#include <cstdint>

// Shapes
#define BB     8
#define NHEADS 12
#define HD     32
#define NW     64
#define WSQ    144
#define MROWS  73728        // BB*NW*WSQ
#define QKV_N  1152
#define LOG2E  1.4426950408889634f

// Scratch (allocation-free rule: __device__ globals)
__device__ __nv_bfloat16 g_qh[MROWS * 384];   // per-head [B,NW,H,144,32]
__device__ __nv_bfloat16 g_ql[MROWS * 384];
__device__ __nv_bfloat16 g_kh[MROWS * 384];   // per-head [B,NW,H,144,32]
__device__ __nv_bfloat16 g_kl[MROWS * 384];
__device__ __half        g_vh[MROWS * 384];   // per-head, fp16 hi only
__device__ __half g_xh[MROWS * 384];          // fp16 split-2 (A operand)
__device__ __half g_xl[MROWS * 384];
__device__ __half g_atth[MROWS * 384];        // fp16 hi only (out-proj A)
__device__ __half g_wqh[384 * QKV_N];         // fp16 hi-only (B operand)
__device__ __half g_woh[384 * 384];

// ---------------------------------------------------------------------------
// helpers
// ---------------------------------------------------------------------------
__device__ __forceinline__ uint32_t smem_u32(const void* p) {
    return (uint32_t)__cvta_generic_to_shared(p);
}
__device__ __forceinline__ void ldsmx4(uint32_t& r0, uint32_t& r1, uint32_t& r2,
                                       uint32_t& r3, uint32_t a) {
    asm volatile("ldmatrix.sync.aligned.m8n8.x4.shared.b16 {%0,%1,%2,%3}, [%4];"
                 : "=r"(r0), "=r"(r1), "=r"(r2), "=r"(r3) : "r"(a));
}
__device__ __forceinline__ void ldsmx4t(uint32_t& r0, uint32_t& r1, uint32_t& r2,
                                        uint32_t& r3, uint32_t a) {
    asm volatile("ldmatrix.sync.aligned.m8n8.x4.trans.shared.b16 {%0,%1,%2,%3}, [%4];"
                 : "=r"(r0), "=r"(r1), "=r"(r2), "=r"(r3) : "r"(a));
}
__device__ __forceinline__ void mma_f16(float* c, const uint32_t* a,
                                        uint32_t b0, uint32_t b1) {
    asm volatile(
        "mma.sync.aligned.m16n8k16.row.col.f32.f16.f16.f32 "
        "{%0,%1,%2,%3},{%4,%5,%6,%7},{%8,%9},{%0,%1,%2,%3};"
        : "+f"(c[0]), "+f"(c[1]), "+f"(c[2]), "+f"(c[3])
        : "r"(a[0]), "r"(a[1]), "r"(a[2]), "r"(a[3]), "r"(b0), "r"(b1));
}
__device__ __forceinline__ void mma_bf16(float* c, const uint32_t* a,
                                         uint32_t b0, uint32_t b1) {
    asm volatile(
        "mma.sync.aligned.m16n8k16.row.col.f32.bf16.bf16.f32 "
        "{%0,%1,%2,%3},{%4,%5,%6,%7},{%8,%9},{%0,%1,%2,%3};"
        : "+f"(c[0]), "+f"(c[1]), "+f"(c[2]), "+f"(c[3])
        : "r"(a[0]), "r"(a[1]), "r"(a[2]), "r"(a[3]), "r"(b0), "r"(b1));
}
__device__ __forceinline__ void split2(float f, __nv_bfloat16& h, __nv_bfloat16& l) {
    h = __float2bfloat16_rn(f);
    l = __float2bfloat16_rn(f - __bfloat162float(h));
}
__device__ __forceinline__ void split2h(float f, __half& h, __half& l) {
    h = __float2half_rn(f);
    l = __float2half_rn(f - __half2float(h));
}
__device__ __forceinline__ uint32_t packbf2(__nv_bfloat16 a, __nv_bfloat16 b) {
    __nv_bfloat162 v(a, b);
    return *(uint32_t*)&v;
}
__device__ __forceinline__ uint32_t packh2(__half a, __half b) {
    __half2 v = __halves2half2(a, b);
    return *(uint32_t*)&v;
}
__device__ __forceinline__ void cpasync16(void* s, const void* g) {
    asm volatile("cp.async.cg.shared.global [%0], [%1], 16;"
                 :: "r"(smem_u32(s)), "l"(g));
}
__device__ __forceinline__ float ex2f(float x) {
    float r;
    asm("ex2.approx.f32 %0, %1;" : "=f"(r) : "f"(x));
    return r;
}

#define AST  40      // A smem row stride (fp16 elems): 80 B -> conflict-free
#define BST  136     // B smem row stride: 272 B -> conflict-free
#define A_STAGE 5120 // 128*AST
#define B_STAGE 4352 // 32*BST
#define NST  4
#define SMEM_QK  ((2 * NST * A_STAGE + NST * B_STAGE) * 2)   // 116736
#define SMEM_1   ((NST * A_STAGE + NST * B_STAGE) * 2)       // 75776

// ---------------------------------------------------------------------------
// Prep kernels: roll-gather + fp32 -> fp16 split
// ---------------------------------------------------------------------------
__global__ __launch_bounds__(256) void prep_x(const float* __restrict__ X) {
    const int id = blockIdx.x * 256 + threadIdx.x;   // float4 id
    const int r = id / 96, t = id - r * 96;
    int b = r / 9216; int rem = r - b * 9216;
    int w = rem / 144; int i = rem - w * 144;
    int y = (w >> 3) * 12 + i / 12 + 6; if (y >= 96) y -= 96;
    int x = (w & 7) * 12 + i % 12 + 6;  if (x >= 96) x -= 96;
    float4 v = *((const float4*)(X + ((b * 96 + y) * 96 + x) * 384) + t);
    __half hx, hy, hz, hw, lx, ly, lz, lw;
    split2h(v.x, hx, lx); split2h(v.y, hy, ly);
    split2h(v.z, hz, lz); split2h(v.w, hw, lw);
    int o = r * 384 + t * 4;
    *(uint32_t*)(g_xh + o)     = packh2(hx, hy);
    *(uint32_t*)(g_xh + o + 2) = packh2(hz, hw);
    *(uint32_t*)(g_xl + o)     = packh2(lx, ly);
    *(uint32_t*)(g_xl + o + 2) = packh2(lz, lw);
}

__global__ __launch_bounds__(256) void prep_w(const float* __restrict__ wqkv,
                                              const float* __restrict__ wout) {
    const int id = blockIdx.x * 256 + threadIdx.x;  // float4 index
    float4 v;
    __half* oh; int o;
    if (id < 110592) {                        // 384*1152/4
        v = ((const float4*)wqkv)[id];
        oh = g_wqh; o = id * 4;
    } else {
        int id2 = id - 110592;                // < 36864
        v = ((const float4*)wout)[id2];
        oh = g_woh; o = id2 * 4;
    }
    *(uint32_t*)(oh + o)     = packh2(__float2half_rn(v.x), __float2half_rn(v.y));
    *(uint32_t*)(oh + o + 2) = packh2(__float2half_rn(v.z), __float2half_rn(v.w));
}

// ---------------------------------------------------------------------------
// GEMM: 128x128 tile, BK=32, 256 thr, 8 warps (4m x 2n, 32x64 warp tile).
// UAL=true: C += Ah*Bh + Al*Bh (2 mmas). UAL=false: C += Ah*Bh (1 mma).
// 4-stage cp.async pipeline.
// ---------------------------------------------------------------------------
template<bool UAL>
__device__ __forceinline__ void load_stage(
    const __half* __restrict__ Agh, const __half* __restrict__ Agl,
    const __half* __restrict__ Bgh,
    __half* Ah, __half* Al, __half* Bh,
    int m0, int n0, int ldb, int k0, int st, int tid)
{
    __half* ash = Ah + st * A_STAGE;
    __half* bsh = Bh + st * B_STAGE;
#pragma unroll
    for (int q = 0; q < 2; q++) {
        int c = tid * 2 + q;
        int row = c >> 2, ch = (c & 3) * 8;                 // A: 128 x 32
        int go = (m0 + row) * 384 + k0 + ch;
        int so = row * AST + ch;
        cpasync16(ash + so, Agh + go);
        if (UAL) cpasync16(Al + st * A_STAGE + so, Agl + go);
    }
#pragma unroll
    for (int q = 0; q < 2; q++) {
        int c = tid * 2 + q;
        int row = c >> 4, ch = (c & 15) * 8;                // B: 32 x 128
        int go = (k0 + row) * ldb + n0 + ch;
        cpasync16(bsh + row * BST + ch, Bgh + go);
    }
}

template<bool UAL>
__device__ __forceinline__ void compute_stage(
    const __half* Ah, const __half* Al, const __half* Bh,
    int wm, int wn, int lane, float acc[2][8][4])
{
#pragma unroll
    for (int ks = 0; ks < 2; ks++) {
        const int kk = ks * 16;
        uint32_t ah[2][4], al[2][4], bh[4][4];
        const int arow = wm + (lane & 15);
        const int acol = kk + (lane >> 4) * 8;
#pragma unroll
        for (int mt = 0; mt < 2; mt++) {
            ldsmx4(ah[mt][0], ah[mt][1], ah[mt][2], ah[mt][3],
                   smem_u32(Ah + (arow + mt * 16) * AST + acol));
            if (UAL)
                ldsmx4(al[mt][0], al[mt][1], al[mt][2], al[mt][3],
                       smem_u32(Al + (arow + mt * 16) * AST + acol));
        }
        const int bk = kk + (lane & 15);
        const int bnb = wn + (lane >> 4) * 8;
#pragma unroll
        for (int g = 0; g < 4; g++) {
            ldsmx4t(bh[g][0], bh[g][1], bh[g][2], bh[g][3],
                    smem_u32(Bh + bk * BST + bnb + g * 16));
        }
#pragma unroll
        for (int mt = 0; mt < 2; mt++)
#pragma unroll
            for (int g = 0; g < 4; g++)
#pragma unroll
                for (int hf = 0; hf < 2; hf++) {
                    float* c = acc[mt][2 * g + hf];
                    mma_f16(c, ah[mt], bh[g][2 * hf], bh[g][2 * hf + 1]);
                    if (UAL) mma_f16(c, al[mt], bh[g][2 * hf], bh[g][2 * hf + 1]);
                }
    }
}

#define GEMM_MAINLOOP(UAL, AGH, AGL, BGH, LDB, NOFS)                             \
    extern __shared__ __align__(16) __half smem[];                               \
    __half* Ah = smem;                                                           \
    __half* Al = smem + NST * A_STAGE;                                           \
    __half* Bh = smem + (UAL ? 2 : 1) * NST * A_STAGE;                           \
    const int tid = threadIdx.x;                                                 \
    const int m0 = blockIdx.y * 128;                                             \
    const int n0 = (NOFS) + blockIdx.x * 128;                                    \
    const int wid = tid >> 5, lane = tid & 31;                                   \
    const int wm = (wid >> 1) * 32;                                              \
    const int wn = (wid & 1) * 64;                                               \
    float acc[2][8][4];                                                          \
    _Pragma("unroll") for (int a_ = 0; a_ < 2; a_++)                             \
    _Pragma("unroll") for (int b_ = 0; b_ < 8; b_++)                             \
    _Pragma("unroll") for (int c_ = 0; c_ < 4; c_++) acc[a_][b_][c_] = 0.f;      \
    _Pragma("unroll") for (int s_ = 0; s_ < NST - 1; s_++) {                     \
        load_stage<UAL>(AGH, AGL, BGH, Ah, Al, Bh, m0, n0, LDB, s_ * 32, s_, tid);\
        asm volatile("cp.async.commit_group;" ::: "memory");                     \
    }                                                                            \
    for (int it = 0; it < 12; it++) {                                            \
        asm volatile("cp.async.wait_group %0;" :: "n"(NST - 2) : "memory");      \
        __syncthreads();                                                         \
        if (it < 12 - (NST - 1)) {                                               \
            load_stage<UAL>(AGH, AGL, BGH, Ah, Al, Bh, m0, n0, LDB,              \
                            (it + NST - 1) * 32, (it + NST - 1) & (NST - 1), tid);\
        }                                                                        \
        asm volatile("cp.async.commit_group;" ::: "memory");                     \
        const int st = it & (NST - 1);                                           \
        compute_stage<UAL>(Ah + st * A_STAGE, Al + st * A_STAGE,                 \
                           Bh + st * B_STAGE, wm, wn, lane, acc);                \
    }

// ---------------------------------------------------------------------------
// Kernel: Q,K GEMM (2-mma split) -> bf16 hi/lo row-major per-head.
// ---------------------------------------------------------------------------
__global__ __launch_bounds__(256, 1) void qk_gemm_mma() {
    GEMM_MAINLOOP(true, g_xh, g_xl, g_wqh, QKV_N, 0)

    const int part = n0 / 384;                // 0=Q, 1=K
    const int cbase = n0 - part * 384;

#pragma unroll
    for (int mt = 0; mt < 2; mt++) {
#pragma unroll
        for (int rr = 0; rr < 2; rr++) {
            int r = m0 + wm + mt * 16 + (lane >> 2) + rr * 8;
            int b = r / 9216; int rem = r - b * 9216;
            int w = rem / 144; int i = rem - w * 144;
            int bw12 = (b * 64 + w) * 12;
#pragma unroll
            for (int nt = 0; nt < 8; nt++) {
                int c = cbase + wn + nt * 8 + (lane & 3) * 2;
                int h = c >> 5, d = c & 31;
                int tq = ((bw12 + h) * 144 + i) * 32 + d;
                float f0 = acc[mt][nt][rr * 2], f1 = acc[mt][nt][rr * 2 + 1];
                __nv_bfloat16 h0, l0, h1, l1;
                split2(f0, h0, l0); split2(f1, h1, l1);
                __nv_bfloat16* oh = (part == 0) ? g_qh : g_kh;
                __nv_bfloat16* ol = (part == 0) ? g_ql : g_kl;
                *(uint32_t*)(oh + tq) = packbf2(h0, h1);
                *(uint32_t*)(ol + tq) = packbf2(l0, l1);
            }
        }
    }
}

// ---------------------------------------------------------------------------
// Kernel: V GEMM (1 mma, A-hi only) -> fp16 hi row-major per-head.
// ---------------------------------------------------------------------------
__global__ __launch_bounds__(256, 1) void v_gemm_mma() {
    GEMM_MAINLOOP(false, g_xh, g_xh, g_wqh, QKV_N, 768)

    const int cbase = n0 - 768;

#pragma unroll
    for (int mt = 0; mt < 2; mt++) {
#pragma unroll
        for (int rr = 0; rr < 2; rr++) {
            int r = m0 + wm + mt * 16 + (lane >> 2) + rr * 8;
            int b = r / 9216; int rem = r - b * 9216;
            int w = rem / 144; int i = rem - w * 144;
            int bw12 = (b * 64 + w) * 12;
#pragma unroll
            for (int nt = 0; nt < 8; nt++) {
                int c = cbase + wn + nt * 8 + (lane & 3) * 2;
                int h = c >> 5, d = c & 31;
                int tq = ((bw12 + h) * 144 + i) * 32 + d;
                *(uint32_t*)(g_vh + tq) =
                    packh2(__float2half_rn(acc[mt][nt][rr * 2]),
                           __float2half_rn(acc[mt][nt][rr * 2 + 1]));
            }
        }
    }
}

// ---------------------------------------------------------------------------
// Kernel: flash-chunked tensor-core attention.
// S: bf16 split-2 (3 mmas), K row-major via non-trans ldmatrix.
// PV: 1 fp16 mma (P hi, V hi). Softmax: single EX2 via folded tables.
// ---------------------------------------------------------------------------
#define VST  40

__global__ __launch_bounds__(288, 2) void attn_mma(const int* __restrict__ pixmap,
                                                   const float* __restrict__ posemb,
                                                   const float* __restrict__ pixemb) {
    __shared__ __align__(16) __nv_bfloat16 Ksh[144 * VST], Ksl[144 * VST];
    __shared__ __align__(16) __half Vsh[144 * VST];
    __shared__ float pose[529];        // pre-scaled by log2e
    __shared__ float pmv[WSQ];
    __shared__ float MASKP[8 * WSQ];   // [(cls*2+act)*144+j], log2e-domain
    __shared__ int   jinfo[WSQ];

    const int tid = threadIdx.x;
    const int b = blockIdx.y;
    const int w = blockIdx.x / 12;
    const int h = blockIdx.x - w * 12;
    const int tb2 = ((b * 64 + w) * 12 + h) * 4608;
    const bool ul = (w >> 3) == 7;
    const bool lr = (w & 7) == 7;

#pragma unroll
    for (int q = 0; q < 2; q++) {
        int cix = tid + q * 288;                 // < 576
        int j = cix >> 2, ch = (cix & 3) * 8;
        cpasync16(Ksh + j * VST + ch, g_kh + tb2 + j * 32 + ch);
        cpasync16(Ksl + j * VST + ch, g_kl + tb2 + j * 32 + ch);
        cpasync16(Vsh + j * VST + ch, g_vh + tb2 + j * 32 + ch);
    }
    asm volatile("cp.async.commit_group;" ::: "memory");

    for (int f = tid; f < 529; f += 288) pose[f] = posemb[f] * LOG2E;
    if (tid < 144) {
        int wy = w >> 3, wx = w & 7;
        int iy = tid / 12, ix = tid - iy * 12;
        float pm = (float)pixmap[(b * 96 + wy * 12 + iy) * 96 + wx * 12 + ix];
        pmv[tid] = pm;
        jinfo[tid] = iy * 23 + ix;
        float pe0 = pixemb[0] * LOG2E, pe1 = pixemb[1] * LOG2E;
        bool jh = tid >= 72, jxh = ix >= 6;
#pragma unroll
        for (int cls = 0; cls < 4; cls++) {
            bool m = (ul && (jh != (bool)(cls >> 1))) || (lr && (jxh != (bool)(cls & 1)));
            float base = m ? -1e30f : 0.f;
            MASKP[(cls * 2 + 0) * 144 + tid] = base + pe0;
            MASKP[(cls * 2 + 1) * 144 + tid] = base + ((pm != 0.f) ? pe1 : pe0);
        }
    }

    const int wr = tid >> 5;
    const int lane = tid & 31;
    const int g = lane >> 2, t = lane & 3;
    const int i0 = wr * 16 + g, i1 = i0 + 8;

    // Q fragments: packed bf16x2 direct from gmem (pre-split)
    uint32_t qh[2][4], ql[2][4];
#pragma unroll
    for (int kc = 0; kc < 2; kc++) {
        int o0 = tb2 + i0 * 32 + kc * 16 + 2 * t;
        int o1 = tb2 + i1 * 32 + kc * 16 + 2 * t;
        qh[kc][0] = *(const uint32_t*)(g_qh + o0);
        ql[kc][0] = *(const uint32_t*)(g_ql + o0);
        qh[kc][1] = *(const uint32_t*)(g_qh + o1);
        ql[kc][1] = *(const uint32_t*)(g_ql + o1);
        qh[kc][2] = *(const uint32_t*)(g_qh + o0 + 8);
        ql[kc][2] = *(const uint32_t*)(g_ql + o0 + 8);
        qh[kc][3] = *(const uint32_t*)(g_qh + o1 + 8);
        ql[kc][3] = *(const uint32_t*)(g_ql + o1 + 8);
    }

    asm volatile("cp.async.wait_group 0;" ::: "memory");
    __syncthreads();

    const int iy0 = i0 / 12, ix0 = i0 - iy0 * 12;
    const int iy1 = i1 / 12, ix1 = i1 - iy1 * 12;
    const float* pr0 = pose + (11 - iy0) * 23 + (11 - ix0);
    const float* pr1 = pose + (11 - iy1) * 23 + (11 - ix1);
    const int a0 = (pmv[i0] != 0.f) ? 1 : 0;
    const int a1 = (pmv[i1] != 0.f) ? 1 : 0;
    const float* mr0 = MASKP + (((i0 >= 72 ? 2 : 0) + (ix0 >= 6 ? 1 : 0)) * 2 + a0) * 144;
    const float* mr1 = MASKP + (((i1 >= 72 ? 2 : 0) + (ix1 >= 6 ? 1 : 0)) * 2 + a1) * 144;
    const float scale2 = 0.17677669529663689f * LOG2E;

    float oacc[4][4];
#pragma unroll
    for (int nt = 0; nt < 4; nt++)
#pragma unroll
        for (int c = 0; c < 4; c++) oacc[nt][c] = 0.f;
    float rs0 = 0.f, rs1 = 0.f;

#pragma unroll
    for (int jc = 0; jc < 9; jc++) {
        // ---- S chunk via non-trans ldmatrix on row-major K [n=j][k=d]
        float sc[2][4];
#pragma unroll
        for (int u = 0; u < 2; u++)
#pragma unroll
            for (int c = 0; c < 4; c++) sc[u][c] = 0.f;

        const int jr = jc * 16 + ((lane >> 4) & 1) * 8 + (lane & 7);
        const int dbl = ((lane >> 3) & 1) * 8;
#pragma unroll
        for (int kc = 0; kc < 2; kc++) {
            uint32_t bh[4], bl[4];
            uint32_t ah_ = smem_u32(Ksh + jr * VST + kc * 16 + dbl);
            uint32_t al_ = smem_u32(Ksl + jr * VST + kc * 16 + dbl);
            ldsmx4(bh[0], bh[1], bh[2], bh[3], ah_);
            ldsmx4(bl[0], bl[1], bl[2], bl[3], al_);
            mma_bf16(sc[0], qh[kc], bh[0], bh[1]);
            mma_bf16(sc[0], qh[kc], bl[0], bl[1]);
            mma_bf16(sc[0], ql[kc], bh[0], bh[1]);
            mma_bf16(sc[1], qh[kc], bh[2], bh[3]);
            mma_bf16(sc[1], qh[kc], bl[2], bl[3]);
            mma_bf16(sc[1], ql[kc], bh[2], bh[3]);
        }

        // ---- softmax chunk: p = ex2(sc*scale2 + MASKP[sel][j] + pose'[poff])
#pragma unroll
        for (int u = 0; u < 2; u++) {
#pragma unroll
            for (int fc = 0; fc < 2; fc++) {
                int j = jc * 16 + u * 8 + 2 * t + fc;
                int poff = jinfo[j];
                {
                    float p = ex2f(sc[u][fc] * scale2 + mr0[j] + pr0[poff]);
                    sc[u][fc] = p; rs0 += p;
                }
                {
                    float p = ex2f(sc[u][fc + 2] * scale2 + mr1[j] + pr1[poff]);
                    sc[u][fc + 2] = p; rs1 += p;
                }
            }
        }

        // ---- P -> fp16 hi A fragments, accumulate P@V (1 fp16 mma/ng)
        uint32_t ph[4];
        ph[0] = packh2(__float2half_rn(sc[0][0]), __float2half_rn(sc[0][1]));
        ph[1] = packh2(__float2half_rn(sc[0][2]), __float2half_rn(sc[0][3]));
        ph[2] = packh2(__float2half_rn(sc[1][0]), __float2half_rn(sc[1][1]));
        ph[3] = packh2(__float2half_rn(sc[1][2]), __float2half_rn(sc[1][3]));
#pragma unroll
        for (int ng = 0; ng < 2; ng++) {
            uint32_t bv[4];
            uint32_t av_ = smem_u32(Vsh + (jc * 16 + (lane & 15)) * VST +
                                    ng * 16 + (lane >> 4) * 8);
            ldsmx4t(bv[0], bv[1], bv[2], bv[3], av_);
            mma_f16(oacc[2 * ng],     ph, bv[0], bv[1]);
            mma_f16(oacc[2 * ng + 1], ph, bv[2], bv[3]);
        }
    }

    rs0 += __shfl_xor_sync(0xffffffff, rs0, 1);
    rs0 += __shfl_xor_sync(0xffffffff, rs0, 2);
    rs1 += __shfl_xor_sync(0xffffffff, rs1, 1);
    rs1 += __shfl_xor_sync(0xffffffff, rs1, 2);
    const float inv0 = 1.f / rs0, inv1 = 1.f / rs1;

    // write normalized output as fp16 hi for the out-proj GEMM
    const int orow0 = ((b * 64 + w) * 144 + i0) * 384 + h * 32;
    const int orow1 = ((b * 64 + w) * 144 + i1) * 384 + h * 32;
#pragma unroll
    for (int nt = 0; nt < 4; nt++) {
        int col = nt * 8 + 2 * t;
        *(uint32_t*)(g_atth + orow0 + col) =
            packh2(__float2half_rn(oacc[nt][0] * inv0),
                   __float2half_rn(oacc[nt][1] * inv0));
        *(uint32_t*)(g_atth + orow1 + col) =
            packh2(__float2half_rn(oacc[nt][2] * inv1),
                   __float2half_rn(oacc[nt][3] * inv1));
    }
}

// ---------------------------------------------------------------------------
// Kernel: output projection (single fp16 mma) + bias + roll(+6,+6) scatter
// ---------------------------------------------------------------------------
__global__ __launch_bounds__(256, 2) void out_gemm_mma(const float* __restrict__ bout,
                                                       float* __restrict__ Out) {
    GEMM_MAINLOOP(false, g_atth, g_atth, g_woh, 384, 0)

#pragma unroll
    for (int mt = 0; mt < 2; mt++) {
#pragma unroll
        for (int rr = 0; rr < 2; rr++) {
            int r = m0 + wm + mt * 16 + (lane >> 2) + rr * 8;
            int b = r / 9216; int rem = r - b * 9216;
            int w = rem / 144; int i = rem - w * 144;
            int iy = i / 12, ix = i - iy * 12;
            int y = (w >> 3) * 12 + iy + 6; if (y >= 96) y -= 96;
            int x = (w & 7) * 12 + ix + 6;  if (x >= 96) x -= 96;
            float* orow = Out + ((b * 96 + y) * 96 + x) * 384;
#pragma unroll
            for (int nt = 0; nt < 8; nt++) {
                int c = n0 + wn + nt * 8 + (lane & 3) * 2;
                float2 bi = *(const float2*)(bout + c);
                float2 v = make_float2(acc[mt][nt][rr * 2] + bi.x,
                                       acc[mt][nt][rr * 2 + 1] + bi.y);
                *(float2*)(orow + c) = v;
            }
        }
    }
}

// ---------------------------------------------------------------------------
extern "C" void kernel_launch(void* const* d_in, const int* in_sizes, int n_in,
                              void* d_out, int out_size) {
    (void)in_sizes; (void)n_in; (void)out_size;
    const float* x      = (const float*)d_in[0];
    const int*   pixmap = (const int*)d_in[1];
    const float* wqkv   = (const float*)d_in[2];
    const float* posemb = (const float*)d_in[3];
    const float* pixemb = (const float*)d_in[4];
    const float* wout   = (const float*)d_in[5];
    const float* bout   = (const float*)d_in[6];
    float* out = (float*)d_out;

    cudaFuncSetAttribute(qk_gemm_mma, cudaFuncAttributeMaxDynamicSharedMemorySize,
                         SMEM_QK);
    cudaFuncSetAttribute(v_gemm_mma, cudaFuncAttributeMaxDynamicSharedMemorySize,
                         SMEM_1);
    cudaFuncSetAttribute(out_gemm_mma, cudaFuncAttributeMaxDynamicSharedMemorySize,
                         SMEM_1);

    prep_x<<<27648, 256>>>(x);
    prep_w<<<576, 256>>>(wqkv, wout);
    qk_gemm_mma<<<dim3(6, MROWS / 128), 256, SMEM_QK>>>();
    v_gemm_mma<<<dim3(3, MROWS / 128), 256, SMEM_1>>>();
    attn_mma<<<dim3(NW * NHEADS, BB), 288>>>(pixmap, posemb, pixemb);
    out_gemm_mma<<<dim3(384 / 128, MROWS / 128), 256, SMEM_1>>>(bout, out);
}

// round 12
// speedup vs baseline: 5.2745x; 1.5101x over previous
#include <cuda_runtime.h>
#include <cuda_fp16.h>
#include <cstdint>

// Shapes
#define BB     8
#define NHEADS 12
#define HD     32
#define NW     64
#define WSQ    144
#define MROWS  73728        // BB*NW*WSQ
#define QKV_N  1152
#define LOG2E  1.4426950408889634f

// Scratch (allocation-free rule: __device__ globals)
__device__ __half g_qh[MROWS * 384];   // per-head [B,NW,H,144,32] fp16
__device__ __half g_kh[MROWS * 384];   // per-head [B,NW,H,144,32] fp16
__device__ __half g_vh[MROWS * 384];   // per-head [B,NW,H,144,32] fp16
__device__ __half g_xh[MROWS * 384];   // rolled/windowed x, fp16
__device__ __half g_atth[MROWS * 384]; // attention out, fp16
__device__ __half g_wqh[384 * QKV_N];  // weights fp16
__device__ __half g_woh[384 * 384];

// ---------------------------------------------------------------------------
// helpers
// ---------------------------------------------------------------------------
__device__ __forceinline__ uint32_t smem_u32(const void* p) {
    return (uint32_t)__cvta_generic_to_shared(p);
}
__device__ __forceinline__ void ldsmx4(uint32_t& r0, uint32_t& r1, uint32_t& r2,
                                       uint32_t& r3, uint32_t a) {
    asm volatile("ldmatrix.sync.aligned.m8n8.x4.shared.b16 {%0,%1,%2,%3}, [%4];"
                 : "=r"(r0), "=r"(r1), "=r"(r2), "=r"(r3) : "r"(a));
}
__device__ __forceinline__ void ldsmx4t(uint32_t& r0, uint32_t& r1, uint32_t& r2,
                                        uint32_t& r3, uint32_t a) {
    asm volatile("ldmatrix.sync.aligned.m8n8.x4.trans.shared.b16 {%0,%1,%2,%3}, [%4];"
                 : "=r"(r0), "=r"(r1), "=r"(r2), "=r"(r3) : "r"(a));
}
__device__ __forceinline__ void mma_f16(float* c, const uint32_t* a,
                                        uint32_t b0, uint32_t b1) {
    asm volatile(
        "mma.sync.aligned.m16n8k16.row.col.f32.f16.f16.f32 "
        "{%0,%1,%2,%3},{%4,%5,%6,%7},{%8,%9},{%0,%1,%2,%3};"
        : "+f"(c[0]), "+f"(c[1]), "+f"(c[2]), "+f"(c[3])
        : "r"(a[0]), "r"(a[1]), "r"(a[2]), "r"(a[3]), "r"(b0), "r"(b1));
}
__device__ __forceinline__ uint32_t packh2(__half a, __half b) {
    __half2 v = __halves2half2(a, b);
    return *(uint32_t*)&v;
}
__device__ __forceinline__ void cpasync16(void* s, const void* g) {
    asm volatile("cp.async.cg.shared.global [%0], [%1], 16;"
                 :: "r"(smem_u32(s)), "l"(g));
}
__device__ __forceinline__ float ex2f(float x) {
    float r;
    asm("ex2.approx.f32 %0, %1;" : "=f"(r) : "f"(x));
    return r;
}

#define AST  40      // A smem row stride (fp16 elems): 80 B -> conflict-free
#define BST  136     // B smem row stride: 272 B -> conflict-free
#define A_STAGE 5120 // 128*AST
#define B_STAGE 4352 // 32*BST
#define NST  4
#define SMEM_1   ((NST * A_STAGE + NST * B_STAGE) * 2)       // 75776

// ---------------------------------------------------------------------------
// Prep kernels: roll-gather + fp32 -> fp16
// ---------------------------------------------------------------------------
__global__ __launch_bounds__(256) void prep_x(const float* __restrict__ X) {
    const int id = blockIdx.x * 256 + threadIdx.x;   // float4 id
    const int r = id / 96, t = id - r * 96;
    int b = r / 9216; int rem = r - b * 9216;
    int w = rem / 144; int i = rem - w * 144;
    int y = (w >> 3) * 12 + i / 12 + 6; if (y >= 96) y -= 96;
    int x = (w & 7) * 12 + i % 12 + 6;  if (x >= 96) x -= 96;
    float4 v = *((const float4*)(X + ((b * 96 + y) * 96 + x) * 384) + t);
    int o = r * 384 + t * 4;
    *(uint32_t*)(g_xh + o)     = packh2(__float2half_rn(v.x), __float2half_rn(v.y));
    *(uint32_t*)(g_xh + o + 2) = packh2(__float2half_rn(v.z), __float2half_rn(v.w));
}

__global__ __launch_bounds__(256) void prep_w(const float* __restrict__ wqkv,
                                              const float* __restrict__ wout) {
    const int id = blockIdx.x * 256 + threadIdx.x;  // float4 index
    float4 v;
    __half* oh; int o;
    if (id < 110592) {                        // 384*1152/4
        v = ((const float4*)wqkv)[id];
        oh = g_wqh; o = id * 4;
    } else {
        int id2 = id - 110592;                // < 36864
        v = ((const float4*)wout)[id2];
        oh = g_woh; o = id2 * 4;
    }
    *(uint32_t*)(oh + o)     = packh2(__float2half_rn(v.x), __float2half_rn(v.y));
    *(uint32_t*)(oh + o + 2) = packh2(__float2half_rn(v.z), __float2half_rn(v.w));
}

// ---------------------------------------------------------------------------
// GEMM: 128x128 tile, BK=32, 256 thr, 8 warps (4m x 2n, 32x64 warp tile).
// Single fp16 mma: C += A*B. 4-stage cp.async pipeline.
// ---------------------------------------------------------------------------
__device__ __forceinline__ void load_stage(
    const __half* __restrict__ Ag, const __half* __restrict__ Bg,
    __half* Ah, __half* Bh,
    int m0, int n0, int ldb, int k0, int st, int tid)
{
    __half* ash = Ah + st * A_STAGE;
    __half* bsh = Bh + st * B_STAGE;
#pragma unroll
    for (int q = 0; q < 2; q++) {
        int c = tid * 2 + q;
        int row = c >> 2, ch = (c & 3) * 8;                 // A: 128 x 32
        cpasync16(ash + row * AST + ch, Ag + (m0 + row) * 384 + k0 + ch);
    }
#pragma unroll
    for (int q = 0; q < 2; q++) {
        int c = tid * 2 + q;
        int row = c >> 4, ch = (c & 15) * 8;                // B: 32 x 128
        cpasync16(bsh + row * BST + ch, Bg + (k0 + row) * ldb + n0 + ch);
    }
}

__device__ __forceinline__ void compute_stage(
    const __half* Ah, const __half* Bh,
    int wm, int wn, int lane, float acc[2][8][4])
{
#pragma unroll
    for (int ks = 0; ks < 2; ks++) {
        const int kk = ks * 16;
        uint32_t ah[2][4], bh[4][4];
        const int arow = wm + (lane & 15);
        const int acol = kk + (lane >> 4) * 8;
#pragma unroll
        for (int mt = 0; mt < 2; mt++) {
            ldsmx4(ah[mt][0], ah[mt][1], ah[mt][2], ah[mt][3],
                   smem_u32(Ah + (arow + mt * 16) * AST + acol));
        }
        const int bk = kk + (lane & 15);
        const int bnb = wn + (lane >> 4) * 8;
#pragma unroll
        for (int g = 0; g < 4; g++) {
            ldsmx4t(bh[g][0], bh[g][1], bh[g][2], bh[g][3],
                    smem_u32(Bh + bk * BST + bnb + g * 16));
        }
#pragma unroll
        for (int mt = 0; mt < 2; mt++)
#pragma unroll
            for (int g = 0; g < 4; g++)
#pragma unroll
                for (int hf = 0; hf < 2; hf++) {
                    mma_f16(acc[mt][2 * g + hf], ah[mt],
                            bh[g][2 * hf], bh[g][2 * hf + 1]);
                }
    }
}

#define GEMM_MAINLOOP(AG, BG, LDB)                                               \
    extern __shared__ __align__(16) __half smem[];                               \
    __half* Ah = smem;                                                           \
    __half* Bh = smem + NST * A_STAGE;                                           \
    const int tid = threadIdx.x;                                                 \
    const int m0 = blockIdx.y * 128;                                             \
    const int n0 = blockIdx.x * 128;                                             \
    const int wid = tid >> 5, lane = tid & 31;                                   \
    const int wm = (wid >> 1) * 32;                                              \
    const int wn = (wid & 1) * 64;                                               \
    float acc[2][8][4];                                                          \
    _Pragma("unroll") for (int a_ = 0; a_ < 2; a_++)                             \
    _Pragma("unroll") for (int b_ = 0; b_ < 8; b_++)                             \
    _Pragma("unroll") for (int c_ = 0; c_ < 4; c_++) acc[a_][b_][c_] = 0.f;      \
    _Pragma("unroll") for (int s_ = 0; s_ < NST - 1; s_++) {                     \
        load_stage(AG, BG, Ah, Bh, m0, n0, LDB, s_ * 32, s_, tid);               \
        asm volatile("cp.async.commit_group;" ::: "memory");                     \
    }                                                                            \
    for (int it = 0; it < 12; it++) {                                            \
        asm volatile("cp.async.wait_group %0;" :: "n"(NST - 2) : "memory");      \
        __syncthreads();                                                         \
        if (it < 12 - (NST - 1)) {                                               \
            load_stage(AG, BG, Ah, Bh, m0, n0, LDB,                              \
                       (it + NST - 1) * 32, (it + NST - 1) & (NST - 1), tid);    \
        }                                                                        \
        asm volatile("cp.async.commit_group;" ::: "memory");                     \
        const int st = it & (NST - 1);                                           \
        compute_stage(Ah + st * A_STAGE, Bh + st * B_STAGE, wm, wn, lane, acc);  \
    }

// ---------------------------------------------------------------------------
// Kernel: QKV GEMM (1 fp16 mma) -> Q,K,V fp16 row-major per-head.
// ---------------------------------------------------------------------------
__global__ __launch_bounds__(256, 2) void qkv_gemm_mma() {
    GEMM_MAINLOOP(g_xh, g_wqh, QKV_N)

    const int part = n0 / 384;                // 0=Q, 1=K, 2=V
    const int cbase = n0 - part * 384;
    __half* outp = (part == 0) ? g_qh : (part == 1 ? g_kh : g_vh);

#pragma unroll
    for (int mt = 0; mt < 2; mt++) {
#pragma unroll
        for (int rr = 0; rr < 2; rr++) {
            int r = m0 + wm + mt * 16 + (lane >> 2) + rr * 8;
            int b = r / 9216; int rem = r - b * 9216;
            int w = rem / 144; int i = rem - w * 144;
            int bw12 = (b * 64 + w) * 12;
#pragma unroll
            for (int nt = 0; nt < 8; nt++) {
                int c = cbase + wn + nt * 8 + (lane & 3) * 2;
                int h = c >> 5, d = c & 31;
                int tq = ((bw12 + h) * 144 + i) * 32 + d;
                *(uint32_t*)(outp + tq) =
                    packh2(__float2half_rn(acc[mt][nt][rr * 2]),
                           __float2half_rn(acc[mt][nt][rr * 2 + 1]));
            }
        }
    }
}

// ---------------------------------------------------------------------------
// Kernel: flash-chunked tensor-core attention, all-fp16.
// S: 1 fp16 mma per n-half (q-hi . k-hi); K row-major via non-trans ldmatrix.
// PV: 1 fp16 mma. Softmax: single EX2 via folded tables.
// ---------------------------------------------------------------------------
#define VST  40

__global__ __launch_bounds__(288, 2) void attn_mma(const int* __restrict__ pixmap,
                                                   const float* __restrict__ posemb,
                                                   const float* __restrict__ pixemb) {
    __shared__ __align__(16) __half Ksh[144 * VST];
    __shared__ __align__(16) __half Vsh[144 * VST];
    __shared__ float pose[529];        // pre-scaled by log2e
    __shared__ float pmv[WSQ];
    __shared__ float MASKP[8 * WSQ];   // [(cls*2+act)*144+j], log2e-domain
    __shared__ int   jinfo[WSQ];

    const int tid = threadIdx.x;
    const int b = blockIdx.y;
    const int w = blockIdx.x / 12;
    const int h = blockIdx.x - w * 12;
    const int tb2 = ((b * 64 + w) * 12 + h) * 4608;
    const bool ul = (w >> 3) == 7;
    const bool lr = (w & 7) == 7;

#pragma unroll
    for (int q = 0; q < 2; q++) {
        int cix = tid + q * 288;                 // < 576
        int j = cix >> 2, ch = (cix & 3) * 8;
        cpasync16(Ksh + j * VST + ch, g_kh + tb2 + j * 32 + ch);
        cpasync16(Vsh + j * VST + ch, g_vh + tb2 + j * 32 + ch);
    }
    asm volatile("cp.async.commit_group;" ::: "memory");

    for (int f = tid; f < 529; f += 288) pose[f] = posemb[f] * LOG2E;
    if (tid < 144) {
        int wy = w >> 3, wx = w & 7;
        int iy = tid / 12, ix = tid - iy * 12;
        float pm = (float)pixmap[(b * 96 + wy * 12 + iy) * 96 + wx * 12 + ix];
        pmv[tid] = pm;
        jinfo[tid] = iy * 23 + ix;
        float pe0 = pixemb[0] * LOG2E, pe1 = pixemb[1] * LOG2E;
        bool jh = tid >= 72, jxh = ix >= 6;
#pragma unroll
        for (int cls = 0; cls < 4; cls++) {
            bool m = (ul && (jh != (bool)(cls >> 1))) || (lr && (jxh != (bool)(cls & 1)));
            float base = m ? -1e30f : 0.f;
            MASKP[(cls * 2 + 0) * 144 + tid] = base + pe0;
            MASKP[(cls * 2 + 1) * 144 + tid] = base + ((pm != 0.f) ? pe1 : pe0);
        }
    }

    const int wr = tid >> 5;
    const int lane = tid & 31;
    const int g = lane >> 2, t = lane & 3;
    const int i0 = wr * 16 + g, i1 = i0 + 8;

    // Q fragments: packed fp16x2 direct from gmem
    uint32_t qh[2][4];
#pragma unroll
    for (int kc = 0; kc < 2; kc++) {
        int o0 = tb2 + i0 * 32 + kc * 16 + 2 * t;
        int o1 = tb2 + i1 * 32 + kc * 16 + 2 * t;
        qh[kc][0] = *(const uint32_t*)(g_qh + o0);
        qh[kc][1] = *(const uint32_t*)(g_qh + o1);
        qh[kc][2] = *(const uint32_t*)(g_qh + o0 + 8);
        qh[kc][3] = *(const uint32_t*)(g_qh + o1 + 8);
    }

    asm volatile("cp.async.wait_group 0;" ::: "memory");
    __syncthreads();

    const int iy0 = i0 / 12, ix0 = i0 - iy0 * 12;
    const int iy1 = i1 / 12, ix1 = i1 - iy1 * 12;
    const float* pr0 = pose + (11 - iy0) * 23 + (11 - ix0);
    const float* pr1 = pose + (11 - iy1) * 23 + (11 - ix1);
    const int a0 = (pmv[i0] != 0.f) ? 1 : 0;
    const int a1 = (pmv[i1] != 0.f) ? 1 : 0;
    const float* mr0 = MASKP + (((i0 >= 72 ? 2 : 0) + (ix0 >= 6 ? 1 : 0)) * 2 + a0) * 144;
    const float* mr1 = MASKP + (((i1 >= 72 ? 2 : 0) + (ix1 >= 6 ? 1 : 0)) * 2 + a1) * 144;
    const float scale2 = 0.17677669529663689f * LOG2E;

    float oacc[4][4];
#pragma unroll
    for (int nt = 0; nt < 4; nt++)
#pragma unroll
        for (int c = 0; c < 4; c++) oacc[nt][c] = 0.f;
    float rs0 = 0.f, rs1 = 0.f;

#pragma unroll
    for (int jc = 0; jc < 9; jc++) {
        // ---- S chunk via non-trans ldmatrix on row-major K [n=j][k=d]
        float sc[2][4];
#pragma unroll
        for (int u = 0; u < 2; u++)
#pragma unroll
            for (int c = 0; c < 4; c++) sc[u][c] = 0.f;

        const int jr = jc * 16 + ((lane >> 4) & 1) * 8 + (lane & 7);
        const int dbl = ((lane >> 3) & 1) * 8;
#pragma unroll
        for (int kc = 0; kc < 2; kc++) {
            uint32_t bh[4];
            ldsmx4(bh[0], bh[1], bh[2], bh[3],
                   smem_u32(Ksh + jr * VST + kc * 16 + dbl));
            mma_f16(sc[0], qh[kc], bh[0], bh[1]);
            mma_f16(sc[1], qh[kc], bh[2], bh[3]);
        }

        // ---- softmax chunk: p = ex2(sc*scale2 + MASKP[sel][j] + pose'[poff])
#pragma unroll
        for (int u = 0; u < 2; u++) {
#pragma unroll
            for (int fc = 0; fc < 2; fc++) {
                int j = jc * 16 + u * 8 + 2 * t + fc;
                int poff = jinfo[j];
                {
                    float p = ex2f(sc[u][fc] * scale2 + mr0[j] + pr0[poff]);
                    sc[u][fc] = p; rs0 += p;
                }
                {
                    float p = ex2f(sc[u][fc + 2] * scale2 + mr1[j] + pr1[poff]);
                    sc[u][fc + 2] = p; rs1 += p;
                }
            }
        }

        // ---- P -> fp16 hi A fragments, accumulate P@V (1 fp16 mma/ng)
        uint32_t ph[4];
        ph[0] = packh2(__float2half_rn(sc[0][0]), __float2half_rn(sc[0][1]));
        ph[1] = packh2(__float2half_rn(sc[0][2]), __float2half_rn(sc[0][3]));
        ph[2] = packh2(__float2half_rn(sc[1][0]), __float2half_rn(sc[1][1]));
        ph[3] = packh2(__float2half_rn(sc[1][2]), __float2half_rn(sc[1][3]));
#pragma unroll
        for (int ng = 0; ng < 2; ng++) {
            uint32_t bv[4];
            uint32_t av_ = smem_u32(Vsh + (jc * 16 + (lane & 15)) * VST +
                                    ng * 16 + (lane >> 4) * 8);
            ldsmx4t(bv[0], bv[1], bv[2], bv[3], av_);
            mma_f16(oacc[2 * ng],     ph, bv[0], bv[1]);
            mma_f16(oacc[2 * ng + 1], ph, bv[2], bv[3]);
        }
    }

    rs0 += __shfl_xor_sync(0xffffffff, rs0, 1);
    rs0 += __shfl_xor_sync(0xffffffff, rs0, 2);
    rs1 += __shfl_xor_sync(0xffffffff, rs1, 1);
    rs1 += __shfl_xor_sync(0xffffffff, rs1, 2);
    const float inv0 = 1.f / rs0, inv1 = 1.f / rs1;

    // write normalized output as fp16 for the out-proj GEMM
    const int orow0 = ((b * 64 + w) * 144 + i0) * 384 + h * 32;
    const int orow1 = ((b * 64 + w) * 144 + i1) * 384 + h * 32;
#pragma unroll
    for (int nt = 0; nt < 4; nt++) {
        int col = nt * 8 + 2 * t;
        *(uint32_t*)(g_atth + orow0 + col) =
            packh2(__float2half_rn(oacc[nt][0] * inv0),
                   __float2half_rn(oacc[nt][1] * inv0));
        *(uint32_t*)(g_atth + orow1 + col) =
            packh2(__float2half_rn(oacc[nt][2] * inv1),
                   __float2half_rn(oacc[nt][3] * inv1));
    }
}

// ---------------------------------------------------------------------------
// Kernel: output projection (single fp16 mma) + bias + roll(+6,+6) scatter
// ---------------------------------------------------------------------------
__global__ __launch_bounds__(256, 2) void out_gemm_mma(const float* __restrict__ bout,
                                                       float* __restrict__ Out) {
    GEMM_MAINLOOP(g_atth, g_woh, 384)

#pragma unroll
    for (int mt = 0; mt < 2; mt++) {
#pragma unroll
        for (int rr = 0; rr < 2; rr++) {
            int r = m0 + wm + mt * 16 + (lane >> 2) + rr * 8;
            int b = r / 9216; int rem = r - b * 9216;
            int w = rem / 144; int i = rem - w * 144;
            int iy = i / 12, ix = i - iy * 12;
            int y = (w >> 3) * 12 + iy + 6; if (y >= 96) y -= 96;
            int x = (w & 7) * 12 + ix + 6;  if (x >= 96) x -= 96;
            float* orow = Out + ((b * 96 + y) * 96 + x) * 384;
#pragma unroll
            for (int nt = 0; nt < 8; nt++) {
                int c = n0 + wn + nt * 8 + (lane & 3) * 2;
                float2 bi = *(const float2*)(bout + c);
                float2 v = make_float2(acc[mt][nt][rr * 2] + bi.x,
                                       acc[mt][nt][rr * 2 + 1] + bi.y);
                *(float2*)(orow + c) = v;
            }
        }
    }
}

// ---------------------------------------------------------------------------
extern "C" void kernel_launch(void* const* d_in, const int* in_sizes, int n_in,
                              void* d_out, int out_size) {
    (void)in_sizes; (void)n_in; (void)out_size;
    const float* x      = (const float*)d_in[0];
    const int*   pixmap = (const int*)d_in[1];
    const float* wqkv   = (const float*)d_in[2];
    const float* posemb = (const float*)d_in[3];
    const float* pixemb = (const float*)d_in[4];
    const float* wout   = (const float*)d_in[5];
    const float* bout   = (const float*)d_in[6];
    float* out = (float*)d_out;

    cudaFuncSetAttribute(qkv_gemm_mma, cudaFuncAttributeMaxDynamicSharedMemorySize,
                         SMEM_1);
    cudaFuncSetAttribute(out_gemm_mma, cudaFuncAttributeMaxDynamicSharedMemorySize,
                         SMEM_1);

    prep_x<<<27648, 256>>>(x);
    prep_w<<<576, 256>>>(wqkv, wout);
    qkv_gemm_mma<<<dim3(9, MROWS / 128), 256, SMEM_1>>>();
    attn_mma<<<dim3(NW * NHEADS, BB), 288>>>(pixmap, posemb, pixemb);
    out_gemm_mma<<<dim3(3, MROWS / 128), 256, SMEM_1>>>(bout, out);
}

// round 13
// speedup vs baseline: 5.2756x; 1.0002x over previous
#include <cuda_runtime.h>
#include <cuda_fp16.h>
#include <cstdint>

// Shapes
#define BB     8
#define NHEADS 12
#define HD     32
#define NW     64
#define WSQ    144
#define MROWS  73728        // BB*NW*WSQ
#define QKV_N  1152
#define LOG2E  1.4426950408889634f

// Scratch (allocation-free rule: __device__ globals)
__device__ __half g_qh[MROWS * 384];   // per-head [B,NW,H,144,32] fp16
__device__ __half g_kh[MROWS * 384];   // per-head [B,NW,H,144,32] fp16
__device__ __half g_vh[MROWS * 384];   // per-head [B,NW,H,144,32] fp16
__device__ __half g_xh[MROWS * 384];   // rolled/windowed x, fp16
__device__ __half g_atth[MROWS * 384]; // attention out, fp16
__device__ __half g_wqh[384 * QKV_N];  // weights fp16
__device__ __half g_woh[384 * 384];

// ---------------------------------------------------------------------------
// helpers
// ---------------------------------------------------------------------------
__device__ __forceinline__ uint32_t smem_u32(const void* p) {
    return (uint32_t)__cvta_generic_to_shared(p);
}
__device__ __forceinline__ void ldsmx4(uint32_t& r0, uint32_t& r1, uint32_t& r2,
                                       uint32_t& r3, uint32_t a) {
    asm volatile("ldmatrix.sync.aligned.m8n8.x4.shared.b16 {%0,%1,%2,%3}, [%4];"
                 : "=r"(r0), "=r"(r1), "=r"(r2), "=r"(r3) : "r"(a));
}
__device__ __forceinline__ void ldsmx4t(uint32_t& r0, uint32_t& r1, uint32_t& r2,
                                        uint32_t& r3, uint32_t a) {
    asm volatile("ldmatrix.sync.aligned.m8n8.x4.trans.shared.b16 {%0,%1,%2,%3}, [%4];"
                 : "=r"(r0), "=r"(r1), "=r"(r2), "=r"(r3) : "r"(a));
}
__device__ __forceinline__ void mma_f16(float* c, const uint32_t* a,
                                        uint32_t b0, uint32_t b1) {
    asm volatile(
        "mma.sync.aligned.m16n8k16.row.col.f32.f16.f16.f32 "
        "{%0,%1,%2,%3},{%4,%5,%6,%7},{%8,%9},{%0,%1,%2,%3};"
        : "+f"(c[0]), "+f"(c[1]), "+f"(c[2]), "+f"(c[3])
        : "r"(a[0]), "r"(a[1]), "r"(a[2]), "r"(a[3]), "r"(b0), "r"(b1));
}
__device__ __forceinline__ uint32_t packh2(__half a, __half b) {
    __half2 v = __halves2half2(a, b);
    return *(uint32_t*)&v;
}
// packs (lo, hi) floats into one fp16x2 register with a single CVT
__device__ __forceinline__ uint32_t cvt2h(float lo, float hi) {
    uint32_t r;
    asm("cvt.rn.f16x2.f32 %0, %1, %2;" : "=r"(r) : "f"(hi), "f"(lo));
    return r;
}
__device__ __forceinline__ void cpasync16(void* s, const void* g) {
    asm volatile("cp.async.cg.shared.global [%0], [%1], 16;"
                 :: "r"(smem_u32(s)), "l"(g));
}
__device__ __forceinline__ float ex2f(float x) {
    float r;
    asm("ex2.approx.f32 %0, %1;" : "=f"(r) : "f"(x));
    return r;
}

#define AST  40      // A smem row stride (fp16 elems): 80 B -> conflict-free
#define BST  136     // B smem row stride: 272 B -> conflict-free
#define A_STAGE 5120 // 128*AST
#define B_STAGE 4352 // 32*BST
#define NST  4
#define SMEM_1   ((NST * A_STAGE + NST * B_STAGE) * 2)       // 75776

// ---------------------------------------------------------------------------
// Merged prep kernel: roll-gather x -> fp16, weights -> fp16
// ---------------------------------------------------------------------------
__global__ __launch_bounds__(256) void prep_all(const float* __restrict__ X,
                                                const float* __restrict__ wqkv,
                                                const float* __restrict__ wout) {
    const int bid = blockIdx.x;
    if (bid < 27648) {
        const int id = bid * 256 + threadIdx.x;   // float4 id
        const int r = id / 96, t = id - r * 96;
        int b = r / 9216; int rem = r - b * 9216;
        int w = rem / 144; int i = rem - w * 144;
        int y = (w >> 3) * 12 + i / 12 + 6; if (y >= 96) y -= 96;
        int x = (w & 7) * 12 + i % 12 + 6;  if (x >= 96) x -= 96;
        float4 v = *((const float4*)(X + ((b * 96 + y) * 96 + x) * 384) + t);
        int o = r * 384 + t * 4;
        *(uint32_t*)(g_xh + o)     = cvt2h(v.x, v.y);
        *(uint32_t*)(g_xh + o + 2) = cvt2h(v.z, v.w);
    } else {
        const int id = (bid - 27648) * 256 + threadIdx.x;
        float4 v;
        __half* oh; int o;
        if (id < 110592) {                        // 384*1152/4
            v = ((const float4*)wqkv)[id];
            oh = g_wqh; o = id * 4;
        } else {
            int id2 = id - 110592;                // < 36864
            v = ((const float4*)wout)[id2];
            oh = g_woh; o = id2 * 4;
        }
        *(uint32_t*)(oh + o)     = cvt2h(v.x, v.y);
        *(uint32_t*)(oh + o + 2) = cvt2h(v.z, v.w);
    }
}

// ---------------------------------------------------------------------------
// GEMM: 128x128 tile, BK=32, 256 thr, 8 warps (4m x 2n, 32x64 warp tile).
// Single fp16 mma: C += A*B. 4-stage cp.async pipeline.
// ---------------------------------------------------------------------------
__device__ __forceinline__ void load_stage(
    const __half* __restrict__ Ag, const __half* __restrict__ Bg,
    __half* Ah, __half* Bh,
    int m0, int n0, int ldb, int k0, int st, int tid)
{
    __half* ash = Ah + st * A_STAGE;
    __half* bsh = Bh + st * B_STAGE;
#pragma unroll
    for (int q = 0; q < 2; q++) {
        int c = tid * 2 + q;
        int row = c >> 2, ch = (c & 3) * 8;                 // A: 128 x 32
        cpasync16(ash + row * AST + ch, Ag + (m0 + row) * 384 + k0 + ch);
    }
#pragma unroll
    for (int q = 0; q < 2; q++) {
        int c = tid * 2 + q;
        int row = c >> 4, ch = (c & 15) * 8;                // B: 32 x 128
        cpasync16(bsh + row * BST + ch, Bg + (k0 + row) * ldb + n0 + ch);
    }
}

__device__ __forceinline__ void compute_stage(
    const __half* Ah, const __half* Bh,
    int wm, int wn, int lane, float acc[2][8][4])
{
#pragma unroll
    for (int ks = 0; ks < 2; ks++) {
        const int kk = ks * 16;
        uint32_t ah[2][4], bh[4][4];
        const int arow = wm + (lane & 15);
        const int acol = kk + (lane >> 4) * 8;
#pragma unroll
        for (int mt = 0; mt < 2; mt++) {
            ldsmx4(ah[mt][0], ah[mt][1], ah[mt][2], ah[mt][3],
                   smem_u32(Ah + (arow + mt * 16) * AST + acol));
        }
        const int bk = kk + (lane & 15);
        const int bnb = wn + (lane >> 4) * 8;
#pragma unroll
        for (int g = 0; g < 4; g++) {
            ldsmx4t(bh[g][0], bh[g][1], bh[g][2], bh[g][3],
                    smem_u32(Bh + bk * BST + bnb + g * 16));
        }
#pragma unroll
        for (int mt = 0; mt < 2; mt++)
#pragma unroll
            for (int g = 0; g < 4; g++)
#pragma unroll
                for (int hf = 0; hf < 2; hf++) {
                    mma_f16(acc[mt][2 * g + hf], ah[mt],
                            bh[g][2 * hf], bh[g][2 * hf + 1]);
                }
    }
}

#define GEMM_MAINLOOP(AG, BG, LDB)                                               \
    extern __shared__ __align__(16) __half smem[];                               \
    __half* Ah = smem;                                                           \
    __half* Bh = smem + NST * A_STAGE;                                           \
    const int tid = threadIdx.x;                                                 \
    const int m0 = blockIdx.y * 128;                                             \
    const int n0 = blockIdx.x * 128;                                             \
    const int wid = tid >> 5, lane = tid & 31;                                   \
    const int wm = (wid >> 1) * 32;                                              \
    const int wn = (wid & 1) * 64;                                               \
    float acc[2][8][4];                                                          \
    _Pragma("unroll") for (int a_ = 0; a_ < 2; a_++)                             \
    _Pragma("unroll") for (int b_ = 0; b_ < 8; b_++)                             \
    _Pragma("unroll") for (int c_ = 0; c_ < 4; c_++) acc[a_][b_][c_] = 0.f;      \
    _Pragma("unroll") for (int s_ = 0; s_ < NST - 1; s_++) {                     \
        load_stage(AG, BG, Ah, Bh, m0, n0, LDB, s_ * 32, s_, tid);               \
        asm volatile("cp.async.commit_group;" ::: "memory");                     \
    }                                                                            \
    for (int it = 0; it < 12; it++) {                                            \
        asm volatile("cp.async.wait_group %0;" :: "n"(NST - 2) : "memory");      \
        __syncthreads();                                                         \
        if (it < 12 - (NST - 1)) {                                               \
            load_stage(AG, BG, Ah, Bh, m0, n0, LDB,                              \
                       (it + NST - 1) * 32, (it + NST - 1) & (NST - 1), tid);    \
        }                                                                        \
        asm volatile("cp.async.commit_group;" ::: "memory");                     \
        const int st = it & (NST - 1);                                           \
        compute_stage(Ah + st * A_STAGE, Bh + st * B_STAGE, wm, wn, lane, acc);  \
    }

// ---------------------------------------------------------------------------
// Kernel: QKV GEMM (1 fp16 mma) -> Q,K,V fp16 row-major per-head.
// ---------------------------------------------------------------------------
__global__ __launch_bounds__(256, 2) void qkv_gemm_mma() {
    GEMM_MAINLOOP(g_xh, g_wqh, QKV_N)

    const int part = n0 / 384;                // 0=Q, 1=K, 2=V
    const int cbase = n0 - part * 384;
    __half* outp = (part == 0) ? g_qh : (part == 1 ? g_kh : g_vh);

#pragma unroll
    for (int mt = 0; mt < 2; mt++) {
#pragma unroll
        for (int rr = 0; rr < 2; rr++) {
            int r = m0 + wm + mt * 16 + (lane >> 2) + rr * 8;
            int b = r / 9216; int rem = r - b * 9216;
            int w = rem / 144; int i = rem - w * 144;
            int bw12 = (b * 64 + w) * 12;
#pragma unroll
            for (int nt = 0; nt < 8; nt++) {
                int c = cbase + wn + nt * 8 + (lane & 3) * 2;
                int h = c >> 5, d = c & 31;
                int tq = ((bw12 + h) * 144 + i) * 32 + d;
                *(uint32_t*)(outp + tq) =
                    cvt2h(acc[mt][nt][rr * 2], acc[mt][nt][rr * 2 + 1]);
            }
        }
    }
}

// ---------------------------------------------------------------------------
// Kernel: flash-chunked attention; block = (b, w, head-group of 4).
// Tables built once per block; K/V double-buffered across heads via cp.async.
// ---------------------------------------------------------------------------
#define VST  40
#define KV_BUF (WSQ * VST)                 // 5760 halfs per tile

__global__ __launch_bounds__(288, 2) void attn_mma(const int* __restrict__ pixmap,
                                                   const float* __restrict__ posemb,
                                                   const float* __restrict__ pixemb) {
    extern __shared__ __align__(16) char smemraw[];
    __half* Ksh   = (__half*)smemraw;                 // [2][KV_BUF]
    __half* Vsh   = Ksh + 2 * KV_BUF;                 // [2][KV_BUF]
    float*  pose  = (float*)(Vsh + 2 * KV_BUF);       // 529
    float*  MASKP = pose + 529;                       // 8*144
    float*  pmv   = MASKP + 8 * WSQ;                  // 144
    int*    jinfo = (int*)(pmv + WSQ);                // 144

    const int tid = threadIdx.x;
    const int b = blockIdx.y;
    const int w = blockIdx.x / 3;
    const int hg = blockIdx.x - w * 3;                // head group: heads 4hg..4hg+3
    const int hbase = ((b * 64 + w) * 12 + hg * 4) * 4608;
    const bool ul = (w >> 3) == 7;
    const bool lr = (w & 7) == 7;

    // issue head 0 K/V
#pragma unroll
    for (int q = 0; q < 2; q++) {
        int cix = tid + q * 288;                 // < 576
        int j = cix >> 2, ch = (cix & 3) * 8;
        cpasync16(Ksh + j * VST + ch, g_kh + hbase + j * 32 + ch);
        cpasync16(Vsh + j * VST + ch, g_vh + hbase + j * 32 + ch);
    }
    asm volatile("cp.async.commit_group;" ::: "memory");

    // per-block tables (head-independent)
    for (int f = tid; f < 529; f += 288) pose[f] = posemb[f] * LOG2E;
    if (tid < 144) {
        int wy = w >> 3, wx = w & 7;
        int iy = tid / 12, ix = tid - iy * 12;
        float pm = (float)pixmap[(b * 96 + wy * 12 + iy) * 96 + wx * 12 + ix];
        pmv[tid] = pm;
        jinfo[tid] = iy * 23 + ix;
        float pe0 = pixemb[0] * LOG2E, pe1 = pixemb[1] * LOG2E;
        bool jh = tid >= 72, jxh = ix >= 6;
#pragma unroll
        for (int cls = 0; cls < 4; cls++) {
            bool m = (ul && (jh != (bool)(cls >> 1))) || (lr && (jxh != (bool)(cls & 1)));
            float base = m ? -1e30f : 0.f;
            MASKP[(cls * 2 + 0) * 144 + tid] = base + pe0;
            MASKP[(cls * 2 + 1) * 144 + tid] = base + ((pm != 0.f) ? pe1 : pe0);
        }
    }

    const int wr = tid >> 5;
    const int lane = tid & 31;
    const int g = lane >> 2, t = lane & 3;
    const int i0 = wr * 16 + g, i1 = i0 + 8;
    const int iy0 = i0 / 12, ix0 = i0 - iy0 * 12;
    const int iy1 = i1 / 12, ix1 = i1 - iy1 * 12;
    const float* pr0 = pose + (11 - iy0) * 23 + (11 - ix0);
    const float* pr1 = pose + (11 - iy1) * 23 + (11 - ix1);
    const float scale2 = 0.17677669529663689f * LOG2E;

    bool rowsel_done = false;
    const float* mr0 = nullptr;
    const float* mr1 = nullptr;

    for (int hh = 0; hh < 4; hh++) {
        // prefetch next head's K/V into the other buffer
        if (hh < 3) {
            const int nb = hbase + (hh + 1) * 4608;
            __half* kd = Ksh + ((hh + 1) & 1) * KV_BUF;
            __half* vd = Vsh + ((hh + 1) & 1) * KV_BUF;
#pragma unroll
            for (int q = 0; q < 2; q++) {
                int cix = tid + q * 288;
                int j = cix >> 2, ch = (cix & 3) * 8;
                cpasync16(kd + j * VST + ch, g_kh + nb + j * 32 + ch);
                cpasync16(vd + j * VST + ch, g_vh + nb + j * 32 + ch);
            }
        }
        asm volatile("cp.async.commit_group;" ::: "memory");
        asm volatile("cp.async.wait_group 1;" ::: "memory");
        __syncthreads();

        if (!rowsel_done) {   // needs pmv (written above, visible after sync)
            const int a0 = (pmv[i0] != 0.f) ? 1 : 0;
            const int a1 = (pmv[i1] != 0.f) ? 1 : 0;
            mr0 = MASKP + (((i0 >= 72 ? 2 : 0) + (ix0 >= 6 ? 1 : 0)) * 2 + a0) * 144;
            mr1 = MASKP + (((i1 >= 72 ? 2 : 0) + (ix1 >= 6 ? 1 : 0)) * 2 + a1) * 144;
            rowsel_done = true;
        }

        const int tb2 = hbase + hh * 4608;
        const __half* Kc = Ksh + (hh & 1) * KV_BUF;
        const __half* Vc = Vsh + (hh & 1) * KV_BUF;

        // Q fragments for this head
        uint32_t qh[2][4];
#pragma unroll
        for (int kc = 0; kc < 2; kc++) {
            int o0 = tb2 + i0 * 32 + kc * 16 + 2 * t;
            int o1 = tb2 + i1 * 32 + kc * 16 + 2 * t;
            qh[kc][0] = *(const uint32_t*)(g_qh + o0);
            qh[kc][1] = *(const uint32_t*)(g_qh + o1);
            qh[kc][2] = *(const uint32_t*)(g_qh + o0 + 8);
            qh[kc][3] = *(const uint32_t*)(g_qh + o1 + 8);
        }

        float oacc[4][4];
#pragma unroll
        for (int nt = 0; nt < 4; nt++)
#pragma unroll
            for (int c = 0; c < 4; c++) oacc[nt][c] = 0.f;
        float rs0 = 0.f, rs1 = 0.f;

#pragma unroll
        for (int jc = 0; jc < 9; jc++) {
            // S chunk via non-trans ldmatrix on row-major K [n=j][k=d]
            float sc[2][4];
#pragma unroll
            for (int u = 0; u < 2; u++)
#pragma unroll
                for (int c = 0; c < 4; c++) sc[u][c] = 0.f;

            const int jr = jc * 16 + ((lane >> 4) & 1) * 8 + (lane & 7);
            const int dbl = ((lane >> 3) & 1) * 8;
#pragma unroll
            for (int kc = 0; kc < 2; kc++) {
                uint32_t bh[4];
                ldsmx4(bh[0], bh[1], bh[2], bh[3],
                       smem_u32(Kc + jr * VST + kc * 16 + dbl));
                mma_f16(sc[0], qh[kc], bh[0], bh[1]);
                mma_f16(sc[1], qh[kc], bh[2], bh[3]);
            }

            // softmax chunk
#pragma unroll
            for (int u = 0; u < 2; u++) {
#pragma unroll
                for (int fc = 0; fc < 2; fc++) {
                    int j = jc * 16 + u * 8 + 2 * t + fc;
                    int poff = jinfo[j];
                    {
                        float p = ex2f(sc[u][fc] * scale2 + mr0[j] + pr0[poff]);
                        sc[u][fc] = p; rs0 += p;
                    }
                    {
                        float p = ex2f(sc[u][fc + 2] * scale2 + mr1[j] + pr1[poff]);
                        sc[u][fc + 2] = p; rs1 += p;
                    }
                }
            }

            // P -> fp16 A fragments (single-CVT packs), accumulate P@V
            uint32_t ph[4];
            ph[0] = cvt2h(sc[0][0], sc[0][1]);
            ph[1] = cvt2h(sc[0][2], sc[0][3]);
            ph[2] = cvt2h(sc[1][0], sc[1][1]);
            ph[3] = cvt2h(sc[1][2], sc[1][3]);
#pragma unroll
            for (int ng = 0; ng < 2; ng++) {
                uint32_t bv[4];
                uint32_t av_ = smem_u32(Vc + (jc * 16 + (lane & 15)) * VST +
                                        ng * 16 + (lane >> 4) * 8);
                ldsmx4t(bv[0], bv[1], bv[2], bv[3], av_);
                mma_f16(oacc[2 * ng],     ph, bv[0], bv[1]);
                mma_f16(oacc[2 * ng + 1], ph, bv[2], bv[3]);
            }
        }

        rs0 += __shfl_xor_sync(0xffffffff, rs0, 1);
        rs0 += __shfl_xor_sync(0xffffffff, rs0, 2);
        rs1 += __shfl_xor_sync(0xffffffff, rs1, 1);
        rs1 += __shfl_xor_sync(0xffffffff, rs1, 2);
        const float inv0 = 1.f / rs0, inv1 = 1.f / rs1;

        // write normalized output as fp16 for the out-proj GEMM
        const int hcol = (hg * 4 + hh) * 32;
        const int orow0 = ((b * 64 + w) * 144 + i0) * 384 + hcol;
        const int orow1 = ((b * 64 + w) * 144 + i1) * 384 + hcol;
#pragma unroll
        for (int nt = 0; nt < 4; nt++) {
            int col = nt * 8 + 2 * t;
            *(uint32_t*)(g_atth + orow0 + col) =
                cvt2h(oacc[nt][0] * inv0, oacc[nt][1] * inv0);
            *(uint32_t*)(g_atth + orow1 + col) =
                cvt2h(oacc[nt][2] * inv1, oacc[nt][3] * inv1);
        }
        __syncthreads();   // protect K/V buffer reuse by next prefetch
    }
}
#define SMEM_ATT (4 * KV_BUF * 2 + (529 + 8 * WSQ + WSQ) * 4 + WSQ * 4 + 16)

// ---------------------------------------------------------------------------
// Kernel: output projection (single fp16 mma) + bias + roll(+6,+6) scatter
// ---------------------------------------------------------------------------
__global__ __launch_bounds__(256, 2) void out_gemm_mma(const float* __restrict__ bout,
                                                       float* __restrict__ Out) {
    GEMM_MAINLOOP(g_atth, g_woh, 384)

#pragma unroll
    for (int mt = 0; mt < 2; mt++) {
#pragma unroll
        for (int rr = 0; rr < 2; rr++) {
            int r = m0 + wm + mt * 16 + (lane >> 2) + rr * 8;
            int b = r / 9216; int rem = r - b * 9216;
            int w = rem / 144; int i = rem - w * 144;
            int iy = i / 12, ix = i - iy * 12;
            int y = (w >> 3) * 12 + iy + 6; if (y >= 96) y -= 96;
            int x = (w & 7) * 12 + ix + 6;  if (x >= 96) x -= 96;
            float* orow = Out + ((b * 96 + y) * 96 + x) * 384;
#pragma unroll
            for (int nt = 0; nt < 8; nt++) {
                int c = n0 + wn + nt * 8 + (lane & 3) * 2;
                float2 bi = *(const float2*)(bout + c);
                float2 v = make_float2(acc[mt][nt][rr * 2] + bi.x,
                                       acc[mt][nt][rr * 2 + 1] + bi.y);
                *(float2*)(orow + c) = v;
            }
        }
    }
}

// ---------------------------------------------------------------------------
extern "C" void kernel_launch(void* const* d_in, const int* in_sizes, int n_in,
                              void* d_out, int out_size) {
    (void)in_sizes; (void)n_in; (void)out_size;
    const float* x      = (const float*)d_in[0];
    const int*   pixmap = (const int*)d_in[1];
    const float* wqkv   = (const float*)d_in[2];
    const float* posemb = (const float*)d_in[3];
    const float* pixemb = (const float*)d_in[4];
    const float* wout   = (const float*)d_in[5];
    const float* bout   = (const float*)d_in[6];
    float* out = (float*)d_out;

    cudaFuncSetAttribute(qkv_gemm_mma, cudaFuncAttributeMaxDynamicSharedMemorySize,
                         SMEM_1);
    cudaFuncSetAttribute(attn_mma, cudaFuncAttributeMaxDynamicSharedMemorySize,
                         SMEM_ATT);
    cudaFuncSetAttribute(out_gemm_mma, cudaFuncAttributeMaxDynamicSharedMemorySize,
                         SMEM_1);

    prep_all<<<28224, 256>>>(x, wqkv, wout);
    qkv_gemm_mma<<<dim3(9, MROWS / 128), 256, SMEM_1>>>();
    attn_mma<<<dim3(NW * 3, BB), 288, SMEM_ATT>>>(pixmap, posemb, pixemb);
    out_gemm_mma<<<dim3(3, MROWS / 128), 256, SMEM_1>>>(bout, out);
}